// round 8
// baseline (speedup 1.0000x reference)
#include <cuda_runtime.h>
#include <cuda_bf16.h>
#include <cstdint>

#define NB 8
#define NS 1024
#define ND 1024
#define NH 16
#define NDH 64
#define KAUG 3072   // augmented K for QKV GEMM: [hi, hi/lo, lo/hi]

// ---------------- scratch (static device globals) ----------------
__device__ __align__(128) __nv_bfloat16 g_A[(size_t)NB * NS * KAUG];   // [xh|xh|xl]
__device__ __align__(128) __nv_bfloat16 g_Bm[3 * (size_t)ND * KAUG];   // [wh|wl|wh]
// attention operands, bf16 splits, seg-major: [bh][seg][s][64]
__device__ __align__(128) __nv_bfloat16 g_Qs[(size_t)NB * NH * 3 * NS * NDH]; // [qh|qh|ql]*0.125
__device__ __align__(128) __nv_bfloat16 g_Ks[(size_t)NB * NH * 3 * NS * NDH]; // [kh|kl|kh]
__device__ __align__(128) __nv_bfloat16 g_Vs[(size_t)NB * NH * 2 * NS * NDH]; // [vh|vl]

// ---------------- PTX helpers (compute_103-safe) ----------------
__device__ __forceinline__ uint32_t smem_u32(const void* p) {
    uint32_t a;
    asm("{ .reg .u64 t; cvta.to.shared.u64 t, %1; cvt.u32.u64 %0, t; }" : "=r"(a) : "l"(p));
    return a;
}
__device__ __forceinline__ void cp_async16(uint32_t dst, const void* src) {
    asm volatile("cp.async.cg.shared.global [%0], [%1], 16;" :: "r"(dst), "l"(src));
}
#define CP_COMMIT() asm volatile("cp.async.commit_group;" ::: "memory")
#define CP_WAIT(n)  asm volatile("cp.async.wait_group %0;" :: "n"(n) : "memory")

__device__ __forceinline__ void ldsm4(uint32_t* r, uint32_t addr) {
    asm volatile("ldmatrix.sync.aligned.m8n8.x4.shared.b16 {%0,%1,%2,%3}, [%4];"
                 : "=r"(r[0]), "=r"(r[1]), "=r"(r[2]), "=r"(r[3]) : "r"(addr));
}
__device__ __forceinline__ void ldsm2(uint32_t* r, uint32_t addr) {
    asm volatile("ldmatrix.sync.aligned.m8n8.x2.shared.b16 {%0,%1}, [%2];"
                 : "=r"(r[0]), "=r"(r[1]) : "r"(addr));
}
__device__ __forceinline__ void ldsm4t(uint32_t* r, uint32_t addr) {
    asm volatile("ldmatrix.sync.aligned.m8n8.x4.trans.shared.b16 {%0,%1,%2,%3}, [%4];"
                 : "=r"(r[0]), "=r"(r[1]), "=r"(r[2]), "=r"(r[3]) : "r"(addr));
}
__device__ __forceinline__ void mma16816(float* c, const uint32_t* a, const uint32_t* b) {
    asm volatile("mma.sync.aligned.m16n8k16.row.col.f32.bf16.bf16.f32 "
                 "{%0,%1,%2,%3}, {%4,%5,%6,%7}, {%8,%9}, {%0,%1,%2,%3};"
                 : "+f"(c[0]), "+f"(c[1]), "+f"(c[2]), "+f"(c[3])
                 : "r"(a[0]), "r"(a[1]), "r"(a[2]), "r"(a[3]), "r"(b[0]), "r"(b[1]));
}
__device__ __forceinline__ void mma16816v(float* c, const uint32_t* a, uint32_t b0, uint32_t b1) {
    asm volatile("mma.sync.aligned.m16n8k16.row.col.f32.bf16.bf16.f32 "
                 "{%0,%1,%2,%3}, {%4,%5,%6,%7}, {%8,%9}, {%0,%1,%2,%3};"
                 : "+f"(c[0]), "+f"(c[1]), "+f"(c[2]), "+f"(c[3])
                 : "r"(a[0]), "r"(a[1]), "r"(a[2]), "r"(a[3]), "r"(b0), "r"(b1));
}
__device__ __forceinline__ uint32_t sw128(uint32_t off) { return off ^ ((off >> 3) & 0x70); }

// ============================================================================
// Prep: split fp32 -> bf16 hi/lo, build augmented K-major operands for QKV.
// ============================================================================
__global__ __launch_bounds__(256) void prep_x_kernel(const float* __restrict__ x)
{
    size_t e = ((size_t)blockIdx.x * 256 + threadIdx.x) * 4;
    int m = (int)(e >> 10), k = (int)(e & 1023);
    float4 v = *(const float4*)&x[e];
    __nv_bfloat162 h01 = __floats2bfloat162_rn(v.x, v.y);
    __nv_bfloat162 h23 = __floats2bfloat162_rn(v.z, v.w);
    __nv_bfloat162 l01 = __floats2bfloat162_rn(v.x - __bfloat162float(h01.x),
                                               v.y - __bfloat162float(h01.y));
    __nv_bfloat162 l23 = __floats2bfloat162_rn(v.z - __bfloat162float(h23.x),
                                               v.w - __bfloat162float(h23.y));
    size_t ro = (size_t)m * KAUG;
    *(__nv_bfloat162*)&g_A[ro + k]            = h01;
    *(__nv_bfloat162*)&g_A[ro + k + 2]        = h23;
    *(__nv_bfloat162*)&g_A[ro + 1024 + k]     = h01;
    *(__nv_bfloat162*)&g_A[ro + 1024 + k + 2] = h23;
    *(__nv_bfloat162*)&g_A[ro + 2048 + k]     = l01;
    *(__nv_bfloat162*)&g_A[ro + 2048 + k + 2] = l23;
}

__global__ __launch_bounds__(256) void prep_w_kernel(
    const float* __restrict__ Wq, const float* __restrict__ Wk, const float* __restrict__ Wv)
{
    int z = blockIdx.y;
    const float* W = (z == 0) ? Wq : (z == 1) ? Wk : Wv;
    __nv_bfloat16* gb = g_Bm + (size_t)z * ND * KAUG;
    size_t e = ((size_t)blockIdx.x * 256 + threadIdx.x) * 4;
    int n = (int)(e >> 10), k = (int)(e & 1023);
    float4 v = *(const float4*)&W[e];
    __nv_bfloat162 h01 = __floats2bfloat162_rn(v.x, v.y);
    __nv_bfloat162 h23 = __floats2bfloat162_rn(v.z, v.w);
    __nv_bfloat162 l01 = __floats2bfloat162_rn(v.x - __bfloat162float(h01.x),
                                               v.y - __bfloat162float(h01.y));
    __nv_bfloat162 l23 = __floats2bfloat162_rn(v.z - __bfloat162float(h23.x),
                                               v.w - __bfloat162float(h23.y));
    size_t ro = (size_t)n * KAUG;
    *(__nv_bfloat162*)&gb[ro + k]            = h01;
    *(__nv_bfloat162*)&gb[ro + k + 2]        = h23;
    *(__nv_bfloat162*)&gb[ro + 1024 + k]     = l01;
    *(__nv_bfloat162*)&gb[ro + 1024 + k + 2] = l23;
    *(__nv_bfloat162*)&gb[ro + 2048 + k]     = h01;
    *(__nv_bfloat162*)&gb[ro + 2048 + k + 2] = h23;
}

// ============================================================================
// QKV GEMM via mma.sync bf16. CTA 128x128, K-tile 64, 3-stage cp.async
// pipeline (96KB smem), 2 CTAs/SM.
// ============================================================================
#define STAGE_BYTES 32768
#define QKV_SMEM (3 * STAGE_BYTES)

__global__ __launch_bounds__(256, 2)
void qkv_mma_kernel(const float* __restrict__ bq, const float* __restrict__ bk,
                    const float* __restrict__ bv)
{
    extern __shared__ char smraw[];
    __shared__ float biasS[128];
    uint32_t sm = smem_u32(smraw);

    int t = threadIdx.x;
    int wid = t >> 5, lane = t & 31;
    int warp_m = wid & 1, warp_n = wid >> 1;

    int bx = blockIdx.x;
    int z = bx >> 3;
    int n0 = (bx & 7) * 128;
    int m0 = blockIdx.y * 128;

    const float* bias = (z == 0) ? bq : (z == 1) ? bk : bv;
    const __nv_bfloat16* Asrc = g_A + (size_t)m0 * KAUG;
    const __nv_bfloat16* Bsrc = g_Bm + (size_t)z * ND * KAUG + (size_t)n0 * KAUG;

    if (t < 128) biasS[t] = bias[n0 + t];

    auto load_tile = [&](int kt, int s) {
        uint32_t base = sm + s * STAGE_BYTES;
        int k0 = kt * 64;
        #pragma unroll
        for (int i = 0; i < 8; i++) {
            int c = t + i * 256;
            int row = c >> 3, col = c & 7;
            uint32_t off = sw128((uint32_t)((row & 127) * 128 + col * 16));
            const __nv_bfloat16* src = (row < 128)
                ? Asrc + (size_t)row * KAUG + k0 + col * 8
                : Bsrc + (size_t)(row - 128) * KAUG + k0 + col * 8;
            cp_async16(base + (row < 128 ? 0u : 16384u) + off, src);
        }
    };

    float acc[4][4][4];
    #pragma unroll
    for (int mt = 0; mt < 4; mt++)
        #pragma unroll
        for (int nt = 0; nt < 4; nt++)
            #pragma unroll
            for (int r = 0; r < 4; r++) acc[mt][nt][r] = 0.f;

    uint32_t a_row = (uint32_t)(warp_m * 64 + (lane & 15));
    uint32_t a_kb  = (uint32_t)((lane >> 4) << 4);
    uint32_t b_row = (uint32_t)(warp_n * 32 + (lane & 15));

    load_tile(0, 0); CP_COMMIT();
    load_tile(1, 1); CP_COMMIT();

    int cur = 0;
    for (int kt = 0; kt < 48; kt++) {
        if (kt + 1 < 48) CP_WAIT(1); else CP_WAIT(0);
        __syncthreads();
        if (kt + 2 < 48) {
            int nxt = cur + 2; if (nxt >= 3) nxt -= 3;
            load_tile(kt + 2, nxt); CP_COMMIT();
        }

        uint32_t abase = sm + cur * STAGE_BYTES;
        uint32_t bbase = abase + 16384u;
        #pragma unroll
        for (int ks = 0; ks < 4; ks++) {
            uint32_t kb = (uint32_t)(ks * 32);
            uint32_t af[4][4], bw[2][4];
            #pragma unroll
            for (int mt = 0; mt < 4; mt++)
                ldsm4(af[mt], abase + sw128((a_row + mt * 16) * 128 + kb + a_kb));
            #pragma unroll
            for (int p = 0; p < 2; p++)
                ldsm4(bw[p], bbase + sw128((b_row + p * 16) * 128 + kb + a_kb));
            #pragma unroll
            for (int mt = 0; mt < 4; mt++)
                #pragma unroll
                for (int p = 0; p < 2; p++) {
                    mma16816v(acc[mt][2 * p],     af[mt], bw[p][0], bw[p][2]);
                    mma16816v(acc[mt][2 * p + 1], af[mt], bw[p][1], bw[p][3]);
                }
        }
        __syncthreads();
        cur = cur + 1; if (cur >= 3) cur = 0;
    }

    // ---- epilogue: bias (+0.125 scale for Q) -> bf16 hi/lo splits ----
    int gq = lane >> 2;
    float scale = (z == 0) ? 0.125f : 1.0f;
    #pragma unroll
    for (int mt = 0; mt < 4; mt++) {
        int m_lo = m0 + warp_m * 64 + mt * 16 + gq;
        #pragma unroll
        for (int half = 0; half < 2; half++) {
            int m = m_lo + half * 8;
            int b = m >> 10, s = m & 1023;
            #pragma unroll
            for (int nt = 0; nt < 4; nt++) {
                int nc = warp_n * 32 + nt * 8 + (lane & 3) * 2;
                int n = n0 + nc;
                int h = n >> 6, dh = n & 63;
                int bh = b * NH + h;
                float c0 = (acc[mt][nt][half * 2 + 0] + biasS[nc]) * scale;
                float c1 = (acc[mt][nt][half * 2 + 1] + biasS[nc + 1]) * scale;
                __nv_bfloat162 hv = __floats2bfloat162_rn(c0, c1);
                __nv_bfloat162 lv = __floats2bfloat162_rn(c0 - __bfloat162float(hv.x),
                                                          c1 - __bfloat162float(hv.y));
                if (z == 2) {
                    size_t o = (((size_t)bh * 2 + 0) * NS + s) * NDH + dh;
                    *(__nv_bfloat162*)&g_Vs[o] = hv;
                    *(__nv_bfloat162*)&g_Vs[o + (size_t)NS * NDH] = lv;
                } else {
                    __nv_bfloat16* dst = (z == 0) ? g_Qs : g_Ks;
                    size_t o = (((size_t)bh * 3 + 0) * NS + s) * NDH + dh;
                    size_t seg = (size_t)NS * NDH;
                    if (z == 0) {   // [qh|qh|ql]
                        *(__nv_bfloat162*)&dst[o]           = hv;
                        *(__nv_bfloat162*)&dst[o + seg]     = hv;
                        *(__nv_bfloat162*)&dst[o + 2 * seg] = lv;
                    } else {        // [kh|kl|kh]
                        *(__nv_bfloat162*)&dst[o]           = hv;
                        *(__nv_bfloat162*)&dst[o + seg]     = lv;
                        *(__nv_bfloat162*)&dst[o + 2 * seg] = hv;
                    }
                }
            }
        }
    }
}

// ============================================================================
// Attention via mma.sync. CTA: 64 q x one (b,h). 8 k-tiles of 128,
// double-buffered. QK: M64 N128 K192. AV: 3 split terms.
// Self-normalizes its own attention slice at the end (L2-resident re-read).
// ============================================================================
#define QS_OFF 0u
#define KS_OFF 24576u
#define VS_OFF 122880u
#define P_OFF  188416u
#define RS_OFF 221184u
#define ATT_SMEM 221440u

__global__ __launch_bounds__(256, 1)
void attn_mma_kernel(float* __restrict__ out_ctx, float* __restrict__ out_att)
{
    extern __shared__ char smraw[];
    uint32_t sm = smem_u32(smraw);
    float* rowsumS = (float*)(smraw + RS_OFF);

    int t = threadIdx.x;
    int wid = t >> 5, lane = t & 31;
    int warp_m = wid & 1, warp_n = wid >> 1;
    int bh = blockIdx.y;
    int q0 = blockIdx.x * 64;

    const __nv_bfloat16* Qg = g_Qs + ((size_t)bh * 3 * NS + q0) * NDH;
    const __nv_bfloat16* Kg = g_Ks + (size_t)bh * 3 * NS * NDH;
    const __nv_bfloat16* Vg = g_Vs + (size_t)bh * 2 * NS * NDH;

    #pragma unroll
    for (int i = 0; i < 6; i++) {
        int c = t + i * 256;
        int seg = c >> 9, row = (c >> 3) & 63, col = c & 7;
        cp_async16(sm + QS_OFF + seg * 8192u + sw128((uint32_t)(row * 128 + col * 16)),
                   Qg + ((size_t)seg * NS + row) * NDH + col * 8);
    }
    auto load_kv = [&](int kt, int buf) {
        #pragma unroll
        for (int i = 0; i < 12; i++) {
            int c = t + i * 256;
            int seg = c >> 10, row = (c >> 3) & 127, col = c & 7;
            cp_async16(sm + KS_OFF + buf * 49152u + seg * 16384u
                          + sw128((uint32_t)(row * 128 + col * 16)),
                       Kg + (((size_t)seg * NS) + kt * 128 + row) * NDH + col * 8);
        }
        #pragma unroll
        for (int i = 0; i < 8; i++) {
            int c = t + i * 256;
            int hl = c >> 10, row = (c >> 3) & 127, col = c & 7;
            cp_async16(sm + VS_OFF + buf * 32768u + hl * 16384u
                          + sw128((uint32_t)(row * 128 + col * 16)),
                       Vg + (((size_t)hl * NS) + kt * 128 + row) * NDH + col * 8);
        }
    };
    load_kv(0, 0); CP_COMMIT();
    if (t < 64) rowsumS[t] = 0.f;

    float ctx[2][2][4];
    #pragma unroll
    for (int mt = 0; mt < 2; mt++)
        #pragma unroll
        for (int nt = 0; nt < 2; nt++)
            #pragma unroll
            for (int r = 0; r < 4; r++) ctx[mt][nt][r] = 0.f;

    uint32_t a_row = (uint32_t)(warp_m * 32 + (lane & 15));
    uint32_t a_kb  = (uint32_t)((lane >> 4) << 4);
    uint32_t b_row = (uint32_t)(warp_n * 32 + (lane & 7));
    uint32_t b_kb  = (uint32_t)(((lane >> 3) & 1) << 4);

    for (int kt = 0; kt < 8; kt++) {
        int cur = kt & 1;
        CP_WAIT(0);
        __syncthreads();
        if (kt + 1 < 8) { load_kv(kt + 1, cur ^ 1); CP_COMMIT(); }

        float sacc[2][4][4];
        #pragma unroll
        for (int mt = 0; mt < 2; mt++)
            #pragma unroll
            for (int nt = 0; nt < 4; nt++)
                #pragma unroll
                for (int r = 0; r < 4; r++) sacc[mt][nt][r] = 0.f;

        uint32_t kbase = sm + KS_OFF + cur * 49152u;
        #pragma unroll
        for (int ks = 0; ks < 12; ks++) {
            uint32_t seg = (uint32_t)(ks >> 2), kb = (uint32_t)((ks & 3) * 32);
            uint32_t af[2][4], bf[4][2];
            #pragma unroll
            for (int mt = 0; mt < 2; mt++)
                ldsm4(af[mt], sm + QS_OFF + seg * 8192u
                              + sw128((a_row + mt * 16) * 128 + kb + a_kb));
            #pragma unroll
            for (int nt = 0; nt < 4; nt++)
                ldsm2(bf[nt], kbase + seg * 16384u
                              + sw128((b_row + nt * 8) * 128 + kb + b_kb));
            #pragma unroll
            for (int mt = 0; mt < 2; mt++)
                #pragma unroll
                for (int nt = 0; nt < 4; nt++)
                    mma16816(sacc[mt][nt], af[mt], bf[nt]);
        }

        size_t attbase = ((size_t)bh * NS + q0) * NS + (size_t)kt * 128;
        #pragma unroll
        for (int mt = 0; mt < 2; mt++) {
            float p0 = 0.f, p1 = 0.f;
            int r0 = warp_m * 32 + mt * 16 + (lane >> 2);
            #pragma unroll
            for (int nt = 0; nt < 4; nt++) {
                int kc = warp_n * 32 + nt * 8 + (lane & 3) * 2;
                float e0 = __expf(sacc[mt][nt][0]);
                float e1 = __expf(sacc[mt][nt][1]);
                float e2 = __expf(sacc[mt][nt][2]);
                float e3 = __expf(sacc[mt][nt][3]);
                p0 += e0 + e1; p1 += e2 + e3;
                *(float2*)&out_att[attbase + (size_t)r0 * NS + kc]       = make_float2(e0, e1);
                *(float2*)&out_att[attbase + (size_t)(r0 + 8) * NS + kc] = make_float2(e2, e3);
                __nv_bfloat162 h0 = __floats2bfloat162_rn(e0, e1);
                __nv_bfloat162 l0 = __floats2bfloat162_rn(e0 - __bfloat162float(h0.x),
                                                          e1 - __bfloat162float(h0.y));
                __nv_bfloat162 h1 = __floats2bfloat162_rn(e2, e3);
                __nv_bfloat162 l1 = __floats2bfloat162_rn(e2 - __bfloat162float(h1.x),
                                                          e3 - __bfloat162float(h1.y));
                uint32_t po = (uint32_t)((kc >> 6) * 8192) + sw128((uint32_t)(r0 * 128 + (kc & 63) * 2));
                uint32_t po8 = (uint32_t)((kc >> 6) * 8192) + sw128((uint32_t)((r0 + 8) * 128 + (kc & 63) * 2));
                *(__nv_bfloat162*)(smraw + P_OFF + po)            = h0;
                *(__nv_bfloat162*)(smraw + P_OFF + 16384u + po)   = l0;
                *(__nv_bfloat162*)(smraw + P_OFF + po8)           = h1;
                *(__nv_bfloat162*)(smraw + P_OFF + 16384u + po8)  = l1;
            }
            p0 += __shfl_xor_sync(0xffffffffu, p0, 1);
            p0 += __shfl_xor_sync(0xffffffffu, p0, 2);
            p1 += __shfl_xor_sync(0xffffffffu, p1, 1);
            p1 += __shfl_xor_sync(0xffffffffu, p1, 2);
            if ((lane & 3) == 0) {
                atomicAdd(&rowsumS[r0], p0);
                atomicAdd(&rowsumS[r0 + 8], p1);
            }
        }
        __syncthreads();

        uint32_t vbase = sm + VS_OFF + cur * 32768u;
        #pragma unroll
        for (int term = 0; term < 3; term++) {
            uint32_t pb = sm + P_OFF + (term == 2 ? 16384u : 0u);
            uint32_t vb = vbase + (term == 1 ? 16384u : 0u);
            #pragma unroll
            for (int ks = 0; ks < 8; ks++) {
                uint32_t kbyte = (uint32_t)(ks * 32) + a_kb;
                uint32_t af[2][4], bv[4];
                #pragma unroll
                for (int mt = 0; mt < 2; mt++)
                    ldsm4(af[mt], pb + (kbyte >> 7) * 8192u
                                  + sw128((a_row + mt * 16) * 128 + (kbyte & 127)));
                ldsm4t(bv, vb + sw128((uint32_t)((ks * 16 + (lane & 15)) * 128)
                                      + (uint32_t)(warp_n * 32) + (uint32_t)((lane >> 4) * 16)));
                #pragma unroll
                for (int mt = 0; mt < 2; mt++) {
                    mma16816(ctx[mt][0], af[mt], bv);
                    mma16816(ctx[mt][1], af[mt], bv + 2);
                }
            }
        }
        __syncthreads();
    }

    // ---- normalized context write: [B,S,D] ----
    int b = bh >> 4, h = bh & 15;
    #pragma unroll
    for (int mt = 0; mt < 2; mt++) {
        #pragma unroll
        for (int half = 0; half < 2; half++) {
            int r = warp_m * 32 + mt * 16 + (lane >> 2) + half * 8;
            float inv = 1.0f / rowsumS[r];
            size_t o = ((size_t)(b * NS + q0 + r)) * ND + h * NDH;
            #pragma unroll
            for (int nt = 0; nt < 2; nt++) {
                int d = warp_n * 16 + nt * 8 + (lane & 3) * 2;
                float c0 = ctx[mt][nt][half * 2 + 0] * inv;
                float c1 = ctx[mt][nt][half * 2 + 1] * inv;
                *(float2*)&out_ctx[o + d] = make_float2(c0, c1);
            }
        }
    }

    // ---- self-normalize this CTA's attention slice (mostly L2-resident) ----
    // __syncthreads above (end of last kt) made all att STGs visible block-wide.
    {
        float* base = out_att + ((size_t)bh * NS + q0) * NS + t * 4;
        #pragma unroll 4
        for (int r = 0; r < 64; r++) {
            float inv = 1.0f / rowsumS[r];
            float4 v = *(float4*)(base + (size_t)r * NS);
            v.x *= inv; v.y *= inv; v.z *= inv; v.w *= inv;
            *(float4*)(base + (size_t)r * NS) = v;
        }
    }
}

extern "C" void kernel_launch(void* const* d_in, const int* in_sizes, int n_in,
                              void* d_out, int out_size) {
    const float* x  = (const float*)d_in[0];
    const float* Wq = (const float*)d_in[1];
    const float* bq = (const float*)d_in[2];
    const float* Wk = (const float*)d_in[3];
    const float* bk = (const float*)d_in[4];
    const float* Wv = (const float*)d_in[5];
    const float* bv = (const float*)d_in[6];
    // d_in[7] structure_bias: constant along the softmax axis -> cancels exactly.

    float* out_ctx = (float*)d_out;
    float* out_att = out_ctx + (size_t)NB * NS * ND;

    cudaFuncSetAttribute(qkv_mma_kernel, cudaFuncAttributeMaxDynamicSharedMemorySize, QKV_SMEM);
    cudaFuncSetAttribute(attn_mma_kernel, cudaFuncAttributeMaxDynamicSharedMemorySize, ATT_SMEM);

    prep_x_kernel<<<8192, 256>>>(x);
    prep_w_kernel<<<dim3(1024, 3), 256>>>(Wq, Wk, Wv);
    qkv_mma_kernel<<<dim3(24, 64), 256, QKV_SMEM>>>(bq, bk, bv);
    attn_mma_kernel<<<dim3(16, 128), 256, ATT_SMEM>>>(out_ctx, out_att);
}

// round 9
// speedup vs baseline: 1.0139x; 1.0139x over previous
#include <cuda_runtime.h>
#include <cuda_bf16.h>
#include <cstdint>

#define NB 8
#define NS 1024
#define ND 1024
#define NH 16
#define NDH 64
#define KAUG 3072   // augmented K for QKV GEMM: [hi, hi/lo, lo/hi]

// ---------------- scratch (static device globals) ----------------
__device__ float g_rowsum[NB * NH * NS];
__device__ __align__(128) __nv_bfloat16 g_A[(size_t)NB * NS * KAUG];   // [xh|xh|xl]
__device__ __align__(128) __nv_bfloat16 g_Bm[3 * (size_t)ND * KAUG];   // [wh|wl|wh]
// attention operands, bf16 splits, seg-major: [bh][seg][s][64]
__device__ __align__(128) __nv_bfloat16 g_Qs[(size_t)NB * NH * 3 * NS * NDH]; // [qh|qh|ql]*0.125
__device__ __align__(128) __nv_bfloat16 g_Ks[(size_t)NB * NH * 3 * NS * NDH]; // [kh|kl|kh]
__device__ __align__(128) __nv_bfloat16 g_Vs[(size_t)NB * NH * 2 * NS * NDH]; // [vh|vl]

// ---------------- PTX helpers (compute_103-safe) ----------------
__device__ __forceinline__ uint32_t smem_u32(const void* p) {
    uint32_t a;
    asm("{ .reg .u64 t; cvta.to.shared.u64 t, %1; cvt.u32.u64 %0, t; }" : "=r"(a) : "l"(p));
    return a;
}
__device__ __forceinline__ void cp_async16(uint32_t dst, const void* src) {
    asm volatile("cp.async.cg.shared.global [%0], [%1], 16;" :: "r"(dst), "l"(src));
}
#define CP_COMMIT() asm volatile("cp.async.commit_group;" ::: "memory")
#define CP_WAIT(n)  asm volatile("cp.async.wait_group %0;" :: "n"(n) : "memory")

__device__ __forceinline__ void ldsm4(uint32_t* r, uint32_t addr) {
    asm volatile("ldmatrix.sync.aligned.m8n8.x4.shared.b16 {%0,%1,%2,%3}, [%4];"
                 : "=r"(r[0]), "=r"(r[1]), "=r"(r[2]), "=r"(r[3]) : "r"(addr));
}
__device__ __forceinline__ void ldsm2(uint32_t* r, uint32_t addr) {
    asm volatile("ldmatrix.sync.aligned.m8n8.x2.shared.b16 {%0,%1}, [%2];"
                 : "=r"(r[0]), "=r"(r[1]) : "r"(addr));
}
__device__ __forceinline__ void ldsm4t(uint32_t* r, uint32_t addr) {
    asm volatile("ldmatrix.sync.aligned.m8n8.x4.trans.shared.b16 {%0,%1,%2,%3}, [%4];"
                 : "=r"(r[0]), "=r"(r[1]), "=r"(r[2]), "=r"(r[3]) : "r"(addr));
}
__device__ __forceinline__ void mma16816(float* c, const uint32_t* a, const uint32_t* b) {
    asm volatile("mma.sync.aligned.m16n8k16.row.col.f32.bf16.bf16.f32 "
                 "{%0,%1,%2,%3}, {%4,%5,%6,%7}, {%8,%9}, {%0,%1,%2,%3};"
                 : "+f"(c[0]), "+f"(c[1]), "+f"(c[2]), "+f"(c[3])
                 : "r"(a[0]), "r"(a[1]), "r"(a[2]), "r"(a[3]), "r"(b[0]), "r"(b[1]));
}
__device__ __forceinline__ void mma16816v(float* c, const uint32_t* a, uint32_t b0, uint32_t b1) {
    asm volatile("mma.sync.aligned.m16n8k16.row.col.f32.bf16.bf16.f32 "
                 "{%0,%1,%2,%3}, {%4,%5,%6,%7}, {%8,%9}, {%0,%1,%2,%3};"
                 : "+f"(c[0]), "+f"(c[1]), "+f"(c[2]), "+f"(c[3])
                 : "r"(a[0]), "r"(a[1]), "r"(a[2]), "r"(a[3]), "r"(b0), "r"(b1));
}
__device__ __forceinline__ uint32_t sw128(uint32_t off) { return off ^ ((off >> 3) & 0x70); }

// ============================================================================
// Prep: split fp32 -> bf16 hi/lo, build augmented K-major operands for QKV.
// ============================================================================
__global__ __launch_bounds__(256) void prep_x_kernel(const float* __restrict__ x)
{
    size_t e = ((size_t)blockIdx.x * 256 + threadIdx.x) * 4;
    int m = (int)(e >> 10), k = (int)(e & 1023);
    float4 v = *(const float4*)&x[e];
    __nv_bfloat162 h01 = __floats2bfloat162_rn(v.x, v.y);
    __nv_bfloat162 h23 = __floats2bfloat162_rn(v.z, v.w);
    __nv_bfloat162 l01 = __floats2bfloat162_rn(v.x - __bfloat162float(h01.x),
                                               v.y - __bfloat162float(h01.y));
    __nv_bfloat162 l23 = __floats2bfloat162_rn(v.z - __bfloat162float(h23.x),
                                               v.w - __bfloat162float(h23.y));
    size_t ro = (size_t)m * KAUG;
    *(__nv_bfloat162*)&g_A[ro + k]            = h01;
    *(__nv_bfloat162*)&g_A[ro + k + 2]        = h23;
    *(__nv_bfloat162*)&g_A[ro + 1024 + k]     = h01;
    *(__nv_bfloat162*)&g_A[ro + 1024 + k + 2] = h23;
    *(__nv_bfloat162*)&g_A[ro + 2048 + k]     = l01;
    *(__nv_bfloat162*)&g_A[ro + 2048 + k + 2] = l23;
}

__global__ __launch_bounds__(256) void prep_w_kernel(
    const float* __restrict__ Wq, const float* __restrict__ Wk, const float* __restrict__ Wv)
{
    int z = blockIdx.y;
    const float* W = (z == 0) ? Wq : (z == 1) ? Wk : Wv;
    __nv_bfloat16* gb = g_Bm + (size_t)z * ND * KAUG;
    size_t e = ((size_t)blockIdx.x * 256 + threadIdx.x) * 4;
    int n = (int)(e >> 10), k = (int)(e & 1023);
    float4 v = *(const float4*)&W[e];
    __nv_bfloat162 h01 = __floats2bfloat162_rn(v.x, v.y);
    __nv_bfloat162 h23 = __floats2bfloat162_rn(v.z, v.w);
    __nv_bfloat162 l01 = __floats2bfloat162_rn(v.x - __bfloat162float(h01.x),
                                               v.y - __bfloat162float(h01.y));
    __nv_bfloat162 l23 = __floats2bfloat162_rn(v.z - __bfloat162float(h23.x),
                                               v.w - __bfloat162float(h23.y));
    size_t ro = (size_t)n * KAUG;
    *(__nv_bfloat162*)&gb[ro + k]            = h01;
    *(__nv_bfloat162*)&gb[ro + k + 2]        = h23;
    *(__nv_bfloat162*)&gb[ro + 1024 + k]     = l01;
    *(__nv_bfloat162*)&gb[ro + 1024 + k + 2] = l23;
    *(__nv_bfloat162*)&gb[ro + 2048 + k]     = h01;
    *(__nv_bfloat162*)&gb[ro + 2048 + k + 2] = h23;
}

// ============================================================================
// QKV GEMM via mma.sync bf16. CTA 128x128, K-tile 64, 3-stage cp.async
// pipeline (96KB smem), 2 CTAs/SM.
// ============================================================================
#define STAGE_BYTES 32768
#define QKV_SMEM (3 * STAGE_BYTES)

__global__ __launch_bounds__(256, 2)
void qkv_mma_kernel(const float* __restrict__ bq, const float* __restrict__ bk,
                    const float* __restrict__ bv)
{
    extern __shared__ char smraw[];
    __shared__ float biasS[128];
    uint32_t sm = smem_u32(smraw);

    int t = threadIdx.x;
    int wid = t >> 5, lane = t & 31;
    int warp_m = wid & 1, warp_n = wid >> 1;

    int bx = blockIdx.x;
    int z = bx >> 3;
    int n0 = (bx & 7) * 128;
    int m0 = blockIdx.y * 128;

    const float* bias = (z == 0) ? bq : (z == 1) ? bk : bv;
    const __nv_bfloat16* Asrc = g_A + (size_t)m0 * KAUG;
    const __nv_bfloat16* Bsrc = g_Bm + (size_t)z * ND * KAUG + (size_t)n0 * KAUG;

    if (t < 128) biasS[t] = bias[n0 + t];

    auto load_tile = [&](int kt, int s) {
        uint32_t base = sm + s * STAGE_BYTES;
        int k0 = kt * 64;
        #pragma unroll
        for (int i = 0; i < 8; i++) {
            int c = t + i * 256;
            int row = c >> 3, col = c & 7;
            uint32_t off = sw128((uint32_t)((row & 127) * 128 + col * 16));
            const __nv_bfloat16* src = (row < 128)
                ? Asrc + (size_t)row * KAUG + k0 + col * 8
                : Bsrc + (size_t)(row - 128) * KAUG + k0 + col * 8;
            cp_async16(base + (row < 128 ? 0u : 16384u) + off, src);
        }
    };

    float acc[4][4][4];
    #pragma unroll
    for (int mt = 0; mt < 4; mt++)
        #pragma unroll
        for (int nt = 0; nt < 4; nt++)
            #pragma unroll
            for (int r = 0; r < 4; r++) acc[mt][nt][r] = 0.f;

    uint32_t a_row = (uint32_t)(warp_m * 64 + (lane & 15));
    uint32_t a_kb  = (uint32_t)((lane >> 4) << 4);
    uint32_t b_row = (uint32_t)(warp_n * 32 + (lane & 15));

    load_tile(0, 0); CP_COMMIT();
    load_tile(1, 1); CP_COMMIT();

    int cur = 0;
    for (int kt = 0; kt < 48; kt++) {
        if (kt + 1 < 48) CP_WAIT(1); else CP_WAIT(0);
        __syncthreads();
        if (kt + 2 < 48) {
            int nxt = cur + 2; if (nxt >= 3) nxt -= 3;
            load_tile(kt + 2, nxt); CP_COMMIT();
        }

        uint32_t abase = sm + cur * STAGE_BYTES;
        uint32_t bbase = abase + 16384u;
        #pragma unroll
        for (int ks = 0; ks < 4; ks++) {
            uint32_t kb = (uint32_t)(ks * 32);
            uint32_t af[4][4], bw[2][4];
            #pragma unroll
            for (int mt = 0; mt < 4; mt++)
                ldsm4(af[mt], abase + sw128((a_row + mt * 16) * 128 + kb + a_kb));
            #pragma unroll
            for (int p = 0; p < 2; p++)
                ldsm4(bw[p], bbase + sw128((b_row + p * 16) * 128 + kb + a_kb));
            #pragma unroll
            for (int mt = 0; mt < 4; mt++)
                #pragma unroll
                for (int p = 0; p < 2; p++) {
                    mma16816v(acc[mt][2 * p],     af[mt], bw[p][0], bw[p][2]);
                    mma16816v(acc[mt][2 * p + 1], af[mt], bw[p][1], bw[p][3]);
                }
        }
        __syncthreads();
        cur = cur + 1; if (cur >= 3) cur = 0;
    }

    // ---- epilogue: bias (+0.125 scale for Q) -> bf16 hi/lo splits ----
    int gq = lane >> 2;
    float scale = (z == 0) ? 0.125f : 1.0f;
    #pragma unroll
    for (int mt = 0; mt < 4; mt++) {
        int m_lo = m0 + warp_m * 64 + mt * 16 + gq;
        #pragma unroll
        for (int half = 0; half < 2; half++) {
            int m = m_lo + half * 8;
            int b = m >> 10, s = m & 1023;
            #pragma unroll
            for (int nt = 0; nt < 4; nt++) {
                int nc = warp_n * 32 + nt * 8 + (lane & 3) * 2;
                int n = n0 + nc;
                int h = n >> 6, dh = n & 63;
                int bh = b * NH + h;
                float c0 = (acc[mt][nt][half * 2 + 0] + biasS[nc]) * scale;
                float c1 = (acc[mt][nt][half * 2 + 1] + biasS[nc + 1]) * scale;
                __nv_bfloat162 hv = __floats2bfloat162_rn(c0, c1);
                __nv_bfloat162 lv = __floats2bfloat162_rn(c0 - __bfloat162float(hv.x),
                                                          c1 - __bfloat162float(hv.y));
                if (z == 2) {
                    size_t o = (((size_t)bh * 2 + 0) * NS + s) * NDH + dh;
                    *(__nv_bfloat162*)&g_Vs[o] = hv;
                    *(__nv_bfloat162*)&g_Vs[o + (size_t)NS * NDH] = lv;
                } else {
                    __nv_bfloat16* dst = (z == 0) ? g_Qs : g_Ks;
                    size_t o = (((size_t)bh * 3 + 0) * NS + s) * NDH + dh;
                    size_t seg = (size_t)NS * NDH;
                    if (z == 0) {   // [qh|qh|ql]
                        *(__nv_bfloat162*)&dst[o]           = hv;
                        *(__nv_bfloat162*)&dst[o + seg]     = hv;
                        *(__nv_bfloat162*)&dst[o + 2 * seg] = lv;
                    } else {        // [kh|kl|kh]
                        *(__nv_bfloat162*)&dst[o]           = hv;
                        *(__nv_bfloat162*)&dst[o + seg]     = lv;
                        *(__nv_bfloat162*)&dst[o + 2 * seg] = hv;
                    }
                }
            }
        }
    }
}

// ============================================================================
// Attention via mma.sync (round-5/7 proven: 393us). CTA: 64 q x one (b,h).
// 8 k-tiles of 128, double-buffered. QK: M64 N128 K192. AV: 3 split terms.
// ============================================================================
#define QS_OFF 0u
#define KS_OFF 24576u
#define VS_OFF 122880u
#define P_OFF  188416u
#define RS_OFF 221184u
#define ATT_SMEM 221440u

__global__ __launch_bounds__(256, 1)
void attn_mma_kernel(float* __restrict__ out_ctx, float* __restrict__ out_att)
{
    extern __shared__ char smraw[];
    uint32_t sm = smem_u32(smraw);
    float* rowsumS = (float*)(smraw + RS_OFF);

    int t = threadIdx.x;
    int wid = t >> 5, lane = t & 31;
    int warp_m = wid & 1, warp_n = wid >> 1;
    int bh = blockIdx.y;
    int q0 = blockIdx.x * 64;

    const __nv_bfloat16* Qg = g_Qs + ((size_t)bh * 3 * NS + q0) * NDH;
    const __nv_bfloat16* Kg = g_Ks + (size_t)bh * 3 * NS * NDH;
    const __nv_bfloat16* Vg = g_Vs + (size_t)bh * 2 * NS * NDH;

    #pragma unroll
    for (int i = 0; i < 6; i++) {
        int c = t + i * 256;
        int seg = c >> 9, row = (c >> 3) & 63, col = c & 7;
        cp_async16(sm + QS_OFF + seg * 8192u + sw128((uint32_t)(row * 128 + col * 16)),
                   Qg + ((size_t)seg * NS + row) * NDH + col * 8);
    }
    auto load_kv = [&](int kt, int buf) {
        #pragma unroll
        for (int i = 0; i < 12; i++) {
            int c = t + i * 256;
            int seg = c >> 10, row = (c >> 3) & 127, col = c & 7;
            cp_async16(sm + KS_OFF + buf * 49152u + seg * 16384u
                          + sw128((uint32_t)(row * 128 + col * 16)),
                       Kg + (((size_t)seg * NS) + kt * 128 + row) * NDH + col * 8);
        }
        #pragma unroll
        for (int i = 0; i < 8; i++) {
            int c = t + i * 256;
            int hl = c >> 10, row = (c >> 3) & 127, col = c & 7;
            cp_async16(sm + VS_OFF + buf * 32768u + hl * 16384u
                          + sw128((uint32_t)(row * 128 + col * 16)),
                       Vg + (((size_t)hl * NS) + kt * 128 + row) * NDH + col * 8);
        }
    };
    load_kv(0, 0); CP_COMMIT();
    if (t < 64) rowsumS[t] = 0.f;

    float ctx[2][2][4];
    #pragma unroll
    for (int mt = 0; mt < 2; mt++)
        #pragma unroll
        for (int nt = 0; nt < 2; nt++)
            #pragma unroll
            for (int r = 0; r < 4; r++) ctx[mt][nt][r] = 0.f;

    uint32_t a_row = (uint32_t)(warp_m * 32 + (lane & 15));
    uint32_t a_kb  = (uint32_t)((lane >> 4) << 4);
    uint32_t b_row = (uint32_t)(warp_n * 32 + (lane & 7));
    uint32_t b_kb  = (uint32_t)(((lane >> 3) & 1) << 4);

    for (int kt = 0; kt < 8; kt++) {
        int cur = kt & 1;
        CP_WAIT(0);
        __syncthreads();
        if (kt + 1 < 8) { load_kv(kt + 1, cur ^ 1); CP_COMMIT(); }

        float sacc[2][4][4];
        #pragma unroll
        for (int mt = 0; mt < 2; mt++)
            #pragma unroll
            for (int nt = 0; nt < 4; nt++)
                #pragma unroll
                for (int r = 0; r < 4; r++) sacc[mt][nt][r] = 0.f;

        uint32_t kbase = sm + KS_OFF + cur * 49152u;
        #pragma unroll
        for (int ks = 0; ks < 12; ks++) {
            uint32_t seg = (uint32_t)(ks >> 2), kb = (uint32_t)((ks & 3) * 32);
            uint32_t af[2][4], bf[4][2];
            #pragma unroll
            for (int mt = 0; mt < 2; mt++)
                ldsm4(af[mt], sm + QS_OFF + seg * 8192u
                              + sw128((a_row + mt * 16) * 128 + kb + a_kb));
            #pragma unroll
            for (int nt = 0; nt < 4; nt++)
                ldsm2(bf[nt], kbase + seg * 16384u
                              + sw128((b_row + nt * 8) * 128 + kb + b_kb));
            #pragma unroll
            for (int mt = 0; mt < 2; mt++)
                #pragma unroll
                for (int nt = 0; nt < 4; nt++)
                    mma16816(sacc[mt][nt], af[mt], bf[nt]);
        }

        size_t attbase = ((size_t)bh * NS + q0) * NS + (size_t)kt * 128;
        #pragma unroll
        for (int mt = 0; mt < 2; mt++) {
            float p0 = 0.f, p1 = 0.f;
            int r0 = warp_m * 32 + mt * 16 + (lane >> 2);
            #pragma unroll
            for (int nt = 0; nt < 4; nt++) {
                int kc = warp_n * 32 + nt * 8 + (lane & 3) * 2;
                float e0 = __expf(sacc[mt][nt][0]);
                float e1 = __expf(sacc[mt][nt][1]);
                float e2 = __expf(sacc[mt][nt][2]);
                float e3 = __expf(sacc[mt][nt][3]);
                p0 += e0 + e1; p1 += e2 + e3;
                *(float2*)&out_att[attbase + (size_t)r0 * NS + kc]       = make_float2(e0, e1);
                *(float2*)&out_att[attbase + (size_t)(r0 + 8) * NS + kc] = make_float2(e2, e3);
                __nv_bfloat162 h0 = __floats2bfloat162_rn(e0, e1);
                __nv_bfloat162 l0 = __floats2bfloat162_rn(e0 - __bfloat162float(h0.x),
                                                          e1 - __bfloat162float(h0.y));
                __nv_bfloat162 h1 = __floats2bfloat162_rn(e2, e3);
                __nv_bfloat162 l1 = __floats2bfloat162_rn(e2 - __bfloat162float(h1.x),
                                                          e3 - __bfloat162float(h1.y));
                uint32_t po = (uint32_t)((kc >> 6) * 8192) + sw128((uint32_t)(r0 * 128 + (kc & 63) * 2));
                uint32_t po8 = (uint32_t)((kc >> 6) * 8192) + sw128((uint32_t)((r0 + 8) * 128 + (kc & 63) * 2));
                *(__nv_bfloat162*)(smraw + P_OFF + po)            = h0;
                *(__nv_bfloat162*)(smraw + P_OFF + 16384u + po)   = l0;
                *(__nv_bfloat162*)(smraw + P_OFF + po8)           = h1;
                *(__nv_bfloat162*)(smraw + P_OFF + 16384u + po8)  = l1;
            }
            p0 += __shfl_xor_sync(0xffffffffu, p0, 1);
            p0 += __shfl_xor_sync(0xffffffffu, p0, 2);
            p1 += __shfl_xor_sync(0xffffffffu, p1, 1);
            p1 += __shfl_xor_sync(0xffffffffu, p1, 2);
            if ((lane & 3) == 0) {
                atomicAdd(&rowsumS[r0], p0);
                atomicAdd(&rowsumS[r0 + 8], p1);
            }
        }
        __syncthreads();

        uint32_t vbase = sm + VS_OFF + cur * 32768u;
        #pragma unroll
        for (int term = 0; term < 3; term++) {
            uint32_t pb = sm + P_OFF + (term == 2 ? 16384u : 0u);
            uint32_t vb = vbase + (term == 1 ? 16384u : 0u);
            #pragma unroll
            for (int ks = 0; ks < 8; ks++) {
                uint32_t kbyte = (uint32_t)(ks * 32) + a_kb;
                uint32_t af[2][4], bv[4];
                #pragma unroll
                for (int mt = 0; mt < 2; mt++)
                    ldsm4(af[mt], pb + (kbyte >> 7) * 8192u
                                  + sw128((a_row + mt * 16) * 128 + (kbyte & 127)));
                ldsm4t(bv, vb + sw128((uint32_t)((ks * 16 + (lane & 15)) * 128)
                                      + (uint32_t)(warp_n * 32) + (uint32_t)((lane >> 4) * 16)));
                #pragma unroll
                for (int mt = 0; mt < 2; mt++) {
                    mma16816(ctx[mt][0], af[mt], bv);
                    mma16816(ctx[mt][1], af[mt], bv + 2);
                }
            }
        }
        __syncthreads();
    }

    if (t < 64) g_rowsum[(size_t)bh * NS + q0 + t] = rowsumS[t];
    __syncthreads();

    int b = bh >> 4, h = bh & 15;
    #pragma unroll
    for (int mt = 0; mt < 2; mt++) {
        #pragma unroll
        for (int half = 0; half < 2; half++) {
            int r = warp_m * 32 + mt * 16 + (lane >> 2) + half * 8;
            float inv = 1.0f / rowsumS[r];
            size_t o = ((size_t)(b * NS + q0 + r)) * ND + h * NDH;
            #pragma unroll
            for (int nt = 0; nt < 2; nt++) {
                int d = warp_n * 16 + nt * 8 + (lane & 3) * 2;
                float c0 = ctx[mt][nt][half * 2 + 0] * inv;
                float c1 = ctx[mt][nt][half * 2 + 1] * inv;
                *(float2*)&out_ctx[o + d] = make_float2(c0, c1);
            }
        }
    }
}

// ============================================================================
// Normalize attention tensor by row sums (pure HBM pass, full-chip parallel).
// ============================================================================
__global__ __launch_bounds__(256) void norm_kernel(float* __restrict__ att)
{
    size_t i = ((size_t)blockIdx.x * 256 + threadIdx.x) * 4;
    float inv = 1.0f / __ldg(&g_rowsum[i >> 10]);
    float4 v = *(float4*)&att[i];
    v.x *= inv; v.y *= inv; v.z *= inv; v.w *= inv;
    *(float4*)&att[i] = v;
}

extern "C" void kernel_launch(void* const* d_in, const int* in_sizes, int n_in,
                              void* d_out, int out_size) {
    const float* x  = (const float*)d_in[0];
    const float* Wq = (const float*)d_in[1];
    const float* bq = (const float*)d_in[2];
    const float* Wk = (const float*)d_in[3];
    const float* bk = (const float*)d_in[4];
    const float* Wv = (const float*)d_in[5];
    const float* bv = (const float*)d_in[6];
    // d_in[7] structure_bias: constant along the softmax axis -> cancels exactly.

    float* out_ctx = (float*)d_out;
    float* out_att = out_ctx + (size_t)NB * NS * ND;

    cudaFuncSetAttribute(qkv_mma_kernel, cudaFuncAttributeMaxDynamicSharedMemorySize, QKV_SMEM);
    cudaFuncSetAttribute(attn_mma_kernel, cudaFuncAttributeMaxDynamicSharedMemorySize, ATT_SMEM);

    prep_x_kernel<<<8192, 256>>>(x);
    prep_w_kernel<<<dim3(1024, 3), 256>>>(Wq, Wk, Wv);
    qkv_mma_kernel<<<dim3(24, 64), 256, QKV_SMEM>>>(bq, bk, bv);
    attn_mma_kernel<<<dim3(16, 128), 256, ATT_SMEM>>>(out_ctx, out_att);
    norm_kernel<<<131072, 256>>>(out_att);
}

// round 10
// speedup vs baseline: 1.1621x; 1.1462x over previous
#include <cuda_runtime.h>
#include <cuda_bf16.h>
#include <cuda_fp16.h>
#include <cstdint>

#define NB 8
#define NS 1024
#define ND 1024
#define NH 16
#define NDH 64
#define KAUG 2048   // augmented K for QKV GEMM, fp16 2-term: A=[xh|xh], B=[wh|wl]

// ---------------- scratch (static device globals) ----------------
__device__ float g_rowsum[NB * NH * NS];
__device__ __align__(128) __half g_A[(size_t)NB * NS * KAUG];          // [xh|xh]
__device__ __align__(128) __half g_Bm[3 * (size_t)ND * KAUG];          // [wh|wl]
// attention operands, bf16 splits, seg-major: [bh][seg][s][64]
__device__ __align__(128) __nv_bfloat16 g_Qs[(size_t)NB * NH * 3 * NS * NDH]; // [qh|qh|ql]*0.125
__device__ __align__(128) __nv_bfloat16 g_Ks[(size_t)NB * NH * 3 * NS * NDH]; // [kh|kl|kh]
__device__ __align__(128) __nv_bfloat16 g_Vs[(size_t)NB * NH * 2 * NS * NDH]; // [vh|vl]

// ---------------- PTX helpers (compute_103-safe) ----------------
__device__ __forceinline__ uint32_t smem_u32(const void* p) {
    uint32_t a;
    asm("{ .reg .u64 t; cvta.to.shared.u64 t, %1; cvt.u32.u64 %0, t; }" : "=r"(a) : "l"(p));
    return a;
}
__device__ __forceinline__ void cp_async16(uint32_t dst, const void* src) {
    asm volatile("cp.async.cg.shared.global [%0], [%1], 16;" :: "r"(dst), "l"(src));
}
#define CP_COMMIT() asm volatile("cp.async.commit_group;" ::: "memory")
#define CP_WAIT(n)  asm volatile("cp.async.wait_group %0;" :: "n"(n) : "memory")

__device__ __forceinline__ void ldsm4(uint32_t* r, uint32_t addr) {
    asm volatile("ldmatrix.sync.aligned.m8n8.x4.shared.b16 {%0,%1,%2,%3}, [%4];"
                 : "=r"(r[0]), "=r"(r[1]), "=r"(r[2]), "=r"(r[3]) : "r"(addr));
}
__device__ __forceinline__ void ldsm2(uint32_t* r, uint32_t addr) {
    asm volatile("ldmatrix.sync.aligned.m8n8.x2.shared.b16 {%0,%1}, [%2];"
                 : "=r"(r[0]), "=r"(r[1]) : "r"(addr));
}
__device__ __forceinline__ void ldsm4t(uint32_t* r, uint32_t addr) {
    asm volatile("ldmatrix.sync.aligned.m8n8.x4.trans.shared.b16 {%0,%1,%2,%3}, [%4];"
                 : "=r"(r[0]), "=r"(r[1]), "=r"(r[2]), "=r"(r[3]) : "r"(addr));
}
// bf16 mma (attention path)
__device__ __forceinline__ void mma16816(float* c, const uint32_t* a, const uint32_t* b) {
    asm volatile("mma.sync.aligned.m16n8k16.row.col.f32.bf16.bf16.f32 "
                 "{%0,%1,%2,%3}, {%4,%5,%6,%7}, {%8,%9}, {%0,%1,%2,%3};"
                 : "+f"(c[0]), "+f"(c[1]), "+f"(c[2]), "+f"(c[3])
                 : "r"(a[0]), "r"(a[1]), "r"(a[2]), "r"(a[3]), "r"(b[0]), "r"(b[1]));
}
// fp16 mma (QKV path)
__device__ __forceinline__ void mma16816hv(float* c, const uint32_t* a, uint32_t b0, uint32_t b1) {
    asm volatile("mma.sync.aligned.m16n8k16.row.col.f32.f16.f16.f32 "
                 "{%0,%1,%2,%3}, {%4,%5,%6,%7}, {%8,%9}, {%0,%1,%2,%3};"
                 : "+f"(c[0]), "+f"(c[1]), "+f"(c[2]), "+f"(c[3])
                 : "r"(a[0]), "r"(a[1]), "r"(a[2]), "r"(a[3]), "r"(b0), "r"(b1));
}
__device__ __forceinline__ uint32_t sw128(uint32_t off) { return off ^ ((off >> 3) & 0x70); }

// ============================================================================
// Prep: fp16 2-term split operands for QKV.
//   A' segs: [xh | xh]      B' segs: [wh | wl]
// ============================================================================
__global__ __launch_bounds__(256) void prep_x_kernel(const float* __restrict__ x)
{
    size_t e = ((size_t)blockIdx.x * 256 + threadIdx.x) * 4;
    int m = (int)(e >> 10), k = (int)(e & 1023);
    float4 v = *(const float4*)&x[e];
    __half2 h01 = __floats2half2_rn(v.x, v.y);
    __half2 h23 = __floats2half2_rn(v.z, v.w);
    size_t ro = (size_t)m * KAUG;
    *(__half2*)&g_A[ro + k]            = h01;
    *(__half2*)&g_A[ro + k + 2]        = h23;
    *(__half2*)&g_A[ro + 1024 + k]     = h01;
    *(__half2*)&g_A[ro + 1024 + k + 2] = h23;
}

__global__ __launch_bounds__(256) void prep_w_kernel(
    const float* __restrict__ Wq, const float* __restrict__ Wk, const float* __restrict__ Wv)
{
    int z = blockIdx.y;
    const float* W = (z == 0) ? Wq : (z == 1) ? Wk : Wv;
    __half* gb = g_Bm + (size_t)z * ND * KAUG;
    size_t e = ((size_t)blockIdx.x * 256 + threadIdx.x) * 4;
    int n = (int)(e >> 10), k = (int)(e & 1023);
    float4 v = *(const float4*)&W[e];
    __half2 h01 = __floats2half2_rn(v.x, v.y);
    __half2 h23 = __floats2half2_rn(v.z, v.w);
    __half2 l01 = __floats2half2_rn(v.x - __half2float(h01.x),
                                    v.y - __half2float(h01.y));
    __half2 l23 = __floats2half2_rn(v.z - __half2float(h23.x),
                                    v.w - __half2float(h23.y));
    size_t ro = (size_t)n * KAUG;
    *(__half2*)&gb[ro + k]            = h01;
    *(__half2*)&gb[ro + k + 2]        = h23;
    *(__half2*)&gb[ro + 1024 + k]     = l01;
    *(__half2*)&gb[ro + 1024 + k + 2] = l23;
}

// ============================================================================
// QKV GEMM via mma.sync fp16 (2-term split). CTA 128x128, K-tile 64,
// 3-stage cp.async pipeline (96KB smem), 2 CTAs/SM. 32 k-tiles.
// Epilogue: fp32 acc + bias (+0.125 for Q) -> bf16 hi/lo splits for attn.
// ============================================================================
#define STAGE_BYTES 32768
#define QKV_SMEM (3 * STAGE_BYTES)

__global__ __launch_bounds__(256, 2)
void qkv_mma_kernel(const float* __restrict__ bq, const float* __restrict__ bk,
                    const float* __restrict__ bv)
{
    extern __shared__ char smraw[];
    __shared__ float biasS[128];
    uint32_t sm = smem_u32(smraw);

    int t = threadIdx.x;
    int wid = t >> 5, lane = t & 31;
    int warp_m = wid & 1, warp_n = wid >> 1;

    int bx = blockIdx.x;
    int z = bx >> 3;
    int n0 = (bx & 7) * 128;
    int m0 = blockIdx.y * 128;

    const float* bias = (z == 0) ? bq : (z == 1) ? bk : bv;
    const __half* Asrc = g_A + (size_t)m0 * KAUG;
    const __half* Bsrc = g_Bm + (size_t)z * ND * KAUG + (size_t)n0 * KAUG;

    if (t < 128) biasS[t] = bias[n0 + t];

    auto load_tile = [&](int kt, int s) {
        uint32_t base = sm + s * STAGE_BYTES;
        int k0 = kt * 64;
        #pragma unroll
        for (int i = 0; i < 8; i++) {
            int c = t + i * 256;
            int row = c >> 3, col = c & 7;
            uint32_t off = sw128((uint32_t)((row & 127) * 128 + col * 16));
            const __half* src = (row < 128)
                ? Asrc + (size_t)row * KAUG + k0 + col * 8
                : Bsrc + (size_t)(row - 128) * KAUG + k0 + col * 8;
            cp_async16(base + (row < 128 ? 0u : 16384u) + off, src);
        }
    };

    float acc[4][4][4];
    #pragma unroll
    for (int mt = 0; mt < 4; mt++)
        #pragma unroll
        for (int nt = 0; nt < 4; nt++)
            #pragma unroll
            for (int r = 0; r < 4; r++) acc[mt][nt][r] = 0.f;

    uint32_t a_row = (uint32_t)(warp_m * 64 + (lane & 15));
    uint32_t a_kb  = (uint32_t)((lane >> 4) << 4);
    uint32_t b_row = (uint32_t)(warp_n * 32 + (lane & 15));

    load_tile(0, 0); CP_COMMIT();
    load_tile(1, 1); CP_COMMIT();

    int cur = 0;
    for (int kt = 0; kt < 32; kt++) {
        if (kt + 1 < 32) CP_WAIT(1); else CP_WAIT(0);
        __syncthreads();
        if (kt + 2 < 32) {
            int nxt = cur + 2; if (nxt >= 3) nxt -= 3;
            load_tile(kt + 2, nxt); CP_COMMIT();
        }

        uint32_t abase = sm + cur * STAGE_BYTES;
        uint32_t bbase = abase + 16384u;
        #pragma unroll
        for (int ks = 0; ks < 4; ks++) {
            uint32_t kb = (uint32_t)(ks * 32);
            uint32_t af[4][4], bw[2][4];
            #pragma unroll
            for (int mt = 0; mt < 4; mt++)
                ldsm4(af[mt], abase + sw128((a_row + mt * 16) * 128 + kb + a_kb));
            #pragma unroll
            for (int p = 0; p < 2; p++)
                ldsm4(bw[p], bbase + sw128((b_row + p * 16) * 128 + kb + a_kb));
            #pragma unroll
            for (int mt = 0; mt < 4; mt++)
                #pragma unroll
                for (int p = 0; p < 2; p++) {
                    mma16816hv(acc[mt][2 * p],     af[mt], bw[p][0], bw[p][2]);
                    mma16816hv(acc[mt][2 * p + 1], af[mt], bw[p][1], bw[p][3]);
                }
        }
        __syncthreads();
        cur = cur + 1; if (cur >= 3) cur = 0;
    }

    // ---- epilogue: bias (+0.125 scale for Q) -> bf16 hi/lo splits ----
    int gq = lane >> 2;
    float scale = (z == 0) ? 0.125f : 1.0f;
    #pragma unroll
    for (int mt = 0; mt < 4; mt++) {
        int m_lo = m0 + warp_m * 64 + mt * 16 + gq;
        #pragma unroll
        for (int half = 0; half < 2; half++) {
            int m = m_lo + half * 8;
            int b = m >> 10, s = m & 1023;
            #pragma unroll
            for (int nt = 0; nt < 4; nt++) {
                int nc = warp_n * 32 + nt * 8 + (lane & 3) * 2;
                int n = n0 + nc;
                int h = n >> 6, dh = n & 63;
                int bh = b * NH + h;
                float c0 = (acc[mt][nt][half * 2 + 0] + biasS[nc]) * scale;
                float c1 = (acc[mt][nt][half * 2 + 1] + biasS[nc + 1]) * scale;
                __nv_bfloat162 hv = __floats2bfloat162_rn(c0, c1);
                __nv_bfloat162 lv = __floats2bfloat162_rn(c0 - __bfloat162float(hv.x),
                                                          c1 - __bfloat162float(hv.y));
                if (z == 2) {
                    size_t o = (((size_t)bh * 2 + 0) * NS + s) * NDH + dh;
                    *(__nv_bfloat162*)&g_Vs[o] = hv;
                    *(__nv_bfloat162*)&g_Vs[o + (size_t)NS * NDH] = lv;
                } else {
                    __nv_bfloat16* dst = (z == 0) ? g_Qs : g_Ks;
                    size_t o = (((size_t)bh * 3 + 0) * NS + s) * NDH + dh;
                    size_t seg = (size_t)NS * NDH;
                    if (z == 0) {   // [qh|qh|ql]
                        *(__nv_bfloat162*)&dst[o]           = hv;
                        *(__nv_bfloat162*)&dst[o + seg]     = hv;
                        *(__nv_bfloat162*)&dst[o + 2 * seg] = lv;
                    } else {        // [kh|kl|kh]
                        *(__nv_bfloat162*)&dst[o]           = hv;
                        *(__nv_bfloat162*)&dst[o + seg]     = lv;
                        *(__nv_bfloat162*)&dst[o + 2 * seg] = hv;
                    }
                }
            }
        }
    }
}

// ============================================================================
// Attention via mma.sync (proven 393us). CTA: 64 q x one (b,h). 8 k-tiles
// of 128, double-buffered. QK: M64 N128 K192. AV: 3 split terms.
// ============================================================================
#define QS_OFF 0u
#define KS_OFF 24576u
#define VS_OFF 122880u
#define P_OFF  188416u
#define RS_OFF 221184u
#define ATT_SMEM 221440u

__global__ __launch_bounds__(256, 1)
void attn_mma_kernel(float* __restrict__ out_ctx, float* __restrict__ out_att)
{
    extern __shared__ char smraw[];
    uint32_t sm = smem_u32(smraw);
    float* rowsumS = (float*)(smraw + RS_OFF);

    int t = threadIdx.x;
    int wid = t >> 5, lane = t & 31;
    int warp_m = wid & 1, warp_n = wid >> 1;
    int bh = blockIdx.y;
    int q0 = blockIdx.x * 64;

    const __nv_bfloat16* Qg = g_Qs + ((size_t)bh * 3 * NS + q0) * NDH;
    const __nv_bfloat16* Kg = g_Ks + (size_t)bh * 3 * NS * NDH;
    const __nv_bfloat16* Vg = g_Vs + (size_t)bh * 2 * NS * NDH;

    #pragma unroll
    for (int i = 0; i < 6; i++) {
        int c = t + i * 256;
        int seg = c >> 9, row = (c >> 3) & 63, col = c & 7;
        cp_async16(sm + QS_OFF + seg * 8192u + sw128((uint32_t)(row * 128 + col * 16)),
                   Qg + ((size_t)seg * NS + row) * NDH + col * 8);
    }
    auto load_kv = [&](int kt, int buf) {
        #pragma unroll
        for (int i = 0; i < 12; i++) {
            int c = t + i * 256;
            int seg = c >> 10, row = (c >> 3) & 127, col = c & 7;
            cp_async16(sm + KS_OFF + buf * 49152u + seg * 16384u
                          + sw128((uint32_t)(row * 128 + col * 16)),
                       Kg + (((size_t)seg * NS) + kt * 128 + row) * NDH + col * 8);
        }
        #pragma unroll
        for (int i = 0; i < 8; i++) {
            int c = t + i * 256;
            int hl = c >> 10, row = (c >> 3) & 127, col = c & 7;
            cp_async16(sm + VS_OFF + buf * 32768u + hl * 16384u
                          + sw128((uint32_t)(row * 128 + col * 16)),
                       Vg + (((size_t)hl * NS) + kt * 128 + row) * NDH + col * 8);
        }
    };
    load_kv(0, 0); CP_COMMIT();
    if (t < 64) rowsumS[t] = 0.f;

    float ctx[2][2][4];
    #pragma unroll
    for (int mt = 0; mt < 2; mt++)
        #pragma unroll
        for (int nt = 0; nt < 2; nt++)
            #pragma unroll
            for (int r = 0; r < 4; r++) ctx[mt][nt][r] = 0.f;

    uint32_t a_row = (uint32_t)(warp_m * 32 + (lane & 15));
    uint32_t a_kb  = (uint32_t)((lane >> 4) << 4);
    uint32_t b_row = (uint32_t)(warp_n * 32 + (lane & 7));
    uint32_t b_kb  = (uint32_t)(((lane >> 3) & 1) << 4);

    for (int kt = 0; kt < 8; kt++) {
        int cur = kt & 1;
        CP_WAIT(0);
        __syncthreads();
        if (kt + 1 < 8) { load_kv(kt + 1, cur ^ 1); CP_COMMIT(); }

        float sacc[2][4][4];
        #pragma unroll
        for (int mt = 0; mt < 2; mt++)
            #pragma unroll
            for (int nt = 0; nt < 4; nt++)
                #pragma unroll
                for (int r = 0; r < 4; r++) sacc[mt][nt][r] = 0.f;

        uint32_t kbase = sm + KS_OFF + cur * 49152u;
        #pragma unroll
        for (int ks = 0; ks < 12; ks++) {
            uint32_t seg = (uint32_t)(ks >> 2), kb = (uint32_t)((ks & 3) * 32);
            uint32_t af[2][4], bf[4][2];
            #pragma unroll
            for (int mt = 0; mt < 2; mt++)
                ldsm4(af[mt], sm + QS_OFF + seg * 8192u
                              + sw128((a_row + mt * 16) * 128 + kb + a_kb));
            #pragma unroll
            for (int nt = 0; nt < 4; nt++)
                ldsm2(bf[nt], kbase + seg * 16384u
                              + sw128((b_row + nt * 8) * 128 + kb + b_kb));
            #pragma unroll
            for (int mt = 0; mt < 2; mt++)
                #pragma unroll
                for (int nt = 0; nt < 4; nt++)
                    mma16816(sacc[mt][nt], af[mt], bf[nt]);
        }

        size_t attbase = ((size_t)bh * NS + q0) * NS + (size_t)kt * 128;
        #pragma unroll
        for (int mt = 0; mt < 2; mt++) {
            float p0 = 0.f, p1 = 0.f;
            int r0 = warp_m * 32 + mt * 16 + (lane >> 2);
            #pragma unroll
            for (int nt = 0; nt < 4; nt++) {
                int kc = warp_n * 32 + nt * 8 + (lane & 3) * 2;
                float e0 = __expf(sacc[mt][nt][0]);
                float e1 = __expf(sacc[mt][nt][1]);
                float e2 = __expf(sacc[mt][nt][2]);
                float e3 = __expf(sacc[mt][nt][3]);
                p0 += e0 + e1; p1 += e2 + e3;
                *(float2*)&out_att[attbase + (size_t)r0 * NS + kc]       = make_float2(e0, e1);
                *(float2*)&out_att[attbase + (size_t)(r0 + 8) * NS + kc] = make_float2(e2, e3);
                __nv_bfloat162 h0 = __floats2bfloat162_rn(e0, e1);
                __nv_bfloat162 l0 = __floats2bfloat162_rn(e0 - __bfloat162float(h0.x),
                                                          e1 - __bfloat162float(h0.y));
                __nv_bfloat162 h1 = __floats2bfloat162_rn(e2, e3);
                __nv_bfloat162 l1 = __floats2bfloat162_rn(e2 - __bfloat162float(h1.x),
                                                          e3 - __bfloat162float(h1.y));
                uint32_t po = (uint32_t)((kc >> 6) * 8192) + sw128((uint32_t)(r0 * 128 + (kc & 63) * 2));
                uint32_t po8 = (uint32_t)((kc >> 6) * 8192) + sw128((uint32_t)((r0 + 8) * 128 + (kc & 63) * 2));
                *(__nv_bfloat162*)(smraw + P_OFF + po)            = h0;
                *(__nv_bfloat162*)(smraw + P_OFF + 16384u + po)   = l0;
                *(__nv_bfloat162*)(smraw + P_OFF + po8)           = h1;
                *(__nv_bfloat162*)(smraw + P_OFF + 16384u + po8)  = l1;
            }
            p0 += __shfl_xor_sync(0xffffffffu, p0, 1);
            p0 += __shfl_xor_sync(0xffffffffu, p0, 2);
            p1 += __shfl_xor_sync(0xffffffffu, p1, 1);
            p1 += __shfl_xor_sync(0xffffffffu, p1, 2);
            if ((lane & 3) == 0) {
                atomicAdd(&rowsumS[r0], p0);
                atomicAdd(&rowsumS[r0 + 8], p1);
            }
        }
        __syncthreads();

        uint32_t vbase = sm + VS_OFF + cur * 32768u;
        #pragma unroll
        for (int term = 0; term < 3; term++) {
            uint32_t pb = sm + P_OFF + (term == 2 ? 16384u : 0u);
            uint32_t vb = vbase + (term == 1 ? 16384u : 0u);
            #pragma unroll
            for (int ks = 0; ks < 8; ks++) {
                uint32_t kbyte = (uint32_t)(ks * 32) + a_kb;
                uint32_t af[2][4], bv[4];
                #pragma unroll
                for (int mt = 0; mt < 2; mt++)
                    ldsm4(af[mt], pb + (kbyte >> 7) * 8192u
                                  + sw128((a_row + mt * 16) * 128 + (kbyte & 127)));
                ldsm4t(bv, vb + sw128((uint32_t)((ks * 16 + (lane & 15)) * 128)
                                      + (uint32_t)(warp_n * 32) + (uint32_t)((lane >> 4) * 16)));
                #pragma unroll
                for (int mt = 0; mt < 2; mt++) {
                    mma16816(ctx[mt][0], af[mt], bv);
                    mma16816(ctx[mt][1], af[mt], bv + 2);
                }
            }
        }
        __syncthreads();
    }

    if (t < 64) g_rowsum[(size_t)bh * NS + q0 + t] = rowsumS[t];
    __syncthreads();

    int b = bh >> 4, h = bh & 15;
    #pragma unroll
    for (int mt = 0; mt < 2; mt++) {
        #pragma unroll
        for (int half = 0; half < 2; half++) {
            int r = warp_m * 32 + mt * 16 + (lane >> 2) + half * 8;
            float inv = 1.0f / rowsumS[r];
            size_t o = ((size_t)(b * NS + q0 + r)) * ND + h * NDH;
            #pragma unroll
            for (int nt = 0; nt < 2; nt++) {
                int d = warp_n * 16 + nt * 8 + (lane & 3) * 2;
                float c0 = ctx[mt][nt][half * 2 + 0] * inv;
                float c1 = ctx[mt][nt][half * 2 + 1] * inv;
                *(float2*)&out_ctx[o + d] = make_float2(c0, c1);
            }
        }
    }
}

// ============================================================================
// Normalize attention tensor by row sums (pure HBM pass, full-chip parallel).
// ============================================================================
__global__ __launch_bounds__(256) void norm_kernel(float* __restrict__ att)
{
    size_t i = ((size_t)blockIdx.x * 256 + threadIdx.x) * 4;
    float inv = 1.0f / __ldg(&g_rowsum[i >> 10]);
    float4 v = *(float4*)&att[i];
    v.x *= inv; v.y *= inv; v.z *= inv; v.w *= inv;
    *(float4*)&att[i] = v;
}

extern "C" void kernel_launch(void* const* d_in, const int* in_sizes, int n_in,
                              void* d_out, int out_size) {
    const float* x  = (const float*)d_in[0];
    const float* Wq = (const float*)d_in[1];
    const float* bq = (const float*)d_in[2];
    const float* Wk = (const float*)d_in[3];
    const float* bk = (const float*)d_in[4];
    const float* Wv = (const float*)d_in[5];
    const float* bv = (const float*)d_in[6];
    // d_in[7] structure_bias: constant along the softmax axis -> cancels exactly.

    float* out_ctx = (float*)d_out;
    float* out_att = out_ctx + (size_t)NB * NS * ND;

    cudaFuncSetAttribute(qkv_mma_kernel, cudaFuncAttributeMaxDynamicSharedMemorySize, QKV_SMEM);
    cudaFuncSetAttribute(attn_mma_kernel, cudaFuncAttributeMaxDynamicSharedMemorySize, ATT_SMEM);

    prep_x_kernel<<<8192, 256>>>(x);
    prep_w_kernel<<<dim3(1024, 3), 256>>>(Wq, Wk, Wv);
    qkv_mma_kernel<<<dim3(24, 64), 256, QKV_SMEM>>>(bq, bk, bv);
    attn_mma_kernel<<<dim3(16, 128), 256, ATT_SMEM>>>(out_ctx, out_att);
    norm_kernel<<<131072, 256>>>(out_att);
}

// round 11
// speedup vs baseline: 1.3382x; 1.1515x over previous
#include <cuda_runtime.h>
#include <cuda_bf16.h>
#include <cuda_fp16.h>
#include <cstdint>

#define NB 8
#define NS 1024
#define ND 1024
#define NH 16
#define NDH 64
#define KAUG 2048   // augmented K for QKV GEMM, fp16 2-term: A=[xh|xh], B=[wh|wl]

// ---------------- scratch (static device globals) ----------------
__device__ float g_rowsum[NB * NH * NS];
__device__ __align__(128) __half g_A[(size_t)NB * NS * KAUG];          // [xh|xh]
__device__ __align__(128) __half g_Bm[3 * (size_t)ND * KAUG];          // [wh|wl]
// attention operands, fp16 splits, seg-major: [bh][seg][s][64]
__device__ __align__(128) __half g_Qs[(size_t)NB * NH * NS * NDH];     // [qh]*0.125
__device__ __align__(128) __half g_Ks[(size_t)NB * NH * 2 * NS * NDH]; // [kh|kl]
__device__ __align__(128) __half g_Vs[(size_t)NB * NH * 2 * NS * NDH]; // [vh|vl]

// ---------------- PTX helpers (compute_103-safe) ----------------
__device__ __forceinline__ uint32_t smem_u32(const void* p) {
    uint32_t a;
    asm("{ .reg .u64 t; cvta.to.shared.u64 t, %1; cvt.u32.u64 %0, t; }" : "=r"(a) : "l"(p));
    return a;
}
__device__ __forceinline__ void cp_async16(uint32_t dst, const void* src) {
    asm volatile("cp.async.cg.shared.global [%0], [%1], 16;" :: "r"(dst), "l"(src));
}
#define CP_COMMIT() asm volatile("cp.async.commit_group;" ::: "memory")
#define CP_WAIT(n)  asm volatile("cp.async.wait_group %0;" :: "n"(n) : "memory")

__device__ __forceinline__ void ldsm4(uint32_t* r, uint32_t addr) {
    asm volatile("ldmatrix.sync.aligned.m8n8.x4.shared.b16 {%0,%1,%2,%3}, [%4];"
                 : "=r"(r[0]), "=r"(r[1]), "=r"(r[2]), "=r"(r[3]) : "r"(addr));
}
__device__ __forceinline__ void ldsm2(uint32_t* r, uint32_t addr) {
    asm volatile("ldmatrix.sync.aligned.m8n8.x2.shared.b16 {%0,%1}, [%2];"
                 : "=r"(r[0]), "=r"(r[1]) : "r"(addr));
}
__device__ __forceinline__ void ldsm4t(uint32_t* r, uint32_t addr) {
    asm volatile("ldmatrix.sync.aligned.m8n8.x4.trans.shared.b16 {%0,%1,%2,%3}, [%4];"
                 : "=r"(r[0]), "=r"(r[1]), "=r"(r[2]), "=r"(r[3]) : "r"(addr));
}
// fp16 mma
__device__ __forceinline__ void mma16816h(float* c, const uint32_t* a, const uint32_t* b) {
    asm volatile("mma.sync.aligned.m16n8k16.row.col.f32.f16.f16.f32 "
                 "{%0,%1,%2,%3}, {%4,%5,%6,%7}, {%8,%9}, {%0,%1,%2,%3};"
                 : "+f"(c[0]), "+f"(c[1]), "+f"(c[2]), "+f"(c[3])
                 : "r"(a[0]), "r"(a[1]), "r"(a[2]), "r"(a[3]), "r"(b[0]), "r"(b[1]));
}
__device__ __forceinline__ void mma16816hv(float* c, const uint32_t* a, uint32_t b0, uint32_t b1) {
    asm volatile("mma.sync.aligned.m16n8k16.row.col.f32.f16.f16.f32 "
                 "{%0,%1,%2,%3}, {%4,%5,%6,%7}, {%8,%9}, {%0,%1,%2,%3};"
                 : "+f"(c[0]), "+f"(c[1]), "+f"(c[2]), "+f"(c[3])
                 : "r"(a[0]), "r"(a[1]), "r"(a[2]), "r"(a[3]), "r"(b0), "r"(b1));
}
__device__ __forceinline__ uint32_t sw128(uint32_t off) { return off ^ ((off >> 3) & 0x70); }

// ============================================================================
// Prep: fp16 2-term split operands for QKV. A'=[xh|xh], B'=[wh|wl].
// ============================================================================
__global__ __launch_bounds__(256) void prep_x_kernel(const float* __restrict__ x)
{
    size_t e = ((size_t)blockIdx.x * 256 + threadIdx.x) * 4;
    int m = (int)(e >> 10), k = (int)(e & 1023);
    float4 v = *(const float4*)&x[e];
    __half2 h01 = __floats2half2_rn(v.x, v.y);
    __half2 h23 = __floats2half2_rn(v.z, v.w);
    size_t ro = (size_t)m * KAUG;
    *(__half2*)&g_A[ro + k]            = h01;
    *(__half2*)&g_A[ro + k + 2]        = h23;
    *(__half2*)&g_A[ro + 1024 + k]     = h01;
    *(__half2*)&g_A[ro + 1024 + k + 2] = h23;
}

__global__ __launch_bounds__(256) void prep_w_kernel(
    const float* __restrict__ Wq, const float* __restrict__ Wk, const float* __restrict__ Wv)
{
    int z = blockIdx.y;
    const float* W = (z == 0) ? Wq : (z == 1) ? Wk : Wv;
    __half* gb = g_Bm + (size_t)z * ND * KAUG;
    size_t e = ((size_t)blockIdx.x * 256 + threadIdx.x) * 4;
    int n = (int)(e >> 10), k = (int)(e & 1023);
    float4 v = *(const float4*)&W[e];
    __half2 h01 = __floats2half2_rn(v.x, v.y);
    __half2 h23 = __floats2half2_rn(v.z, v.w);
    __half2 l01 = __floats2half2_rn(v.x - __half2float(h01.x),
                                    v.y - __half2float(h01.y));
    __half2 l23 = __floats2half2_rn(v.z - __half2float(h23.x),
                                    v.w - __half2float(h23.y));
    size_t ro = (size_t)n * KAUG;
    *(__half2*)&gb[ro + k]            = h01;
    *(__half2*)&gb[ro + k + 2]        = h23;
    *(__half2*)&gb[ro + 1024 + k]     = l01;
    *(__half2*)&gb[ro + 1024 + k + 2] = l23;
}

// ============================================================================
// QKV GEMM via mma.sync fp16 (2-term split). CTA 128x128, K-tile 64,
// 3-stage cp.async pipeline, 2 CTAs/SM. Epilogue -> fp16 attn operands.
// ============================================================================
#define STAGE_BYTES 32768
#define QKV_SMEM (3 * STAGE_BYTES)

__global__ __launch_bounds__(256, 2)
void qkv_mma_kernel(const float* __restrict__ bq, const float* __restrict__ bk,
                    const float* __restrict__ bv)
{
    extern __shared__ char smraw[];
    __shared__ float biasS[128];
    uint32_t sm = smem_u32(smraw);

    int t = threadIdx.x;
    int wid = t >> 5, lane = t & 31;
    int warp_m = wid & 1, warp_n = wid >> 1;

    int bx = blockIdx.x;
    int z = bx >> 3;
    int n0 = (bx & 7) * 128;
    int m0 = blockIdx.y * 128;

    const float* bias = (z == 0) ? bq : (z == 1) ? bk : bv;
    const __half* Asrc = g_A + (size_t)m0 * KAUG;
    const __half* Bsrc = g_Bm + (size_t)z * ND * KAUG + (size_t)n0 * KAUG;

    if (t < 128) biasS[t] = bias[n0 + t];

    auto load_tile = [&](int kt, int s) {
        uint32_t base = sm + s * STAGE_BYTES;
        int k0 = kt * 64;
        #pragma unroll
        for (int i = 0; i < 8; i++) {
            int c = t + i * 256;
            int row = c >> 3, col = c & 7;
            uint32_t off = sw128((uint32_t)((row & 127) * 128 + col * 16));
            const __half* src = (row < 128)
                ? Asrc + (size_t)row * KAUG + k0 + col * 8
                : Bsrc + (size_t)(row - 128) * KAUG + k0 + col * 8;
            cp_async16(base + (row < 128 ? 0u : 16384u) + off, src);
        }
    };

    float acc[4][4][4];
    #pragma unroll
    for (int mt = 0; mt < 4; mt++)
        #pragma unroll
        for (int nt = 0; nt < 4; nt++)
            #pragma unroll
            for (int r = 0; r < 4; r++) acc[mt][nt][r] = 0.f;

    uint32_t a_row = (uint32_t)(warp_m * 64 + (lane & 15));
    uint32_t a_kb  = (uint32_t)((lane >> 4) << 4);
    uint32_t b_row = (uint32_t)(warp_n * 32 + (lane & 15));

    load_tile(0, 0); CP_COMMIT();
    load_tile(1, 1); CP_COMMIT();

    int cur = 0;
    for (int kt = 0; kt < 32; kt++) {
        if (kt + 1 < 32) CP_WAIT(1); else CP_WAIT(0);
        __syncthreads();
        if (kt + 2 < 32) {
            int nxt = cur + 2; if (nxt >= 3) nxt -= 3;
            load_tile(kt + 2, nxt); CP_COMMIT();
        }

        uint32_t abase = sm + cur * STAGE_BYTES;
        uint32_t bbase = abase + 16384u;
        #pragma unroll
        for (int ks = 0; ks < 4; ks++) {
            uint32_t kb = (uint32_t)(ks * 32);
            uint32_t af[4][4], bw[2][4];
            #pragma unroll
            for (int mt = 0; mt < 4; mt++)
                ldsm4(af[mt], abase + sw128((a_row + mt * 16) * 128 + kb + a_kb));
            #pragma unroll
            for (int p = 0; p < 2; p++)
                ldsm4(bw[p], bbase + sw128((b_row + p * 16) * 128 + kb + a_kb));
            #pragma unroll
            for (int mt = 0; mt < 4; mt++)
                #pragma unroll
                for (int p = 0; p < 2; p++) {
                    mma16816hv(acc[mt][2 * p],     af[mt], bw[p][0], bw[p][2]);
                    mma16816hv(acc[mt][2 * p + 1], af[mt], bw[p][1], bw[p][3]);
                }
        }
        __syncthreads();
        cur = cur + 1; if (cur >= 3) cur = 0;
    }

    // ---- epilogue: bias (+0.125 for Q) -> fp16 operands for attention ----
    int gq = lane >> 2;
    float scale = (z == 0) ? 0.125f : 1.0f;
    #pragma unroll
    for (int mt = 0; mt < 4; mt++) {
        int m_lo = m0 + warp_m * 64 + mt * 16 + gq;
        #pragma unroll
        for (int half = 0; half < 2; half++) {
            int m = m_lo + half * 8;
            int b = m >> 10, s = m & 1023;
            #pragma unroll
            for (int nt = 0; nt < 4; nt++) {
                int nc = warp_n * 32 + nt * 8 + (lane & 3) * 2;
                int n = n0 + nc;
                int h = n >> 6, dh = n & 63;
                int bh = b * NH + h;
                float c0 = (acc[mt][nt][half * 2 + 0] + biasS[nc]) * scale;
                float c1 = (acc[mt][nt][half * 2 + 1] + biasS[nc + 1]) * scale;
                __half2 hv = __floats2half2_rn(c0, c1);
                if (z == 0) {          // Q: single seg
                    size_t o = ((size_t)bh * NS + s) * NDH + dh;
                    *(__half2*)&g_Qs[o] = hv;
                } else {               // K/V: [h|l] 2 segs
                    __half2 lv = __floats2half2_rn(c0 - __half2float(hv.x),
                                                   c1 - __half2float(hv.y));
                    __half* dst = (z == 1) ? g_Ks : g_Vs;
                    size_t o = (((size_t)bh * 2) * NS + s) * NDH + dh;
                    *(__half2*)&dst[o] = hv;
                    *(__half2*)&dst[o + (size_t)NS * NDH] = lv;
                }
            }
        }
    }
}

// ============================================================================
// Attention via mma.sync fp16. CTA: 64 q x one (b,h). 8 k-tiles of 128,
// double-buffered. QK: M64 N128 K128 (qh vs [kh|kl], af shared).
// P stored fp16 h-only. AV: 2 terms (Ph*Vh + Ph*Vl), af shared.
// ============================================================================
#define QS_OFF 0u            // 64 x 128B = 8192
#define KS_OFF 8192u         // 2 bufs x (2 segs x 16384) = 65536
#define VS_OFF 73728u        // 2 bufs x 32768 = 65536
#define P_OFF  139264u       // 2 sub-tiles x 8192 = 16384 (fp16)
#define RS_OFF 155648u       // 64 floats
#define ATT_SMEM 155904u

__global__ __launch_bounds__(256, 1)
void attn_mma_kernel(float* __restrict__ out_ctx, float* __restrict__ out_att)
{
    extern __shared__ char smraw[];
    uint32_t sm = smem_u32(smraw);
    float* rowsumS = (float*)(smraw + RS_OFF);

    int t = threadIdx.x;
    int wid = t >> 5, lane = t & 31;
    int warp_m = wid & 1, warp_n = wid >> 1;
    int bh = blockIdx.y;
    int q0 = blockIdx.x * 64;

    const __half* Qg = g_Qs + ((size_t)bh * NS + q0) * NDH;
    const __half* Kg = g_Ks + (size_t)bh * 2 * NS * NDH;
    const __half* Vg = g_Vs + (size_t)bh * 2 * NS * NDH;

    // prologue: resident Q (8KB)
    #pragma unroll
    for (int i = 0; i < 2; i++) {
        int c = t + i * 256;
        int row = (c >> 3) & 63, col = c & 7;
        cp_async16(sm + QS_OFF + sw128((uint32_t)(row * 128 + col * 16)),
                   Qg + (size_t)row * NDH + col * 8);
    }
    auto load_kv = [&](int kt, int buf) {
        #pragma unroll
        for (int i = 0; i < 8; i++) {      // K: 2 segs x 16KB
            int c = t + i * 256;
            int seg = c >> 10, row = (c >> 3) & 127, col = c & 7;
            cp_async16(sm + KS_OFF + buf * 32768u + seg * 16384u
                          + sw128((uint32_t)(row * 128 + col * 16)),
                       Kg + (((size_t)seg * NS) + kt * 128 + row) * NDH + col * 8);
        }
        #pragma unroll
        for (int i = 0; i < 8; i++) {      // V: 2 segs x 16KB
            int c = t + i * 256;
            int hl = c >> 10, row = (c >> 3) & 127, col = c & 7;
            cp_async16(sm + VS_OFF + buf * 32768u + hl * 16384u
                          + sw128((uint32_t)(row * 128 + col * 16)),
                       Vg + (((size_t)hl * NS) + kt * 128 + row) * NDH + col * 8);
        }
    };
    load_kv(0, 0); CP_COMMIT();
    if (t < 64) rowsumS[t] = 0.f;

    float ctx[2][2][4];
    #pragma unroll
    for (int mt = 0; mt < 2; mt++)
        #pragma unroll
        for (int nt = 0; nt < 2; nt++)
            #pragma unroll
            for (int r = 0; r < 4; r++) ctx[mt][nt][r] = 0.f;

    uint32_t a_row = (uint32_t)(warp_m * 32 + (lane & 15));
    uint32_t a_kb  = (uint32_t)((lane >> 4) << 4);
    uint32_t b_row = (uint32_t)(warp_n * 32 + (lane & 7));
    uint32_t b_kb  = (uint32_t)(((lane >> 3) & 1) << 4);

    for (int kt = 0; kt < 8; kt++) {
        int cur = kt & 1;
        CP_WAIT(0);
        __syncthreads();
        if (kt + 1 < 8) { load_kv(kt + 1, cur ^ 1); CP_COMMIT(); }

        // ---- QK: M64 x N128, K = 64 x (kh + kl) ----
        float sacc[2][4][4];
        #pragma unroll
        for (int mt = 0; mt < 2; mt++)
            #pragma unroll
            for (int nt = 0; nt < 4; nt++)
                #pragma unroll
                for (int r = 0; r < 4; r++) sacc[mt][nt][r] = 0.f;

        uint32_t kbase = sm + KS_OFF + cur * 32768u;
        #pragma unroll
        for (int ks = 0; ks < 4; ks++) {
            uint32_t kb = (uint32_t)(ks * 32);
            uint32_t af[2][4];
            #pragma unroll
            for (int mt = 0; mt < 2; mt++)
                ldsm4(af[mt], sm + QS_OFF + sw128((a_row + mt * 16) * 128 + kb + a_kb));
            #pragma unroll
            for (int seg = 0; seg < 2; seg++) {
                uint32_t bf[4][2];
                #pragma unroll
                for (int nt = 0; nt < 4; nt++)
                    ldsm2(bf[nt], kbase + seg * 16384u
                                  + sw128((b_row + nt * 8) * 128 + kb + b_kb));
                #pragma unroll
                for (int mt = 0; mt < 2; mt++)
                    #pragma unroll
                    for (int nt = 0; nt < 4; nt++)
                        mma16816h(sacc[mt][nt], af[mt], bf[nt]);
            }
        }

        // ---- exp, att out, rowsum, P (fp16 h-only) to smem ----
        size_t attbase = ((size_t)bh * NS + q0) * NS + (size_t)kt * 128;
        #pragma unroll
        for (int mt = 0; mt < 2; mt++) {
            float p0 = 0.f, p1 = 0.f;
            int r0 = warp_m * 32 + mt * 16 + (lane >> 2);
            #pragma unroll
            for (int nt = 0; nt < 4; nt++) {
                int kc = warp_n * 32 + nt * 8 + (lane & 3) * 2;
                float e0 = __expf(sacc[mt][nt][0]);
                float e1 = __expf(sacc[mt][nt][1]);
                float e2 = __expf(sacc[mt][nt][2]);
                float e3 = __expf(sacc[mt][nt][3]);
                p0 += e0 + e1; p1 += e2 + e3;
                *(float2*)&out_att[attbase + (size_t)r0 * NS + kc]       = make_float2(e0, e1);
                *(float2*)&out_att[attbase + (size_t)(r0 + 8) * NS + kc] = make_float2(e2, e3);
                __half2 h0 = __floats2half2_rn(e0, e1);
                __half2 h1 = __floats2half2_rn(e2, e3);
                uint32_t po  = (uint32_t)((kc >> 6) * 8192) + sw128((uint32_t)(r0 * 128 + (kc & 63) * 2));
                uint32_t po8 = (uint32_t)((kc >> 6) * 8192) + sw128((uint32_t)((r0 + 8) * 128 + (kc & 63) * 2));
                *(__half2*)(smraw + P_OFF + po)  = h0;
                *(__half2*)(smraw + P_OFF + po8) = h1;
            }
            p0 += __shfl_xor_sync(0xffffffffu, p0, 1);
            p0 += __shfl_xor_sync(0xffffffffu, p0, 2);
            p1 += __shfl_xor_sync(0xffffffffu, p1, 1);
            p1 += __shfl_xor_sync(0xffffffffu, p1, 2);
            if ((lane & 3) == 0) {
                atomicAdd(&rowsumS[r0], p0);
                atomicAdd(&rowsumS[r0 + 8], p1);
            }
        }
        __syncthreads();   // P complete before AV reads

        // ---- AV: ctx += Ph * (Vh + Vl), M64 x N64 x K128 ----
        uint32_t vbase = sm + VS_OFF + cur * 32768u;
        #pragma unroll
        for (int ks = 0; ks < 8; ks++) {
            uint32_t kbyte = (uint32_t)(ks * 32) + a_kb;
            uint32_t af[2][4];
            #pragma unroll
            for (int mt = 0; mt < 2; mt++)
                ldsm4(af[mt], sm + P_OFF + (kbyte >> 7) * 8192u
                              + sw128((a_row + mt * 16) * 128 + (kbyte & 127)));
            #pragma unroll
            for (int seg = 0; seg < 2; seg++) {
                uint32_t bv[4];
                ldsm4t(bv, vbase + seg * 16384u
                           + sw128((uint32_t)((ks * 16 + (lane & 15)) * 128)
                                   + (uint32_t)(warp_n * 32) + (uint32_t)((lane >> 4) * 16)));
                #pragma unroll
                for (int mt = 0; mt < 2; mt++) {
                    mma16816h(ctx[mt][0], af[mt], bv);
                    mma16816h(ctx[mt][1], af[mt], bv + 2);
                }
            }
        }
        __syncthreads();
    }

    if (t < 64) g_rowsum[(size_t)bh * NS + q0 + t] = rowsumS[t];
    __syncthreads();

    // ---- normalized context write: [B,S,D] ----
    int b = bh >> 4, h = bh & 15;
    #pragma unroll
    for (int mt = 0; mt < 2; mt++) {
        #pragma unroll
        for (int half = 0; half < 2; half++) {
            int r = warp_m * 32 + mt * 16 + (lane >> 2) + half * 8;
            float inv = 1.0f / rowsumS[r];
            size_t o = ((size_t)(b * NS + q0 + r)) * ND + h * NDH;
            #pragma unroll
            for (int nt = 0; nt < 2; nt++) {
                int d = warp_n * 16 + nt * 8 + (lane & 3) * 2;
                float c0 = ctx[mt][nt][half * 2 + 0] * inv;
                float c1 = ctx[mt][nt][half * 2 + 1] * inv;
                *(float2*)&out_ctx[o + d] = make_float2(c0, c1);
            }
        }
    }
}

// ============================================================================
// Normalize attention tensor by row sums (pure HBM pass, full-chip parallel).
// ============================================================================
__global__ __launch_bounds__(256) void norm_kernel(float* __restrict__ att)
{
    size_t i = ((size_t)blockIdx.x * 256 + threadIdx.x) * 4;
    float inv = 1.0f / __ldg(&g_rowsum[i >> 10]);
    float4 v = *(float4*)&att[i];
    v.x *= inv; v.y *= inv; v.z *= inv; v.w *= inv;
    *(float4*)&att[i] = v;
}

extern "C" void kernel_launch(void* const* d_in, const int* in_sizes, int n_in,
                              void* d_out, int out_size) {
    const float* x  = (const float*)d_in[0];
    const float* Wq = (const float*)d_in[1];
    const float* bq = (const float*)d_in[2];
    const float* Wk = (const float*)d_in[3];
    const float* bk = (const float*)d_in[4];
    const float* Wv = (const float*)d_in[5];
    const float* bv = (const float*)d_in[6];
    // d_in[7] structure_bias: constant along the softmax axis -> cancels exactly.

    float* out_ctx = (float*)d_out;
    float* out_att = out_ctx + (size_t)NB * NS * ND;

    cudaFuncSetAttribute(qkv_mma_kernel, cudaFuncAttributeMaxDynamicSharedMemorySize, QKV_SMEM);
    cudaFuncSetAttribute(attn_mma_kernel, cudaFuncAttributeMaxDynamicSharedMemorySize, ATT_SMEM);

    prep_x_kernel<<<8192, 256>>>(x);
    prep_w_kernel<<<dim3(1024, 3), 256>>>(Wq, Wk, Wv);
    qkv_mma_kernel<<<dim3(24, 64), 256, QKV_SMEM>>>(bq, bk, bv);
    attn_mma_kernel<<<dim3(16, 128), 256, ATT_SMEM>>>(out_ctx, out_att);
    norm_kernel<<<131072, 256>>>(out_att);
}

// round 12
// speedup vs baseline: 1.5464x; 1.1556x over previous
#include <cuda_runtime.h>
#include <cuda_bf16.h>
#include <cuda_fp16.h>
#include <cstdint>

#define NB 8
#define NS 1024
#define ND 1024
#define NH 16
#define NDH 64
#define KAUG 2048   // augmented K for QKV GEMM, fp16 2-term: A=[xh|xh], B=[wh|wl]

// ---------------- scratch (static device globals) ----------------
__device__ __align__(128) __half g_A[(size_t)NB * NS * KAUG];          // [xh|xh]
__device__ __align__(128) __half g_Bm[3 * (size_t)ND * KAUG];          // [wh|wl]
// attention operands, fp16 splits, seg-major: [bh][seg][s][64]
__device__ __align__(128) __half g_Qs[(size_t)NB * NH * NS * NDH];     // [qh]*0.125
__device__ __align__(128) __half g_Ks[(size_t)NB * NH * 2 * NS * NDH]; // [kh|kl]
__device__ __align__(128) __half g_Vs[(size_t)NB * NH * 2 * NS * NDH]; // [vh|vl]

// ---------------- PTX helpers (compute_103-safe) ----------------
__device__ __forceinline__ uint32_t smem_u32(const void* p) {
    uint32_t a;
    asm("{ .reg .u64 t; cvta.to.shared.u64 t, %1; cvt.u32.u64 %0, t; }" : "=r"(a) : "l"(p));
    return a;
}
__device__ __forceinline__ void cp_async16(uint32_t dst, const void* src) {
    asm volatile("cp.async.cg.shared.global [%0], [%1], 16;" :: "r"(dst), "l"(src));
}
#define CP_COMMIT() asm volatile("cp.async.commit_group;" ::: "memory")
#define CP_WAIT(n)  asm volatile("cp.async.wait_group %0;" :: "n"(n) : "memory")

__device__ __forceinline__ void ldsm4(uint32_t* r, uint32_t addr) {
    asm volatile("ldmatrix.sync.aligned.m8n8.x4.shared.b16 {%0,%1,%2,%3}, [%4];"
                 : "=r"(r[0]), "=r"(r[1]), "=r"(r[2]), "=r"(r[3]) : "r"(addr));
}
__device__ __forceinline__ void ldsm2(uint32_t* r, uint32_t addr) {
    asm volatile("ldmatrix.sync.aligned.m8n8.x2.shared.b16 {%0,%1}, [%2];"
                 : "=r"(r[0]), "=r"(r[1]) : "r"(addr));
}
__device__ __forceinline__ void ldsm4t(uint32_t* r, uint32_t addr) {
    asm volatile("ldmatrix.sync.aligned.m8n8.x4.trans.shared.b16 {%0,%1,%2,%3}, [%4];"
                 : "=r"(r[0]), "=r"(r[1]), "=r"(r[2]), "=r"(r[3]) : "r"(addr));
}
// fp16 mma
__device__ __forceinline__ void mma16816h(float* c, const uint32_t* a, const uint32_t* b) {
    asm volatile("mma.sync.aligned.m16n8k16.row.col.f32.f16.f16.f32 "
                 "{%0,%1,%2,%3}, {%4,%5,%6,%7}, {%8,%9}, {%0,%1,%2,%3};"
                 : "+f"(c[0]), "+f"(c[1]), "+f"(c[2]), "+f"(c[3])
                 : "r"(a[0]), "r"(a[1]), "r"(a[2]), "r"(a[3]), "r"(b[0]), "r"(b[1]));
}
__device__ __forceinline__ void mma16816hv(float* c, const uint32_t* a, uint32_t b0, uint32_t b1) {
    asm volatile("mma.sync.aligned.m16n8k16.row.col.f32.f16.f16.f32 "
                 "{%0,%1,%2,%3}, {%4,%5,%6,%7}, {%8,%9}, {%0,%1,%2,%3};"
                 : "+f"(c[0]), "+f"(c[1]), "+f"(c[2]), "+f"(c[3])
                 : "r"(a[0]), "r"(a[1]), "r"(a[2]), "r"(a[3]), "r"(b0), "r"(b1));
}
__device__ __forceinline__ uint32_t sw128(uint32_t off) { return off ^ ((off >> 3) & 0x70); }

// ============================================================================
// Prep: fp16 2-term split operands for QKV. A'=[xh|xh], B'=[wh|wl].
// ============================================================================
__global__ __launch_bounds__(256) void prep_x_kernel(const float* __restrict__ x)
{
    size_t e = ((size_t)blockIdx.x * 256 + threadIdx.x) * 4;
    int m = (int)(e >> 10), k = (int)(e & 1023);
    float4 v = *(const float4*)&x[e];
    __half2 h01 = __floats2half2_rn(v.x, v.y);
    __half2 h23 = __floats2half2_rn(v.z, v.w);
    size_t ro = (size_t)m * KAUG;
    *(__half2*)&g_A[ro + k]            = h01;
    *(__half2*)&g_A[ro + k + 2]        = h23;
    *(__half2*)&g_A[ro + 1024 + k]     = h01;
    *(__half2*)&g_A[ro + 1024 + k + 2] = h23;
}

__global__ __launch_bounds__(256) void prep_w_kernel(
    const float* __restrict__ Wq, const float* __restrict__ Wk, const float* __restrict__ Wv)
{
    int z = blockIdx.y;
    const float* W = (z == 0) ? Wq : (z == 1) ? Wk : Wv;
    __half* gb = g_Bm + (size_t)z * ND * KAUG;
    size_t e = ((size_t)blockIdx.x * 256 + threadIdx.x) * 4;
    int n = (int)(e >> 10), k = (int)(e & 1023);
    float4 v = *(const float4*)&W[e];
    __half2 h01 = __floats2half2_rn(v.x, v.y);
    __half2 h23 = __floats2half2_rn(v.z, v.w);
    __half2 l01 = __floats2half2_rn(v.x - __half2float(h01.x),
                                    v.y - __half2float(h01.y));
    __half2 l23 = __floats2half2_rn(v.z - __half2float(h23.x),
                                    v.w - __half2float(h23.y));
    size_t ro = (size_t)n * KAUG;
    *(__half2*)&gb[ro + k]            = h01;
    *(__half2*)&gb[ro + k + 2]        = h23;
    *(__half2*)&gb[ro + 1024 + k]     = l01;
    *(__half2*)&gb[ro + 1024 + k + 2] = l23;
}

// ============================================================================
// QKV GEMM via mma.sync fp16 (2-term split). CTA 128x128, K-tile 64,
// 3-stage cp.async pipeline, 2 CTAs/SM. Epilogue -> fp16 attn operands.
// ============================================================================
#define STAGE_BYTES 32768
#define QKV_SMEM (3 * STAGE_BYTES)

__global__ __launch_bounds__(256, 2)
void qkv_mma_kernel(const float* __restrict__ bq, const float* __restrict__ bk,
                    const float* __restrict__ bv)
{
    extern __shared__ char smraw[];
    __shared__ float biasS[128];
    uint32_t sm = smem_u32(smraw);

    int t = threadIdx.x;
    int wid = t >> 5, lane = t & 31;
    int warp_m = wid & 1, warp_n = wid >> 1;

    int bx = blockIdx.x;
    int z = bx >> 3;
    int n0 = (bx & 7) * 128;
    int m0 = blockIdx.y * 128;

    const float* bias = (z == 0) ? bq : (z == 1) ? bk : bv;
    const __half* Asrc = g_A + (size_t)m0 * KAUG;
    const __half* Bsrc = g_Bm + (size_t)z * ND * KAUG + (size_t)n0 * KAUG;

    if (t < 128) biasS[t] = bias[n0 + t];

    auto load_tile = [&](int kt, int s) {
        uint32_t base = sm + s * STAGE_BYTES;
        int k0 = kt * 64;
        #pragma unroll
        for (int i = 0; i < 8; i++) {
            int c = t + i * 256;
            int row = c >> 3, col = c & 7;
            uint32_t off = sw128((uint32_t)((row & 127) * 128 + col * 16));
            const __half* src = (row < 128)
                ? Asrc + (size_t)row * KAUG + k0 + col * 8
                : Bsrc + (size_t)(row - 128) * KAUG + k0 + col * 8;
            cp_async16(base + (row < 128 ? 0u : 16384u) + off, src);
        }
    };

    float acc[4][4][4];
    #pragma unroll
    for (int mt = 0; mt < 4; mt++)
        #pragma unroll
        for (int nt = 0; nt < 4; nt++)
            #pragma unroll
            for (int r = 0; r < 4; r++) acc[mt][nt][r] = 0.f;

    uint32_t a_row = (uint32_t)(warp_m * 64 + (lane & 15));
    uint32_t a_kb  = (uint32_t)((lane >> 4) << 4);
    uint32_t b_row = (uint32_t)(warp_n * 32 + (lane & 15));

    load_tile(0, 0); CP_COMMIT();
    load_tile(1, 1); CP_COMMIT();

    int cur = 0;
    for (int kt = 0; kt < 32; kt++) {
        if (kt + 1 < 32) CP_WAIT(1); else CP_WAIT(0);
        __syncthreads();
        if (kt + 2 < 32) {
            int nxt = cur + 2; if (nxt >= 3) nxt -= 3;
            load_tile(kt + 2, nxt); CP_COMMIT();
        }

        uint32_t abase = sm + cur * STAGE_BYTES;
        uint32_t bbase = abase + 16384u;
        #pragma unroll
        for (int ks = 0; ks < 4; ks++) {
            uint32_t kb = (uint32_t)(ks * 32);
            uint32_t af[4][4], bw[2][4];
            #pragma unroll
            for (int mt = 0; mt < 4; mt++)
                ldsm4(af[mt], abase + sw128((a_row + mt * 16) * 128 + kb + a_kb));
            #pragma unroll
            for (int p = 0; p < 2; p++)
                ldsm4(bw[p], bbase + sw128((b_row + p * 16) * 128 + kb + a_kb));
            #pragma unroll
            for (int mt = 0; mt < 4; mt++)
                #pragma unroll
                for (int p = 0; p < 2; p++) {
                    mma16816hv(acc[mt][2 * p],     af[mt], bw[p][0], bw[p][2]);
                    mma16816hv(acc[mt][2 * p + 1], af[mt], bw[p][1], bw[p][3]);
                }
        }
        __syncthreads();
        cur = cur + 1; if (cur >= 3) cur = 0;
    }

    // ---- epilogue: bias (+0.125 for Q) -> fp16 operands for attention ----
    int gq = lane >> 2;
    float scale = (z == 0) ? 0.125f : 1.0f;
    #pragma unroll
    for (int mt = 0; mt < 4; mt++) {
        int m_lo = m0 + warp_m * 64 + mt * 16 + gq;
        #pragma unroll
        for (int half = 0; half < 2; half++) {
            int m = m_lo + half * 8;
            int b = m >> 10, s = m & 1023;
            #pragma unroll
            for (int nt = 0; nt < 4; nt++) {
                int nc = warp_n * 32 + nt * 8 + (lane & 3) * 2;
                int n = n0 + nc;
                int h = n >> 6, dh = n & 63;
                int bh = b * NH + h;
                float c0 = (acc[mt][nt][half * 2 + 0] + biasS[nc]) * scale;
                float c1 = (acc[mt][nt][half * 2 + 1] + biasS[nc + 1]) * scale;
                __half2 hv = __floats2half2_rn(c0, c1);
                if (z == 0) {          // Q: single seg
                    size_t o = ((size_t)bh * NS + s) * NDH + dh;
                    *(__half2*)&g_Qs[o] = hv;
                } else {               // K/V: [h|l] 2 segs
                    __half2 lv = __floats2half2_rn(c0 - __half2float(hv.x),
                                                   c1 - __half2float(hv.y));
                    __half* dst = (z == 1) ? g_Ks : g_Vs;
                    size_t o = (((size_t)bh * 2) * NS + s) * NDH + dh;
                    *(__half2*)&dst[o] = hv;
                    *(__half2*)&dst[o + (size_t)NS * NDH] = lv;
                }
            }
        }
    }
}

// ============================================================================
// Attention via mma.sync fp16, fused normalization. CTA: 64 q x one (b,h).
// 8 k-tiles of 128. All 8 P tiles (fp16) stay in smem; att written ONCE,
// normalized, in the tail (norm kernel eliminated).
// Q aliased over P[7] (written only at kt=7, after Q frags are in regs).
// K single-buffered (load hidden behind AV); V double-buffered.
// ============================================================================
#define P_OFF  0u                       // 8 tiles x 16384 = 131072
#define QAL_OFF (P_OFF + 7u * 16384u)   // Q alias (8KB) over P[7]
#define K_OFF  131072u                  // single buf: 2 segs x 16384 = 32768
#define V_OFF  163840u                  // 2 bufs x 32768 = 65536
#define RS_OFF 229376u                  // 64 floats
#define ATT_SMEM 229632u

__global__ __launch_bounds__(256, 1)
void attn_mma_kernel(float* __restrict__ out_ctx, float* __restrict__ out_att)
{
    extern __shared__ char smraw[];
    uint32_t sm = smem_u32(smraw);
    float* rowsumS = (float*)(smraw + RS_OFF);

    int t = threadIdx.x;
    int wid = t >> 5, lane = t & 31;
    int warp_m = wid & 1, warp_n = wid >> 1;
    int bh = blockIdx.y;
    int q0 = blockIdx.x * 64;

    const __half* Qg = g_Qs + ((size_t)bh * NS + q0) * NDH;
    const __half* Kg = g_Ks + (size_t)bh * 2 * NS * NDH;
    const __half* Vg = g_Vs + (size_t)bh * 2 * NS * NDH;

    auto load_k = [&](int kt) {
        #pragma unroll
        for (int i = 0; i < 8; i++) {
            int c = t + i * 256;
            int seg = c >> 10, row = (c >> 3) & 127, col = c & 7;
            cp_async16(sm + K_OFF + seg * 16384u
                          + sw128((uint32_t)(row * 128 + col * 16)),
                       Kg + (((size_t)seg * NS) + kt * 128 + row) * NDH + col * 8);
        }
    };
    auto load_v = [&](int kt, int buf) {
        #pragma unroll
        for (int i = 0; i < 8; i++) {
            int c = t + i * 256;
            int hl = c >> 10, row = (c >> 3) & 127, col = c & 7;
            cp_async16(sm + V_OFF + buf * 32768u + hl * 16384u
                          + sw128((uint32_t)(row * 128 + col * 16)),
                       Vg + (((size_t)hl * NS) + kt * 128 + row) * NDH + col * 8);
        }
    };

    // prologue: Q (into alias region) + K(0) | V(0) | V(1)
    #pragma unroll
    for (int i = 0; i < 2; i++) {
        int c = t + i * 256;
        int row = (c >> 3) & 63, col = c & 7;
        cp_async16(sm + QAL_OFF + sw128((uint32_t)(row * 128 + col * 16)),
                   Qg + (size_t)row * NDH + col * 8);
    }
    load_k(0); CP_COMMIT();
    load_v(0, 0); CP_COMMIT();
    load_v(1, 1); CP_COMMIT();
    if (t < 64) rowsumS[t] = 0.f;

    float ctx[2][2][4];
    #pragma unroll
    for (int mt = 0; mt < 2; mt++)
        #pragma unroll
        for (int nt = 0; nt < 2; nt++)
            #pragma unroll
            for (int r = 0; r < 4; r++) ctx[mt][nt][r] = 0.f;

    uint32_t a_row = (uint32_t)(warp_m * 32 + (lane & 15));
    uint32_t a_kb  = (uint32_t)((lane >> 4) << 4);
    uint32_t b_row = (uint32_t)(warp_n * 32 + (lane & 7));
    uint32_t b_kb  = (uint32_t)(((lane >> 3) & 1) << 4);

    uint32_t afq[4][2][4];    // Q fragments, resident in registers

    for (int kt = 0; kt < 8; kt++) {
        if (kt < 7) { CP_WAIT(1); } else { CP_WAIT(0); }
        __syncthreads();

        if (kt == 0) {
            // hoist Q fragments into registers (reads QAL region = P[7];
            // P[7] first written at kt=7, after many syncthreads)
            #pragma unroll
            for (int ks = 0; ks < 4; ks++)
                #pragma unroll
                for (int mt = 0; mt < 2; mt++)
                    ldsm4(afq[ks][mt], sm + QAL_OFF
                          + sw128((a_row + mt * 16) * 128 + (uint32_t)(ks * 32) + a_kb));
        }

        // ---- QK: M64 x N128, K = 64 x (kh + kl) ----
        float sacc[2][4][4];
        #pragma unroll
        for (int mt = 0; mt < 2; mt++)
            #pragma unroll
            for (int nt = 0; nt < 4; nt++)
                #pragma unroll
                for (int r = 0; r < 4; r++) sacc[mt][nt][r] = 0.f;

        #pragma unroll
        for (int ks = 0; ks < 4; ks++) {
            uint32_t kb = (uint32_t)(ks * 32);
            #pragma unroll
            for (int seg = 0; seg < 2; seg++) {
                uint32_t bf[4][2];
                #pragma unroll
                for (int nt = 0; nt < 4; nt++)
                    ldsm2(bf[nt], sm + K_OFF + seg * 16384u
                                  + sw128((b_row + nt * 8) * 128 + kb + b_kb));
                #pragma unroll
                for (int mt = 0; mt < 2; mt++)
                    #pragma unroll
                    for (int nt = 0; nt < 4; nt++)
                        mma16816h(sacc[mt][nt], afq[ks][mt], bf[nt]);
            }
        }

        // ---- exp -> P[kt] (fp16, smem only) + rowsum ----
        uint32_t pbase = (uint32_t)(P_OFF + kt * 16384);
        #pragma unroll
        for (int mt = 0; mt < 2; mt++) {
            float p0 = 0.f, p1 = 0.f;
            int r0 = warp_m * 32 + mt * 16 + (lane >> 2);
            #pragma unroll
            for (int nt = 0; nt < 4; nt++) {
                int kc = warp_n * 32 + nt * 8 + (lane & 3) * 2;
                float e0 = __expf(sacc[mt][nt][0]);
                float e1 = __expf(sacc[mt][nt][1]);
                float e2 = __expf(sacc[mt][nt][2]);
                float e3 = __expf(sacc[mt][nt][3]);
                p0 += e0 + e1; p1 += e2 + e3;
                __half2 h0 = __floats2half2_rn(e0, e1);
                __half2 h1 = __floats2half2_rn(e2, e3);
                uint32_t po  = pbase + (uint32_t)((kc >> 6) * 8192)
                             + sw128((uint32_t)(r0 * 128 + (kc & 63) * 2));
                uint32_t po8 = pbase + (uint32_t)((kc >> 6) * 8192)
                             + sw128((uint32_t)((r0 + 8) * 128 + (kc & 63) * 2));
                *(__half2*)(smraw + po)  = h0;
                *(__half2*)(smraw + po8) = h1;
            }
            p0 += __shfl_xor_sync(0xffffffffu, p0, 1);
            p0 += __shfl_xor_sync(0xffffffffu, p0, 2);
            p1 += __shfl_xor_sync(0xffffffffu, p1, 1);
            p1 += __shfl_xor_sync(0xffffffffu, p1, 2);
            if ((lane & 3) == 0) {
                atomicAdd(&rowsumS[r0], p0);
                atomicAdd(&rowsumS[r0 + 8], p1);
            }
        }
        __syncthreads();   // P[kt] ready; all warps done with K(kt)
        if (kt + 1 < 8) { load_k(kt + 1); CP_COMMIT(); }   // hidden behind AV

        // ---- AV: ctx += Ph * (Vh + Vl), M64 x N64 x K128 ----
        uint32_t vbase = sm + V_OFF + (uint32_t)((kt & 1) * 32768);
        #pragma unroll
        for (int ks = 0; ks < 8; ks++) {
            uint32_t kbyte = (uint32_t)(ks * 32) + a_kb;
            uint32_t af[2][4];
            #pragma unroll
            for (int mt = 0; mt < 2; mt++)
                ldsm4(af[mt], sm + pbase + (kbyte >> 7) * 8192u
                              + sw128((a_row + mt * 16) * 128 + (kbyte & 127)));
            #pragma unroll
            for (int seg = 0; seg < 2; seg++) {
                uint32_t bv[4];
                ldsm4t(bv, vbase + seg * 16384u
                           + sw128((uint32_t)((ks * 16 + (lane & 15)) * 128)
                                   + (uint32_t)(warp_n * 32) + (uint32_t)((lane >> 4) * 16)));
                #pragma unroll
                for (int mt = 0; mt < 2; mt++) {
                    mma16816h(ctx[mt][0], af[mt], bv);
                    mma16816h(ctx[mt][1], af[mt], bv + 2);
                }
            }
        }
        __syncthreads();   // V buf[kt&1] consumed
        if (kt + 2 < 8) { load_v(kt + 2, kt & 1); CP_COMMIT(); }
    }

    // ---- normalized context write: [B,S,D] ----
    int b = bh >> 4, h = bh & 15;
    #pragma unroll
    for (int mt = 0; mt < 2; mt++) {
        #pragma unroll
        for (int half = 0; half < 2; half++) {
            int r = warp_m * 32 + mt * 16 + (lane >> 2) + half * 8;
            float inv = 1.0f / rowsumS[r];
            size_t o = ((size_t)(b * NS + q0 + r)) * ND + h * NDH;
            #pragma unroll
            for (int nt = 0; nt < 2; nt++) {
                int d = warp_n * 16 + nt * 8 + (lane & 3) * 2;
                float c0 = ctx[mt][nt][half * 2 + 0] * inv;
                float c1 = ctx[mt][nt][half * 2 + 1] * inv;
                *(float2*)&out_ctx[o + d] = make_float2(c0, c1);
            }
        }
    }

    // ---- deferred att write: read P tiles from smem, normalize, store ----
    {
        int r = t >> 2;               // 0..63
        int c4 = t & 3;               // quarter-row: 16 cols each
        float inv = 1.0f / rowsumS[r];
        float* orow = out_att + ((size_t)bh * NS + q0 + r) * NS + c4 * 16;
        #pragma unroll 1
        for (int kt = 0; kt < 8; kt++) {
            char* tb = smraw + P_OFF + kt * 16384;
            #pragma unroll
            for (int s = 0; s < 2; s++) {
                uint32_t boff = (uint32_t)(r * 128 + c4 * 32);
                uint4 d0 = *(uint4*)(tb + s * 8192 + sw128(boff));
                uint4 d1 = *(uint4*)(tb + s * 8192 + sw128(boff + 16));
                float* op = orow + kt * 128 + s * 64;
                const uint32_t* w0 = (const uint32_t*)&d0;
                const uint32_t* w1 = (const uint32_t*)&d1;
                float4 f0, f1, f2, f3;
                {
                    float2 a0 = __half22float2(*(__half2*)&w0[0]);
                    float2 a1 = __half22float2(*(__half2*)&w0[1]);
                    float2 a2 = __half22float2(*(__half2*)&w0[2]);
                    float2 a3 = __half22float2(*(__half2*)&w0[3]);
                    f0 = make_float4(a0.x * inv, a0.y * inv, a1.x * inv, a1.y * inv);
                    f1 = make_float4(a2.x * inv, a2.y * inv, a3.x * inv, a3.y * inv);
                }
                {
                    float2 a0 = __half22float2(*(__half2*)&w1[0]);
                    float2 a1 = __half22float2(*(__half2*)&w1[1]);
                    float2 a2 = __half22float2(*(__half2*)&w1[2]);
                    float2 a3 = __half22float2(*(__half2*)&w1[3]);
                    f2 = make_float4(a0.x * inv, a0.y * inv, a1.x * inv, a1.y * inv);
                    f3 = make_float4(a2.x * inv, a2.y * inv, a3.x * inv, a3.y * inv);
                }
                *(float4*)&op[0]  = f0;
                *(float4*)&op[4]  = f1;
                *(float4*)&op[8]  = f2;
                *(float4*)&op[12] = f3;
            }
        }
    }
}

extern "C" void kernel_launch(void* const* d_in, const int* in_sizes, int n_in,
                              void* d_out, int out_size) {
    const float* x  = (const float*)d_in[0];
    const float* Wq = (const float*)d_in[1];
    const float* bq = (const float*)d_in[2];
    const float* Wk = (const float*)d_in[3];
    const float* bk = (const float*)d_in[4];
    const float* Wv = (const float*)d_in[5];
    const float* bv = (const float*)d_in[6];
    // d_in[7] structure_bias: constant along the softmax axis -> cancels exactly.

    float* out_ctx = (float*)d_out;
    float* out_att = out_ctx + (size_t)NB * NS * ND;

    cudaFuncSetAttribute(qkv_mma_kernel, cudaFuncAttributeMaxDynamicSharedMemorySize, QKV_SMEM);
    cudaFuncSetAttribute(attn_mma_kernel, cudaFuncAttributeMaxDynamicSharedMemorySize, ATT_SMEM);

    prep_x_kernel<<<8192, 256>>>(x);
    prep_w_kernel<<<dim3(1024, 3), 256>>>(Wq, Wk, Wv);
    qkv_mma_kernel<<<dim3(24, 64), 256, QKV_SMEM>>>(bq, bk, bv);
    attn_mma_kernel<<<dim3(16, 128), 256, ATT_SMEM>>>(out_ctx, out_att);
}

// round 13
// speedup vs baseline: 1.6999x; 1.0993x over previous
#include <cuda_runtime.h>
#include <cuda_bf16.h>
#include <cuda_fp16.h>
#include <cstdint>

#define NB 8
#define NS 1024
#define ND 1024
#define NH 16
#define NDH 64
#define KAUG 2048   // augmented K for QKV GEMM, fp16 2-term: A=[xh|xh], B=[wh|wl]

// ---------------- scratch (static device globals) ----------------
__device__ __align__(128) __half g_A[(size_t)NB * NS * KAUG];          // [xh|xh]
__device__ __align__(128) __half g_Bm[3 * (size_t)ND * KAUG];          // [wh|wl]
// attention operands, plain fp16: [bh][s][64]
__device__ __align__(128) __half g_Qs[(size_t)NB * NH * NS * NDH];     // qh*0.125
__device__ __align__(128) __half g_Ks[(size_t)NB * NH * NS * NDH];     // kh
__device__ __align__(128) __half g_Vs[(size_t)NB * NH * NS * NDH];     // vh

// ---------------- PTX helpers (compute_103-safe) ----------------
__device__ __forceinline__ uint32_t smem_u32(const void* p) {
    uint32_t a;
    asm("{ .reg .u64 t; cvta.to.shared.u64 t, %1; cvt.u32.u64 %0, t; }" : "=r"(a) : "l"(p));
    return a;
}
__device__ __forceinline__ void cp_async16(uint32_t dst, const void* src) {
    asm volatile("cp.async.cg.shared.global [%0], [%1], 16;" :: "r"(dst), "l"(src));
}
#define CP_COMMIT() asm volatile("cp.async.commit_group;" ::: "memory")
#define CP_WAIT(n)  asm volatile("cp.async.wait_group %0;" :: "n"(n) : "memory")

__device__ __forceinline__ void ldsm4(uint32_t* r, uint32_t addr) {
    asm volatile("ldmatrix.sync.aligned.m8n8.x4.shared.b16 {%0,%1,%2,%3}, [%4];"
                 : "=r"(r[0]), "=r"(r[1]), "=r"(r[2]), "=r"(r[3]) : "r"(addr));
}
__device__ __forceinline__ void ldsm2(uint32_t* r, uint32_t addr) {
    asm volatile("ldmatrix.sync.aligned.m8n8.x2.shared.b16 {%0,%1}, [%2];"
                 : "=r"(r[0]), "=r"(r[1]) : "r"(addr));
}
__device__ __forceinline__ void ldsm4t(uint32_t* r, uint32_t addr) {
    asm volatile("ldmatrix.sync.aligned.m8n8.x4.trans.shared.b16 {%0,%1,%2,%3}, [%4];"
                 : "=r"(r[0]), "=r"(r[1]), "=r"(r[2]), "=r"(r[3]) : "r"(addr));
}
// fp16 mma
__device__ __forceinline__ void mma16816h(float* c, const uint32_t* a, const uint32_t* b) {
    asm volatile("mma.sync.aligned.m16n8k16.row.col.f32.f16.f16.f32 "
                 "{%0,%1,%2,%3}, {%4,%5,%6,%7}, {%8,%9}, {%0,%1,%2,%3};"
                 : "+f"(c[0]), "+f"(c[1]), "+f"(c[2]), "+f"(c[3])
                 : "r"(a[0]), "r"(a[1]), "r"(a[2]), "r"(a[3]), "r"(b[0]), "r"(b[1]));
}
__device__ __forceinline__ void mma16816hv(float* c, const uint32_t* a, uint32_t b0, uint32_t b1) {
    asm volatile("mma.sync.aligned.m16n8k16.row.col.f32.f16.f16.f32 "
                 "{%0,%1,%2,%3}, {%4,%5,%6,%7}, {%8,%9}, {%0,%1,%2,%3};"
                 : "+f"(c[0]), "+f"(c[1]), "+f"(c[2]), "+f"(c[3])
                 : "r"(a[0]), "r"(a[1]), "r"(a[2]), "r"(a[3]), "r"(b0), "r"(b1));
}
__device__ __forceinline__ uint32_t sw128(uint32_t off) { return off ^ ((off >> 3) & 0x70); }

// ============================================================================
// Prep: fp16 2-term split operands for QKV. A'=[xh|xh], B'=[wh|wl].
// ============================================================================
__global__ __launch_bounds__(256) void prep_x_kernel(const float* __restrict__ x)
{
    size_t e = ((size_t)blockIdx.x * 256 + threadIdx.x) * 4;
    int m = (int)(e >> 10), k = (int)(e & 1023);
    float4 v = *(const float4*)&x[e];
    __half2 h01 = __floats2half2_rn(v.x, v.y);
    __half2 h23 = __floats2half2_rn(v.z, v.w);
    size_t ro = (size_t)m * KAUG;
    *(__half2*)&g_A[ro + k]            = h01;
    *(__half2*)&g_A[ro + k + 2]        = h23;
    *(__half2*)&g_A[ro + 1024 + k]     = h01;
    *(__half2*)&g_A[ro + 1024 + k + 2] = h23;
}

__global__ __launch_bounds__(256) void prep_w_kernel(
    const float* __restrict__ Wq, const float* __restrict__ Wk, const float* __restrict__ Wv)
{
    int z = blockIdx.y;
    const float* W = (z == 0) ? Wq : (z == 1) ? Wk : Wv;
    __half* gb = g_Bm + (size_t)z * ND * KAUG;
    size_t e = ((size_t)blockIdx.x * 256 + threadIdx.x) * 4;
    int n = (int)(e >> 10), k = (int)(e & 1023);
    float4 v = *(const float4*)&W[e];
    __half2 h01 = __floats2half2_rn(v.x, v.y);
    __half2 h23 = __floats2half2_rn(v.z, v.w);
    __half2 l01 = __floats2half2_rn(v.x - __half2float(h01.x),
                                    v.y - __half2float(h01.y));
    __half2 l23 = __floats2half2_rn(v.z - __half2float(h23.x),
                                    v.w - __half2float(h23.y));
    size_t ro = (size_t)n * KAUG;
    *(__half2*)&gb[ro + k]            = h01;
    *(__half2*)&gb[ro + k + 2]        = h23;
    *(__half2*)&gb[ro + 1024 + k]     = l01;
    *(__half2*)&gb[ro + 1024 + k + 2] = l23;
}

// ============================================================================
// QKV GEMM via mma.sync fp16 (2-term split). CTA 128x128, K-tile 64,
// 3-stage cp.async pipeline, 2 CTAs/SM. Epilogue -> plain fp16 attn operands.
// ============================================================================
#define STAGE_BYTES 32768
#define QKV_SMEM (3 * STAGE_BYTES)

__global__ __launch_bounds__(256, 2)
void qkv_mma_kernel(const float* __restrict__ bq, const float* __restrict__ bk,
                    const float* __restrict__ bv)
{
    extern __shared__ char smraw[];
    __shared__ float biasS[128];
    uint32_t sm = smem_u32(smraw);

    int t = threadIdx.x;
    int wid = t >> 5, lane = t & 31;
    int warp_m = wid & 1, warp_n = wid >> 1;

    int bx = blockIdx.x;
    int z = bx >> 3;
    int n0 = (bx & 7) * 128;
    int m0 = blockIdx.y * 128;

    const float* bias = (z == 0) ? bq : (z == 1) ? bk : bv;
    const __half* Asrc = g_A + (size_t)m0 * KAUG;
    const __half* Bsrc = g_Bm + (size_t)z * ND * KAUG + (size_t)n0 * KAUG;

    if (t < 128) biasS[t] = bias[n0 + t];

    auto load_tile = [&](int kt, int s) {
        uint32_t base = sm + s * STAGE_BYTES;
        int k0 = kt * 64;
        #pragma unroll
        for (int i = 0; i < 8; i++) {
            int c = t + i * 256;
            int row = c >> 3, col = c & 7;
            uint32_t off = sw128((uint32_t)((row & 127) * 128 + col * 16));
            const __half* src = (row < 128)
                ? Asrc + (size_t)row * KAUG + k0 + col * 8
                : Bsrc + (size_t)(row - 128) * KAUG + k0 + col * 8;
            cp_async16(base + (row < 128 ? 0u : 16384u) + off, src);
        }
    };

    float acc[4][4][4];
    #pragma unroll
    for (int mt = 0; mt < 4; mt++)
        #pragma unroll
        for (int nt = 0; nt < 4; nt++)
            #pragma unroll
            for (int r = 0; r < 4; r++) acc[mt][nt][r] = 0.f;

    uint32_t a_row = (uint32_t)(warp_m * 64 + (lane & 15));
    uint32_t a_kb  = (uint32_t)((lane >> 4) << 4);
    uint32_t b_row = (uint32_t)(warp_n * 32 + (lane & 15));

    load_tile(0, 0); CP_COMMIT();
    load_tile(1, 1); CP_COMMIT();

    int cur = 0;
    for (int kt = 0; kt < 32; kt++) {
        if (kt + 1 < 32) CP_WAIT(1); else CP_WAIT(0);
        __syncthreads();
        if (kt + 2 < 32) {
            int nxt = cur + 2; if (nxt >= 3) nxt -= 3;
            load_tile(kt + 2, nxt); CP_COMMIT();
        }

        uint32_t abase = sm + cur * STAGE_BYTES;
        uint32_t bbase = abase + 16384u;
        #pragma unroll
        for (int ks = 0; ks < 4; ks++) {
            uint32_t kb = (uint32_t)(ks * 32);
            uint32_t af[4][4], bw[2][4];
            #pragma unroll
            for (int mt = 0; mt < 4; mt++)
                ldsm4(af[mt], abase + sw128((a_row + mt * 16) * 128 + kb + a_kb));
            #pragma unroll
            for (int p = 0; p < 2; p++)
                ldsm4(bw[p], bbase + sw128((b_row + p * 16) * 128 + kb + a_kb));
            #pragma unroll
            for (int mt = 0; mt < 4; mt++)
                #pragma unroll
                for (int p = 0; p < 2; p++) {
                    mma16816hv(acc[mt][2 * p],     af[mt], bw[p][0], bw[p][2]);
                    mma16816hv(acc[mt][2 * p + 1], af[mt], bw[p][1], bw[p][3]);
                }
        }
        __syncthreads();
        cur = cur + 1; if (cur >= 3) cur = 0;
    }

    // ---- epilogue: bias (+0.125 for Q) -> plain fp16 attention operands ----
    int gq = lane >> 2;
    float scale = (z == 0) ? 0.125f : 1.0f;
    __half* dst = (z == 0) ? g_Qs : (z == 1) ? g_Ks : g_Vs;
    #pragma unroll
    for (int mt = 0; mt < 4; mt++) {
        int m_lo = m0 + warp_m * 64 + mt * 16 + gq;
        #pragma unroll
        for (int half = 0; half < 2; half++) {
            int m = m_lo + half * 8;
            int b = m >> 10, s = m & 1023;
            #pragma unroll
            for (int nt = 0; nt < 4; nt++) {
                int nc = warp_n * 32 + nt * 8 + (lane & 3) * 2;
                int n = n0 + nc;
                int h = n >> 6, dh = n & 63;
                int bh = b * NH + h;
                float c0 = (acc[mt][nt][half * 2 + 0] + biasS[nc]) * scale;
                float c1 = (acc[mt][nt][half * 2 + 1] + biasS[nc + 1]) * scale;
                __half2 hv = __floats2half2_rn(c0, c1);
                size_t o = ((size_t)bh * NS + s) * NDH + dh;
                *(__half2*)&dst[o] = hv;
            }
        }
    }
}

// ============================================================================
// Attention via mma.sync fp16, fused normalization. CTA: 64 q x one (b,h).
// 8 k-tiles of 128; plain fp16 K and V (no split terms). All 8 P tiles
// (fp16) stay in smem; att written once, normalized, in the tail.
// Q aliased over P[7]. K single-buffered; V double-buffered.
// ============================================================================
#define P_OFF  0u                       // 8 tiles x 16384 = 131072
#define QAL_OFF (P_OFF + 7u * 16384u)   // Q alias (8KB) over P[7]
#define K_OFF  131072u                  // 16384
#define V_OFF  147456u                  // 2 bufs x 16384 = 32768
#define RS_OFF 180224u                  // 64 floats
#define ATT_SMEM 180480u

__global__ __launch_bounds__(256, 1)
void attn_mma_kernel(float* __restrict__ out_ctx, float* __restrict__ out_att)
{
    extern __shared__ char smraw[];
    uint32_t sm = smem_u32(smraw);
    float* rowsumS = (float*)(smraw + RS_OFF);

    int t = threadIdx.x;
    int wid = t >> 5, lane = t & 31;
    int warp_m = wid & 1, warp_n = wid >> 1;
    int bh = blockIdx.y;
    int q0 = blockIdx.x * 64;

    const __half* Qg = g_Qs + ((size_t)bh * NS + q0) * NDH;
    const __half* Kg = g_Ks + (size_t)bh * NS * NDH;
    const __half* Vg = g_Vs + (size_t)bh * NS * NDH;

    auto load_k = [&](int kt) {
        #pragma unroll
        for (int i = 0; i < 4; i++) {
            int c = t + i * 256;
            int row = (c >> 3) & 127, col = c & 7;
            cp_async16(sm + K_OFF + sw128((uint32_t)(row * 128 + col * 16)),
                       Kg + ((size_t)(kt * 128 + row)) * NDH + col * 8);
        }
    };
    auto load_v = [&](int kt, int buf) {
        #pragma unroll
        for (int i = 0; i < 4; i++) {
            int c = t + i * 256;
            int row = (c >> 3) & 127, col = c & 7;
            cp_async16(sm + V_OFF + buf * 16384u
                          + sw128((uint32_t)(row * 128 + col * 16)),
                       Vg + ((size_t)(kt * 128 + row)) * NDH + col * 8);
        }
    };

    // prologue: Q (into alias region) + K(0) | V(0) | V(1)
    #pragma unroll
    for (int i = 0; i < 2; i++) {
        int c = t + i * 256;
        int row = (c >> 3) & 63, col = c & 7;
        cp_async16(sm + QAL_OFF + sw128((uint32_t)(row * 128 + col * 16)),
                   Qg + (size_t)row * NDH + col * 8);
    }
    load_k(0); CP_COMMIT();
    load_v(0, 0); CP_COMMIT();
    load_v(1, 1); CP_COMMIT();
    if (t < 64) rowsumS[t] = 0.f;

    float ctx[2][2][4];
    #pragma unroll
    for (int mt = 0; mt < 2; mt++)
        #pragma unroll
        for (int nt = 0; nt < 2; nt++)
            #pragma unroll
            for (int r = 0; r < 4; r++) ctx[mt][nt][r] = 0.f;

    uint32_t a_row = (uint32_t)(warp_m * 32 + (lane & 15));
    uint32_t a_kb  = (uint32_t)((lane >> 4) << 4);
    uint32_t b_row = (uint32_t)(warp_n * 32 + (lane & 7));
    uint32_t b_kb  = (uint32_t)(((lane >> 3) & 1) << 4);

    uint32_t afq[4][2][4];    // Q fragments, resident in registers

    for (int kt = 0; kt < 8; kt++) {
        if (kt < 7) { CP_WAIT(1); } else { CP_WAIT(0); }
        __syncthreads();

        if (kt == 0) {
            #pragma unroll
            for (int ks = 0; ks < 4; ks++)
                #pragma unroll
                for (int mt = 0; mt < 2; mt++)
                    ldsm4(afq[ks][mt], sm + QAL_OFF
                          + sw128((a_row + mt * 16) * 128 + (uint32_t)(ks * 32) + a_kb));
        }

        // ---- QK: M64 x N128 x K64 (plain fp16 K) ----
        float sacc[2][4][4];
        #pragma unroll
        for (int mt = 0; mt < 2; mt++)
            #pragma unroll
            for (int nt = 0; nt < 4; nt++)
                #pragma unroll
                for (int r = 0; r < 4; r++) sacc[mt][nt][r] = 0.f;

        #pragma unroll
        for (int ks = 0; ks < 4; ks++) {
            uint32_t kb = (uint32_t)(ks * 32);
            uint32_t bf[4][2];
            #pragma unroll
            for (int nt = 0; nt < 4; nt++)
                ldsm2(bf[nt], sm + K_OFF
                              + sw128((b_row + nt * 8) * 128 + kb + b_kb));
            #pragma unroll
            for (int mt = 0; mt < 2; mt++)
                #pragma unroll
                for (int nt = 0; nt < 4; nt++)
                    mma16816h(sacc[mt][nt], afq[ks][mt], bf[nt]);
        }

        // ---- exp -> P[kt] (fp16, smem only) + rowsum ----
        uint32_t pbase = (uint32_t)(P_OFF + kt * 16384);
        #pragma unroll
        for (int mt = 0; mt < 2; mt++) {
            float p0 = 0.f, p1 = 0.f;
            int r0 = warp_m * 32 + mt * 16 + (lane >> 2);
            #pragma unroll
            for (int nt = 0; nt < 4; nt++) {
                int kc = warp_n * 32 + nt * 8 + (lane & 3) * 2;
                float e0 = __expf(sacc[mt][nt][0]);
                float e1 = __expf(sacc[mt][nt][1]);
                float e2 = __expf(sacc[mt][nt][2]);
                float e3 = __expf(sacc[mt][nt][3]);
                p0 += e0 + e1; p1 += e2 + e3;
                __half2 h0 = __floats2half2_rn(e0, e1);
                __half2 h1 = __floats2half2_rn(e2, e3);
                uint32_t po  = pbase + (uint32_t)((kc >> 6) * 8192)
                             + sw128((uint32_t)(r0 * 128 + (kc & 63) * 2));
                uint32_t po8 = pbase + (uint32_t)((kc >> 6) * 8192)
                             + sw128((uint32_t)((r0 + 8) * 128 + (kc & 63) * 2));
                *(__half2*)(smraw + po)  = h0;
                *(__half2*)(smraw + po8) = h1;
            }
            p0 += __shfl_xor_sync(0xffffffffu, p0, 1);
            p0 += __shfl_xor_sync(0xffffffffu, p0, 2);
            p1 += __shfl_xor_sync(0xffffffffu, p1, 1);
            p1 += __shfl_xor_sync(0xffffffffu, p1, 2);
            if ((lane & 3) == 0) {
                atomicAdd(&rowsumS[r0], p0);
                atomicAdd(&rowsumS[r0 + 8], p1);
            }
        }
        __syncthreads();   // P[kt] ready; all warps done with K(kt)
        if (kt + 1 < 8) { load_k(kt + 1); CP_COMMIT(); }   // hidden behind AV

        // ---- AV: ctx += P * V, M64 x N64 x K128 (plain fp16 V) ----
        uint32_t vbase = sm + V_OFF + (uint32_t)((kt & 1) * 16384);
        #pragma unroll
        for (int ks = 0; ks < 8; ks++) {
            uint32_t kbyte = (uint32_t)(ks * 32) + a_kb;
            uint32_t af[2][4], bv[4];
            #pragma unroll
            for (int mt = 0; mt < 2; mt++)
                ldsm4(af[mt], sm + pbase + (kbyte >> 7) * 8192u
                              + sw128((a_row + mt * 16) * 128 + (kbyte & 127)));
            ldsm4t(bv, vbase + sw128((uint32_t)((ks * 16 + (lane & 15)) * 128)
                                     + (uint32_t)(warp_n * 32) + (uint32_t)((lane >> 4) * 16)));
            #pragma unroll
            for (int mt = 0; mt < 2; mt++) {
                mma16816h(ctx[mt][0], af[mt], bv);
                mma16816h(ctx[mt][1], af[mt], bv + 2);
            }
        }
        __syncthreads();   // V buf[kt&1] consumed
        if (kt + 2 < 8) { load_v(kt + 2, kt & 1); CP_COMMIT(); }
    }

    // ---- normalized context write: [B,S,D] ----
    int b = bh >> 4, h = bh & 15;
    #pragma unroll
    for (int mt = 0; mt < 2; mt++) {
        #pragma unroll
        for (int half = 0; half < 2; half++) {
            int r = warp_m * 32 + mt * 16 + (lane >> 2) + half * 8;
            float inv = 1.0f / rowsumS[r];
            size_t o = ((size_t)(b * NS + q0 + r)) * ND + h * NDH;
            #pragma unroll
            for (int nt = 0; nt < 2; nt++) {
                int d = warp_n * 16 + nt * 8 + (lane & 3) * 2;
                float c0 = ctx[mt][nt][half * 2 + 0] * inv;
                float c1 = ctx[mt][nt][half * 2 + 1] * inv;
                *(float2*)&out_ctx[o + d] = make_float2(c0, c1);
            }
        }
    }

    // ---- deferred att write: read P tiles from smem, normalize, store ----
    {
        int r = t >> 2;
        int c4 = t & 3;
        float inv = 1.0f / rowsumS[r];
        float* orow = out_att + ((size_t)bh * NS + q0 + r) * NS + c4 * 16;
        #pragma unroll 1
        for (int kt = 0; kt < 8; kt++) {
            char* tb = smraw + P_OFF + kt * 16384;
            #pragma unroll
            for (int s = 0; s < 2; s++) {
                uint32_t boff = (uint32_t)(r * 128 + c4 * 32);
                uint4 d0 = *(uint4*)(tb + s * 8192 + sw128(boff));
                uint4 d1 = *(uint4*)(tb + s * 8192 + sw128(boff + 16));
                float* op = orow + kt * 128 + s * 64;
                const uint32_t* w0 = (const uint32_t*)&d0;
                const uint32_t* w1 = (const uint32_t*)&d1;
                float4 f0, f1, f2, f3;
                {
                    float2 a0 = __half22float2(*(__half2*)&w0[0]);
                    float2 a1 = __half22float2(*(__half2*)&w0[1]);
                    float2 a2 = __half22float2(*(__half2*)&w0[2]);
                    float2 a3 = __half22float2(*(__half2*)&w0[3]);
                    f0 = make_float4(a0.x * inv, a0.y * inv, a1.x * inv, a1.y * inv);
                    f1 = make_float4(a2.x * inv, a2.y * inv, a3.x * inv, a3.y * inv);
                }
                {
                    float2 a0 = __half22float2(*(__half2*)&w1[0]);
                    float2 a1 = __half22float2(*(__half2*)&w1[1]);
                    float2 a2 = __half22float2(*(__half2*)&w1[2]);
                    float2 a3 = __half22float2(*(__half2*)&w1[3]);
                    f2 = make_float4(a0.x * inv, a0.y * inv, a1.x * inv, a1.y * inv);
                    f3 = make_float4(a2.x * inv, a2.y * inv, a3.x * inv, a3.y * inv);
                }
                *(float4*)&op[0]  = f0;
                *(float4*)&op[4]  = f1;
                *(float4*)&op[8]  = f2;
                *(float4*)&op[12] = f3;
            }
        }
    }
}

extern "C" void kernel_launch(void* const* d_in, const int* in_sizes, int n_in,
                              void* d_out, int out_size) {
    const float* x  = (const float*)d_in[0];
    const float* Wq = (const float*)d_in[1];
    const float* bq = (const float*)d_in[2];
    const float* Wk = (const float*)d_in[3];
    const float* bk = (const float*)d_in[4];
    const float* Wv = (const float*)d_in[5];
    const float* bv = (const float*)d_in[6];
    // d_in[7] structure_bias: constant along the softmax axis -> cancels exactly.

    float* out_ctx = (float*)d_out;
    float* out_att = out_ctx + (size_t)NB * NS * ND;

    cudaFuncSetAttribute(qkv_mma_kernel, cudaFuncAttributeMaxDynamicSharedMemorySize, QKV_SMEM);
    cudaFuncSetAttribute(attn_mma_kernel, cudaFuncAttributeMaxDynamicSharedMemorySize, ATT_SMEM);

    prep_x_kernel<<<8192, 256>>>(x);
    prep_w_kernel<<<dim3(1024, 3), 256>>>(Wq, Wk, Wv);
    qkv_mma_kernel<<<dim3(24, 64), 256, QKV_SMEM>>>(bq, bk, bv);
    attn_mma_kernel<<<dim3(16, 128), 256, ATT_SMEM>>>(out_ctx, out_att);
}

// round 14
// speedup vs baseline: 1.7529x; 1.0312x over previous
#include <cuda_runtime.h>
#include <cuda_bf16.h>
#include <cuda_fp16.h>
#include <cstdint>

#define NB 8
#define NS 1024
#define ND 1024
#define NH 16
#define NDH 64
#define KAUG 2048   // logical augmented K for QKV (A seg reused, B=[wh|wl])

// ---------------- scratch (static device globals) ----------------
__device__ __align__(128) __half g_A[(size_t)NB * NS * 1024];          // xh (single copy)
__device__ __align__(128) __half g_Bm[3 * (size_t)ND * KAUG];          // [wh|wl]
// attention operands, plain fp16: [bh][s][64]
__device__ __align__(128) __half g_Qs[(size_t)NB * NH * NS * NDH];     // qh*0.125
__device__ __align__(128) __half g_Ks[(size_t)NB * NH * NS * NDH];     // kh
__device__ __align__(128) __half g_Vs[(size_t)NB * NH * NS * NDH];     // vh

// ---------------- PTX helpers (compute_103-safe) ----------------
__device__ __forceinline__ uint32_t smem_u32(const void* p) {
    uint32_t a;
    asm("{ .reg .u64 t; cvta.to.shared.u64 t, %1; cvt.u32.u64 %0, t; }" : "=r"(a) : "l"(p));
    return a;
}
__device__ __forceinline__ void cp_async16(uint32_t dst, const void* src) {
    asm volatile("cp.async.cg.shared.global [%0], [%1], 16;" :: "r"(dst), "l"(src));
}
#define CP_COMMIT() asm volatile("cp.async.commit_group;" ::: "memory")
#define CP_WAIT(n)  asm volatile("cp.async.wait_group %0;" :: "n"(n) : "memory")

__device__ __forceinline__ void ldsm4(uint32_t* r, uint32_t addr) {
    asm volatile("ldmatrix.sync.aligned.m8n8.x4.shared.b16 {%0,%1,%2,%3}, [%4];"
                 : "=r"(r[0]), "=r"(r[1]), "=r"(r[2]), "=r"(r[3]) : "r"(addr));
}
__device__ __forceinline__ void ldsm2(uint32_t* r, uint32_t addr) {
    asm volatile("ldmatrix.sync.aligned.m8n8.x2.shared.b16 {%0,%1}, [%2];"
                 : "=r"(r[0]), "=r"(r[1]) : "r"(addr));
}
__device__ __forceinline__ void ldsm4t(uint32_t* r, uint32_t addr) {
    asm volatile("ldmatrix.sync.aligned.m8n8.x4.trans.shared.b16 {%0,%1,%2,%3}, [%4];"
                 : "=r"(r[0]), "=r"(r[1]), "=r"(r[2]), "=r"(r[3]) : "r"(addr));
}
// fp16 mma
__device__ __forceinline__ void mma16816h(float* c, const uint32_t* a, const uint32_t* b) {
    asm volatile("mma.sync.aligned.m16n8k16.row.col.f32.f16.f16.f32 "
                 "{%0,%1,%2,%3}, {%4,%5,%6,%7}, {%8,%9}, {%0,%1,%2,%3};"
                 : "+f"(c[0]), "+f"(c[1]), "+f"(c[2]), "+f"(c[3])
                 : "r"(a[0]), "r"(a[1]), "r"(a[2]), "r"(a[3]), "r"(b[0]), "r"(b[1]));
}
__device__ __forceinline__ void mma16816hv(float* c, const uint32_t* a, uint32_t b0, uint32_t b1) {
    asm volatile("mma.sync.aligned.m16n8k16.row.col.f32.f16.f16.f32 "
                 "{%0,%1,%2,%3}, {%4,%5,%6,%7}, {%8,%9}, {%0,%1,%2,%3};"
                 : "+f"(c[0]), "+f"(c[1]), "+f"(c[2]), "+f"(c[3])
                 : "r"(a[0]), "r"(a[1]), "r"(a[2]), "r"(a[3]), "r"(b0), "r"(b1));
}
__device__ __forceinline__ uint32_t sw128(uint32_t off) { return off ^ ((off >> 3) & 0x70); }

// ============================================================================
// Prep: fp16 operands for QKV. A = xh (single copy), B' = [wh|wl].
// ============================================================================
__global__ __launch_bounds__(256) void prep_x_kernel(const float* __restrict__ x)
{
    size_t e = ((size_t)blockIdx.x * 256 + threadIdx.x) * 4;
    int m = (int)(e >> 10), k = (int)(e & 1023);
    float4 v = *(const float4*)&x[e];
    __half2 h01 = __floats2half2_rn(v.x, v.y);
    __half2 h23 = __floats2half2_rn(v.z, v.w);
    size_t ro = (size_t)m * 1024;
    *(__half2*)&g_A[ro + k]     = h01;
    *(__half2*)&g_A[ro + k + 2] = h23;
}

__global__ __launch_bounds__(256) void prep_w_kernel(
    const float* __restrict__ Wq, const float* __restrict__ Wk, const float* __restrict__ Wv)
{
    int z = blockIdx.y;
    const float* W = (z == 0) ? Wq : (z == 1) ? Wk : Wv;
    __half* gb = g_Bm + (size_t)z * ND * KAUG;
    size_t e = ((size_t)blockIdx.x * 256 + threadIdx.x) * 4;
    int n = (int)(e >> 10), k = (int)(e & 1023);
    float4 v = *(const float4*)&W[e];
    __half2 h01 = __floats2half2_rn(v.x, v.y);
    __half2 h23 = __floats2half2_rn(v.z, v.w);
    __half2 l01 = __floats2half2_rn(v.x - __half2float(h01.x),
                                    v.y - __half2float(h01.y));
    __half2 l23 = __floats2half2_rn(v.z - __half2float(h23.x),
                                    v.w - __half2float(h23.y));
    size_t ro = (size_t)n * KAUG;
    *(__half2*)&gb[ro + k]            = h01;
    *(__half2*)&gb[ro + k + 2]        = h23;
    *(__half2*)&gb[ro + 1024 + k]     = l01;
    *(__half2*)&gb[ro + 1024 + k + 2] = l23;
}

// ============================================================================
// QKV GEMM via mma.sync fp16 (2-term split, A seg reused via modular index).
// CTA 128x128, K-tile 64, 3-stage cp.async pipeline, 2 CTAs/SM.
// ============================================================================
#define STAGE_BYTES 32768
#define QKV_SMEM (3 * STAGE_BYTES)

__global__ __launch_bounds__(256, 2)
void qkv_mma_kernel(const float* __restrict__ bq, const float* __restrict__ bk,
                    const float* __restrict__ bv)
{
    extern __shared__ char smraw[];
    __shared__ float biasS[128];
    uint32_t sm = smem_u32(smraw);

    int t = threadIdx.x;
    int wid = t >> 5, lane = t & 31;
    int warp_m = wid & 1, warp_n = wid >> 1;

    int bx = blockIdx.x;
    int z = bx >> 3;
    int n0 = (bx & 7) * 128;
    int m0 = blockIdx.y * 128;

    const float* bias = (z == 0) ? bq : (z == 1) ? bk : bv;
    const __half* Asrc = g_A + (size_t)m0 * 1024;
    const __half* Bsrc = g_Bm + (size_t)z * ND * KAUG + (size_t)n0 * KAUG;

    if (t < 128) biasS[t] = bias[n0 + t];

    auto load_tile = [&](int kt, int s) {
        uint32_t base = sm + s * STAGE_BYTES;
        int k0a = (kt * 64) & 1023;        // A seg reused across both halves
        int k0b = kt * 64;
        #pragma unroll
        for (int i = 0; i < 8; i++) {
            int c = t + i * 256;
            int row = c >> 3, col = c & 7;
            uint32_t off = sw128((uint32_t)((row & 127) * 128 + col * 16));
            const __half* src = (row < 128)
                ? Asrc + (size_t)row * 1024 + k0a + col * 8
                : Bsrc + (size_t)(row - 128) * KAUG + k0b + col * 8;
            cp_async16(base + (row < 128 ? 0u : 16384u) + off, src);
        }
    };

    float acc[4][4][4];
    #pragma unroll
    for (int mt = 0; mt < 4; mt++)
        #pragma unroll
        for (int nt = 0; nt < 4; nt++)
            #pragma unroll
            for (int r = 0; r < 4; r++) acc[mt][nt][r] = 0.f;

    uint32_t a_row = (uint32_t)(warp_m * 64 + (lane & 15));
    uint32_t a_kb  = (uint32_t)((lane >> 4) << 4);
    uint32_t b_row = (uint32_t)(warp_n * 32 + (lane & 15));

    load_tile(0, 0); CP_COMMIT();
    load_tile(1, 1); CP_COMMIT();

    int cur = 0;
    for (int kt = 0; kt < 32; kt++) {
        if (kt + 1 < 32) CP_WAIT(1); else CP_WAIT(0);
        __syncthreads();
        if (kt + 2 < 32) {
            int nxt = cur + 2; if (nxt >= 3) nxt -= 3;
            load_tile(kt + 2, nxt); CP_COMMIT();
        }

        uint32_t abase = sm + cur * STAGE_BYTES;
        uint32_t bbase = abase + 16384u;
        #pragma unroll
        for (int ks = 0; ks < 4; ks++) {
            uint32_t kb = (uint32_t)(ks * 32);
            uint32_t af[4][4], bw[2][4];
            #pragma unroll
            for (int mt = 0; mt < 4; mt++)
                ldsm4(af[mt], abase + sw128((a_row + mt * 16) * 128 + kb + a_kb));
            #pragma unroll
            for (int p = 0; p < 2; p++)
                ldsm4(bw[p], bbase + sw128((b_row + p * 16) * 128 + kb + a_kb));
            #pragma unroll
            for (int mt = 0; mt < 4; mt++)
                #pragma unroll
                for (int p = 0; p < 2; p++) {
                    mma16816hv(acc[mt][2 * p],     af[mt], bw[p][0], bw[p][2]);
                    mma16816hv(acc[mt][2 * p + 1], af[mt], bw[p][1], bw[p][3]);
                }
        }
        __syncthreads();
        cur = cur + 1; if (cur >= 3) cur = 0;
    }

    // ---- epilogue: bias (+0.125 for Q) -> plain fp16 attention operands ----
    int gq = lane >> 2;
    float scale = (z == 0) ? 0.125f : 1.0f;
    __half* dst = (z == 0) ? g_Qs : (z == 1) ? g_Ks : g_Vs;
    #pragma unroll
    for (int mt = 0; mt < 4; mt++) {
        int m_lo = m0 + warp_m * 64 + mt * 16 + gq;
        #pragma unroll
        for (int half = 0; half < 2; half++) {
            int m = m_lo + half * 8;
            int b = m >> 10, s = m & 1023;
            #pragma unroll
            for (int nt = 0; nt < 4; nt++) {
                int nc = warp_n * 32 + nt * 8 + (lane & 3) * 2;
                int n = n0 + nc;
                int h = n >> 6, dh = n & 63;
                int bh = b * NH + h;
                float c0 = (acc[mt][nt][half * 2 + 0] + biasS[nc]) * scale;
                float c1 = (acc[mt][nt][half * 2 + 1] + biasS[nc + 1]) * scale;
                __half2 hv = __floats2half2_rn(c0, c1);
                size_t o = ((size_t)bh * NS + s) * NDH + dh;
                *(__half2*)&dst[o] = hv;
            }
        }
    }
}

// ============================================================================
// Attention via mma.sync fp16, fused normalization. CTA: 32 q x one (b,h),
// 2 CTAs/SM (112KB smem). 8 k-tiles of 128. All 8 P tiles (fp16, 8KB each)
// stay in smem; att written once, normalized, in the tail.
// Q (4KB) aliased over P[7]. K single-buffered; V double-buffered.
// ============================================================================
#define P_OFF  0u                       // 8 tiles x 8192 = 65536
#define QAL_OFF (P_OFF + 7u * 8192u)    // Q alias (4KB) over P[7]
#define K_OFF  65536u                   // 16384
#define V_OFF  81920u                   // 2 bufs x 16384 = 32768
#define RS_OFF 114688u                  // 32 floats
#define ATT_SMEM 114816u

__global__ __launch_bounds__(256, 2)
void attn_mma_kernel(float* __restrict__ out_ctx, float* __restrict__ out_att)
{
    extern __shared__ char smraw[];
    uint32_t sm = smem_u32(smraw);
    float* rowsumS = (float*)(smraw + RS_OFF);

    int t = threadIdx.x;
    int wid = t >> 5, lane = t & 31;
    int warp_m = wid & 1, warp_n = wid >> 1;
    int bh = blockIdx.y;
    int q0 = blockIdx.x * 32;

    const __half* Qg = g_Qs + ((size_t)bh * NS + q0) * NDH;
    const __half* Kg = g_Ks + (size_t)bh * NS * NDH;
    const __half* Vg = g_Vs + (size_t)bh * NS * NDH;

    auto load_k = [&](int kt) {
        #pragma unroll
        for (int i = 0; i < 4; i++) {
            int c = t + i * 256;
            int row = (c >> 3) & 127, col = c & 7;
            cp_async16(sm + K_OFF + sw128((uint32_t)(row * 128 + col * 16)),
                       Kg + ((size_t)(kt * 128 + row)) * NDH + col * 8);
        }
    };
    auto load_v = [&](int kt, int buf) {
        #pragma unroll
        for (int i = 0; i < 4; i++) {
            int c = t + i * 256;
            int row = (c >> 3) & 127, col = c & 7;
            cp_async16(sm + V_OFF + buf * 16384u
                          + sw128((uint32_t)(row * 128 + col * 16)),
                       Vg + ((size_t)(kt * 128 + row)) * NDH + col * 8);
        }
    };

    // prologue: Q (into alias region, 4KB = 256 chunks) + K(0) | V(0) | V(1)
    {
        int row = (t >> 3) & 31, col = t & 7;
        cp_async16(sm + QAL_OFF + sw128((uint32_t)(row * 128 + col * 16)),
                   Qg + (size_t)row * NDH + col * 8);
    }
    load_k(0); CP_COMMIT();
    load_v(0, 0); CP_COMMIT();
    load_v(1, 1); CP_COMMIT();
    if (t < 32) rowsumS[t] = 0.f;

    float ctx[2][4];
    #pragma unroll
    for (int nt = 0; nt < 2; nt++)
        #pragma unroll
        for (int r = 0; r < 4; r++) ctx[nt][r] = 0.f;

    uint32_t a_row = (uint32_t)(warp_m * 16 + (lane & 15));
    uint32_t a_kb  = (uint32_t)((lane >> 4) << 4);
    uint32_t b_row = (uint32_t)(warp_n * 32 + (lane & 7));
    uint32_t b_kb  = (uint32_t)(((lane >> 3) & 1) << 4);

    uint32_t afq[4][4];    // Q fragments, resident in registers

    for (int kt = 0; kt < 8; kt++) {
        if (kt < 7) { CP_WAIT(1); } else { CP_WAIT(0); }
        __syncthreads();

        if (kt == 0) {
            #pragma unroll
            for (int ks = 0; ks < 4; ks++)
                ldsm4(afq[ks], sm + QAL_OFF
                      + sw128(a_row * 128 + (uint32_t)(ks * 32) + a_kb));
        }

        // ---- QK: M32 x N128 x K64 (warp tile M16 x N32) ----
        float sacc[4][4];
        #pragma unroll
        for (int nt = 0; nt < 4; nt++)
            #pragma unroll
            for (int r = 0; r < 4; r++) sacc[nt][r] = 0.f;

        #pragma unroll
        for (int ks = 0; ks < 4; ks++) {
            uint32_t kb = (uint32_t)(ks * 32);
            uint32_t bf[4][2];
            #pragma unroll
            for (int nt = 0; nt < 4; nt++)
                ldsm2(bf[nt], sm + K_OFF
                              + sw128((b_row + nt * 8) * 128 + kb + b_kb));
            #pragma unroll
            for (int nt = 0; nt < 4; nt++)
                mma16816h(sacc[nt], afq[ks], bf[nt]);
        }

        // ---- exp -> P[kt] (fp16, smem only) + rowsum ----
        uint32_t pbase = (uint32_t)(P_OFF + kt * 8192);
        {
            float p0 = 0.f, p1 = 0.f;
            int r0 = warp_m * 16 + (lane >> 2);
            #pragma unroll
            for (int nt = 0; nt < 4; nt++) {
                int kc = warp_n * 32 + nt * 8 + (lane & 3) * 2;
                float e0 = __expf(sacc[nt][0]);
                float e1 = __expf(sacc[nt][1]);
                float e2 = __expf(sacc[nt][2]);
                float e3 = __expf(sacc[nt][3]);
                p0 += e0 + e1; p1 += e2 + e3;
                __half2 h0 = __floats2half2_rn(e0, e1);
                __half2 h1 = __floats2half2_rn(e2, e3);
                uint32_t po  = pbase + (uint32_t)((kc >> 6) * 4096)
                             + sw128((uint32_t)(r0 * 128 + (kc & 63) * 2));
                uint32_t po8 = pbase + (uint32_t)((kc >> 6) * 4096)
                             + sw128((uint32_t)((r0 + 8) * 128 + (kc & 63) * 2));
                *(__half2*)(smraw + po)  = h0;
                *(__half2*)(smraw + po8) = h1;
            }
            p0 += __shfl_xor_sync(0xffffffffu, p0, 1);
            p0 += __shfl_xor_sync(0xffffffffu, p0, 2);
            p1 += __shfl_xor_sync(0xffffffffu, p1, 1);
            p1 += __shfl_xor_sync(0xffffffffu, p1, 2);
            if ((lane & 3) == 0) {
                atomicAdd(&rowsumS[r0], p0);
                atomicAdd(&rowsumS[r0 + 8], p1);
            }
        }
        __syncthreads();   // P[kt] ready; all warps done with K(kt)
        if (kt + 1 < 8) { load_k(kt + 1); CP_COMMIT(); }   // hidden behind AV

        // ---- AV: ctx += P * V, M32 x N64 x K128 ----
        uint32_t vbase = sm + V_OFF + (uint32_t)((kt & 1) * 16384);
        #pragma unroll
        for (int ks = 0; ks < 8; ks++) {
            uint32_t kbyte = (uint32_t)(ks * 32) + a_kb;
            uint32_t af[4], bv[4];
            ldsm4(af, sm + pbase + (kbyte >> 7) * 4096u
                      + sw128(a_row * 128 + (kbyte & 127)));
            ldsm4t(bv, vbase + sw128((uint32_t)((ks * 16 + (lane & 15)) * 128)
                                     + (uint32_t)(warp_n * 32) + (uint32_t)((lane >> 4) * 16)));
            mma16816h(ctx[0], af, bv);
            mma16816h(ctx[1], af, bv + 2);
        }
        __syncthreads();   // V buf[kt&1] consumed
        if (kt + 2 < 8) { load_v(kt + 2, kt & 1); CP_COMMIT(); }
    }

    // ---- normalized context write: [B,S,D] ----
    int b = bh >> 4, h = bh & 15;
    #pragma unroll
    for (int half = 0; half < 2; half++) {
        int r = warp_m * 16 + (lane >> 2) + half * 8;
        float inv = 1.0f / rowsumS[r];
        size_t o = ((size_t)(b * NS + q0 + r)) * ND + h * NDH;
        #pragma unroll
        for (int nt = 0; nt < 2; nt++) {
            int d = warp_n * 16 + nt * 8 + (lane & 3) * 2;
            float c0 = ctx[nt][half * 2 + 0] * inv;
            float c1 = ctx[nt][half * 2 + 1] * inv;
            *(float2*)&out_ctx[o + d] = make_float2(c0, c1);
        }
    }

    // ---- deferred att write: read P tiles from smem, normalize, store ----
    {
        int r = t >> 3;               // 0..31
        int c8 = t & 7;               // 16 cols each
        float inv = 1.0f / rowsumS[r];
        int col0 = c8 * 16;
        uint32_t half = (uint32_t)((col0 >> 6) * 4096);
        uint32_t boff = (uint32_t)(r * 128 + (col0 & 63) * 2);
        float* orow = out_att + ((size_t)bh * NS + q0 + r) * NS + col0;
        #pragma unroll 1
        for (int kt = 0; kt < 8; kt++) {
            char* tb = smraw + P_OFF + kt * 8192;
            uint4 d0 = *(uint4*)(tb + half + sw128(boff));
            uint4 d1 = *(uint4*)(tb + half + sw128(boff + 16));
            float* op = orow + kt * 128;
            const uint32_t* w0 = (const uint32_t*)&d0;
            const uint32_t* w1 = (const uint32_t*)&d1;
            float4 f0, f1, f2, f3;
            {
                float2 a0 = __half22float2(*(__half2*)&w0[0]);
                float2 a1 = __half22float2(*(__half2*)&w0[1]);
                float2 a2 = __half22float2(*(__half2*)&w0[2]);
                float2 a3 = __half22float2(*(__half2*)&w0[3]);
                f0 = make_float4(a0.x * inv, a0.y * inv, a1.x * inv, a1.y * inv);
                f1 = make_float4(a2.x * inv, a2.y * inv, a3.x * inv, a3.y * inv);
            }
            {
                float2 a0 = __half22float2(*(__half2*)&w1[0]);
                float2 a1 = __half22float2(*(__half2*)&w1[1]);
                float2 a2 = __half22float2(*(__half2*)&w1[2]);
                float2 a3 = __half22float2(*(__half2*)&w1[3]);
                f2 = make_float4(a0.x * inv, a0.y * inv, a1.x * inv, a1.y * inv);
                f3 = make_float4(a2.x * inv, a2.y * inv, a3.x * inv, a3.y * inv);
            }
            *(float4*)&op[0]  = f0;
            *(float4*)&op[4]  = f1;
            *(float4*)&op[8]  = f2;
            *(float4*)&op[12] = f3;
        }
    }
}

extern "C" void kernel_launch(void* const* d_in, const int* in_sizes, int n_in,
                              void* d_out, int out_size) {
    const float* x  = (const float*)d_in[0];
    const float* Wq = (const float*)d_in[1];
    const float* bq = (const float*)d_in[2];
    const float* Wk = (const float*)d_in[3];
    const float* bk = (const float*)d_in[4];
    const float* Wv = (const float*)d_in[5];
    const float* bv = (const float*)d_in[6];
    // d_in[7] structure_bias: constant along the softmax axis -> cancels exactly.

    float* out_ctx = (float*)d_out;
    float* out_att = out_ctx + (size_t)NB * NS * ND;

    cudaFuncSetAttribute(qkv_mma_kernel, cudaFuncAttributeMaxDynamicSharedMemorySize, QKV_SMEM);
    cudaFuncSetAttribute(attn_mma_kernel, cudaFuncAttributeMaxDynamicSharedMemorySize, ATT_SMEM);

    prep_x_kernel<<<8192, 256>>>(x);
    prep_w_kernel<<<dim3(1024, 3), 256>>>(Wq, Wk, Wv);
    qkv_mma_kernel<<<dim3(24, 64), 256, QKV_SMEM>>>(bq, bk, bv);
    attn_mma_kernel<<<dim3(32, 128), 256, ATT_SMEM>>>(out_ctx, out_att);
}

// round 15
// speedup vs baseline: 2.2176x; 1.2651x over previous
#include <cuda_runtime.h>
#include <cuda_bf16.h>
#include <cuda_fp16.h>
#include <cstdint>

#define NB 8
#define NS 1024
#define ND 1024
#define NH 16
#define NDH 64

// ---------------- scratch (static device globals) ----------------
__device__ __align__(128) __half g_A[(size_t)NB * NS * 1024];          // xh
__device__ __align__(128) __half g_Bm[3 * (size_t)ND * 1024];          // wh
// attention operands, plain fp16: [bh][s][64]
__device__ __align__(128) __half g_Qs[(size_t)NB * NH * NS * NDH];     // qh*0.125
__device__ __align__(128) __half g_Ks[(size_t)NB * NH * NS * NDH];     // kh
__device__ __align__(128) __half g_Vs[(size_t)NB * NH * NS * NDH];     // vh

// ---------------- PTX helpers (compute_103-safe) ----------------
__device__ __forceinline__ uint32_t smem_u32(const void* p) {
    uint32_t a;
    asm("{ .reg .u64 t; cvta.to.shared.u64 t, %1; cvt.u32.u64 %0, t; }" : "=r"(a) : "l"(p));
    return a;
}
__device__ __forceinline__ void cp_async16(uint32_t dst, const void* src) {
    asm volatile("cp.async.cg.shared.global [%0], [%1], 16;" :: "r"(dst), "l"(src));
}
#define CP_COMMIT() asm volatile("cp.async.commit_group;" ::: "memory")
#define CP_WAIT(n)  asm volatile("cp.async.wait_group %0;" :: "n"(n) : "memory")

__device__ __forceinline__ void ldsm4(uint32_t* r, uint32_t addr) {
    asm volatile("ldmatrix.sync.aligned.m8n8.x4.shared.b16 {%0,%1,%2,%3}, [%4];"
                 : "=r"(r[0]), "=r"(r[1]), "=r"(r[2]), "=r"(r[3]) : "r"(addr));
}
__device__ __forceinline__ void ldsm2(uint32_t* r, uint32_t addr) {
    asm volatile("ldmatrix.sync.aligned.m8n8.x2.shared.b16 {%0,%1}, [%2];"
                 : "=r"(r[0]), "=r"(r[1]) : "r"(addr));
}
__device__ __forceinline__ void ldsm4t(uint32_t* r, uint32_t addr) {
    asm volatile("ldmatrix.sync.aligned.m8n8.x4.trans.shared.b16 {%0,%1,%2,%3}, [%4];"
                 : "=r"(r[0]), "=r"(r[1]), "=r"(r[2]), "=r"(r[3]) : "r"(addr));
}
// fp16 mma
__device__ __forceinline__ void mma16816h(float* c, const uint32_t* a, const uint32_t* b) {
    asm volatile("mma.sync.aligned.m16n8k16.row.col.f32.f16.f16.f32 "
                 "{%0,%1,%2,%3}, {%4,%5,%6,%7}, {%8,%9}, {%0,%1,%2,%3};"
                 : "+f"(c[0]), "+f"(c[1]), "+f"(c[2]), "+f"(c[3])
                 : "r"(a[0]), "r"(a[1]), "r"(a[2]), "r"(a[3]), "r"(b[0]), "r"(b[1]));
}
__device__ __forceinline__ void mma16816hv(float* c, const uint32_t* a, uint32_t b0, uint32_t b1) {
    asm volatile("mma.sync.aligned.m16n8k16.row.col.f32.f16.f16.f32 "
                 "{%0,%1,%2,%3}, {%4,%5,%6,%7}, {%8,%9}, {%0,%1,%2,%3};"
                 : "+f"(c[0]), "+f"(c[1]), "+f"(c[2]), "+f"(c[3])
                 : "r"(a[0]), "r"(a[1]), "r"(a[2]), "r"(a[3]), "r"(b0), "r"(b1));
}
__device__ __forceinline__ uint32_t sw128(uint32_t off) { return off ^ ((off >> 3) & 0x70); }

// ============================================================================
// Prep: plain fp16 operands for QKV (wl correction term dropped; Q/K/V are
// rounded to fp16 downstream anyway, so added error is ~1.4e-4 per operand).
// ============================================================================
__global__ __launch_bounds__(256) void prep_x_kernel(const float* __restrict__ x)
{
    size_t e = ((size_t)blockIdx.x * 256 + threadIdx.x) * 4;
    int m = (int)(e >> 10), k = (int)(e & 1023);
    float4 v = *(const float4*)&x[e];
    __half2 h01 = __floats2half2_rn(v.x, v.y);
    __half2 h23 = __floats2half2_rn(v.z, v.w);
    size_t ro = (size_t)m * 1024;
    *(__half2*)&g_A[ro + k]     = h01;
    *(__half2*)&g_A[ro + k + 2] = h23;
}

__global__ __launch_bounds__(256) void prep_w_kernel(
    const float* __restrict__ Wq, const float* __restrict__ Wk, const float* __restrict__ Wv)
{
    int z = blockIdx.y;
    const float* W = (z == 0) ? Wq : (z == 1) ? Wk : Wv;
    __half* gb = g_Bm + (size_t)z * ND * 1024;
    size_t e = ((size_t)blockIdx.x * 256 + threadIdx.x) * 4;
    int n = (int)(e >> 10), k = (int)(e & 1023);
    float4 v = *(const float4*)&W[e];
    __half2 h01 = __floats2half2_rn(v.x, v.y);
    __half2 h23 = __floats2half2_rn(v.z, v.w);
    size_t ro = (size_t)n * 1024;
    *(__half2*)&gb[ro + k]     = h01;
    *(__half2*)&gb[ro + k + 2] = h23;
}

// ============================================================================
// QKV GEMM via mma.sync fp16, K=1024 (16 k-tiles of 64). CTA 128x128,
// 3-stage cp.async pipeline, 2 CTAs/SM.
// ============================================================================
#define STAGE_BYTES 32768
#define QKV_SMEM (3 * STAGE_BYTES)

__global__ __launch_bounds__(256, 2)
void qkv_mma_kernel(const float* __restrict__ bq, const float* __restrict__ bk,
                    const float* __restrict__ bv)
{
    extern __shared__ char smraw[];
    __shared__ float biasS[128];
    uint32_t sm = smem_u32(smraw);

    int t = threadIdx.x;
    int wid = t >> 5, lane = t & 31;
    int warp_m = wid & 1, warp_n = wid >> 1;

    int bx = blockIdx.x;
    int z = bx >> 3;
    int n0 = (bx & 7) * 128;
    int m0 = blockIdx.y * 128;

    const float* bias = (z == 0) ? bq : (z == 1) ? bk : bv;
    const __half* Asrc = g_A + (size_t)m0 * 1024;
    const __half* Bsrc = g_Bm + (size_t)z * ND * 1024 + (size_t)n0 * 1024;

    if (t < 128) biasS[t] = bias[n0 + t];

    auto load_tile = [&](int kt, int s) {
        uint32_t base = sm + s * STAGE_BYTES;
        int k0 = kt * 64;
        #pragma unroll
        for (int i = 0; i < 8; i++) {
            int c = t + i * 256;
            int row = c >> 3, col = c & 7;
            uint32_t off = sw128((uint32_t)((row & 127) * 128 + col * 16));
            const __half* src = (row < 128)
                ? Asrc + (size_t)row * 1024 + k0 + col * 8
                : Bsrc + (size_t)(row - 128) * 1024 + k0 + col * 8;
            cp_async16(base + (row < 128 ? 0u : 16384u) + off, src);
        }
    };

    float acc[4][4][4];
    #pragma unroll
    for (int mt = 0; mt < 4; mt++)
        #pragma unroll
        for (int nt = 0; nt < 4; nt++)
            #pragma unroll
            for (int r = 0; r < 4; r++) acc[mt][nt][r] = 0.f;

    uint32_t a_row = (uint32_t)(warp_m * 64 + (lane & 15));
    uint32_t a_kb  = (uint32_t)((lane >> 4) << 4);
    uint32_t b_row = (uint32_t)(warp_n * 32 + (lane & 15));

    load_tile(0, 0); CP_COMMIT();
    load_tile(1, 1); CP_COMMIT();

    int cur = 0;
    for (int kt = 0; kt < 16; kt++) {
        if (kt + 1 < 16) CP_WAIT(1); else CP_WAIT(0);
        __syncthreads();
        if (kt + 2 < 16) {
            int nxt = cur + 2; if (nxt >= 3) nxt -= 3;
            load_tile(kt + 2, nxt); CP_COMMIT();
        }

        uint32_t abase = sm + cur * STAGE_BYTES;
        uint32_t bbase = abase + 16384u;
        #pragma unroll
        for (int ks = 0; ks < 4; ks++) {
            uint32_t kb = (uint32_t)(ks * 32);
            uint32_t af[4][4], bw[2][4];
            #pragma unroll
            for (int mt = 0; mt < 4; mt++)
                ldsm4(af[mt], abase + sw128((a_row + mt * 16) * 128 + kb + a_kb));
            #pragma unroll
            for (int p = 0; p < 2; p++)
                ldsm4(bw[p], bbase + sw128((b_row + p * 16) * 128 + kb + a_kb));
            #pragma unroll
            for (int mt = 0; mt < 4; mt++)
                #pragma unroll
                for (int p = 0; p < 2; p++) {
                    mma16816hv(acc[mt][2 * p],     af[mt], bw[p][0], bw[p][2]);
                    mma16816hv(acc[mt][2 * p + 1], af[mt], bw[p][1], bw[p][3]);
                }
        }
        __syncthreads();
        cur = cur + 1; if (cur >= 3) cur = 0;
    }

    // ---- epilogue: bias (+0.125 for Q) -> plain fp16 attention operands ----
    int gq = lane >> 2;
    float scale = (z == 0) ? 0.125f : 1.0f;
    __half* dst = (z == 0) ? g_Qs : (z == 1) ? g_Ks : g_Vs;
    #pragma unroll
    for (int mt = 0; mt < 4; mt++) {
        int m_lo = m0 + warp_m * 64 + mt * 16 + gq;
        #pragma unroll
        for (int half = 0; half < 2; half++) {
            int m = m_lo + half * 8;
            int b = m >> 10, s = m & 1023;
            #pragma unroll
            for (int nt = 0; nt < 4; nt++) {
                int nc = warp_n * 32 + nt * 8 + (lane & 3) * 2;
                int n = n0 + nc;
                int h = n >> 6, dh = n & 63;
                int bh = b * NH + h;
                float c0 = (acc[mt][nt][half * 2 + 0] + biasS[nc]) * scale;
                float c1 = (acc[mt][nt][half * 2 + 1] + biasS[nc + 1]) * scale;
                __half2 hv = __floats2half2_rn(c0, c1);
                size_t o = ((size_t)bh * NS + s) * NDH + dh;
                *(__half2*)&dst[o] = hv;
            }
        }
    }
}

// ============================================================================
// Attention via mma.sync fp16, fused normalization. CTA: 32 q x one (b,h),
// 2 CTAs/SM (112KB smem). 8 k-tiles of 128. All 8 P tiles (fp16, 8KB each)
// stay in smem; att written once, normalized, in the tail.
// Q (4KB) aliased over P[7]. K single-buffered; V double-buffered.
// ============================================================================
#define P_OFF  0u                       // 8 tiles x 8192 = 65536
#define QAL_OFF (P_OFF + 7u * 8192u)    // Q alias (4KB) over P[7]
#define K_OFF  65536u                   // 16384
#define V_OFF  81920u                   // 2 bufs x 16384 = 32768
#define RS_OFF 114688u                  // 32 floats
#define ATT_SMEM 114816u

__global__ __launch_bounds__(256, 2)
void attn_mma_kernel(float* __restrict__ out_ctx, float* __restrict__ out_att)
{
    extern __shared__ char smraw[];
    uint32_t sm = smem_u32(smraw);
    float* rowsumS = (float*)(smraw + RS_OFF);

    int t = threadIdx.x;
    int wid = t >> 5, lane = t & 31;
    int warp_m = wid & 1, warp_n = wid >> 1;
    int bh = blockIdx.y;
    int q0 = blockIdx.x * 32;

    const __half* Qg = g_Qs + ((size_t)bh * NS + q0) * NDH;
    const __half* Kg = g_Ks + (size_t)bh * NS * NDH;
    const __half* Vg = g_Vs + (size_t)bh * NS * NDH;

    auto load_k = [&](int kt) {
        #pragma unroll
        for (int i = 0; i < 4; i++) {
            int c = t + i * 256;
            int row = (c >> 3) & 127, col = c & 7;
            cp_async16(sm + K_OFF + sw128((uint32_t)(row * 128 + col * 16)),
                       Kg + ((size_t)(kt * 128 + row)) * NDH + col * 8);
        }
    };
    auto load_v = [&](int kt, int buf) {
        #pragma unroll
        for (int i = 0; i < 4; i++) {
            int c = t + i * 256;
            int row = (c >> 3) & 127, col = c & 7;
            cp_async16(sm + V_OFF + buf * 16384u
                          + sw128((uint32_t)(row * 128 + col * 16)),
                       Vg + ((size_t)(kt * 128 + row)) * NDH + col * 8);
        }
    };

    // prologue: Q (into alias region) + K(0) | V(0) | V(1)
    {
        int row = (t >> 3) & 31, col = t & 7;
        cp_async16(sm + QAL_OFF + sw128((uint32_t)(row * 128 + col * 16)),
                   Qg + (size_t)row * NDH + col * 8);
    }
    load_k(0); CP_COMMIT();
    load_v(0, 0); CP_COMMIT();
    load_v(1, 1); CP_COMMIT();
    if (t < 32) rowsumS[t] = 0.f;

    float ctx[2][4];
    #pragma unroll
    for (int nt = 0; nt < 2; nt++)
        #pragma unroll
        for (int r = 0; r < 4; r++) ctx[nt][r] = 0.f;

    uint32_t a_row = (uint32_t)(warp_m * 16 + (lane & 15));
    uint32_t a_kb  = (uint32_t)((lane >> 4) << 4);
    uint32_t b_row = (uint32_t)(warp_n * 32 + (lane & 7));
    uint32_t b_kb  = (uint32_t)(((lane >> 3) & 1) << 4);

    uint32_t afq[4][4];    // Q fragments, resident in registers

    for (int kt = 0; kt < 8; kt++) {
        if (kt < 7) { CP_WAIT(1); } else { CP_WAIT(0); }
        __syncthreads();

        if (kt == 0) {
            #pragma unroll
            for (int ks = 0; ks < 4; ks++)
                ldsm4(afq[ks], sm + QAL_OFF
                      + sw128(a_row * 128 + (uint32_t)(ks * 32) + a_kb));
        }

        // ---- QK: M32 x N128 x K64 (warp tile M16 x N32) ----
        float sacc[4][4];
        #pragma unroll
        for (int nt = 0; nt < 4; nt++)
            #pragma unroll
            for (int r = 0; r < 4; r++) sacc[nt][r] = 0.f;

        #pragma unroll
        for (int ks = 0; ks < 4; ks++) {
            uint32_t kb = (uint32_t)(ks * 32);
            uint32_t bf[4][2];
            #pragma unroll
            for (int nt = 0; nt < 4; nt++)
                ldsm2(bf[nt], sm + K_OFF
                              + sw128((b_row + nt * 8) * 128 + kb + b_kb));
            #pragma unroll
            for (int nt = 0; nt < 4; nt++)
                mma16816h(sacc[nt], afq[ks], bf[nt]);
        }

        // ---- exp -> P[kt] (fp16, smem only) + rowsum ----
        uint32_t pbase = (uint32_t)(P_OFF + kt * 8192);
        {
            float p0 = 0.f, p1 = 0.f;
            int r0 = warp_m * 16 + (lane >> 2);
            #pragma unroll
            for (int nt = 0; nt < 4; nt++) {
                int kc = warp_n * 32 + nt * 8 + (lane & 3) * 2;
                float e0 = __expf(sacc[nt][0]);
                float e1 = __expf(sacc[nt][1]);
                float e2 = __expf(sacc[nt][2]);
                float e3 = __expf(sacc[nt][3]);
                p0 += e0 + e1; p1 += e2 + e3;
                __half2 h0 = __floats2half2_rn(e0, e1);
                __half2 h1 = __floats2half2_rn(e2, e3);
                uint32_t po  = pbase + (uint32_t)((kc >> 6) * 4096)
                             + sw128((uint32_t)(r0 * 128 + (kc & 63) * 2));
                uint32_t po8 = pbase + (uint32_t)((kc >> 6) * 4096)
                             + sw128((uint32_t)((r0 + 8) * 128 + (kc & 63) * 2));
                *(__half2*)(smraw + po)  = h0;
                *(__half2*)(smraw + po8) = h1;
            }
            p0 += __shfl_xor_sync(0xffffffffu, p0, 1);
            p0 += __shfl_xor_sync(0xffffffffu, p0, 2);
            p1 += __shfl_xor_sync(0xffffffffu, p1, 1);
            p1 += __shfl_xor_sync(0xffffffffu, p1, 2);
            if ((lane & 3) == 0) {
                atomicAdd(&rowsumS[r0], p0);
                atomicAdd(&rowsumS[r0 + 8], p1);
            }
        }
        __syncthreads();   // P[kt] ready; all warps done with K(kt)
        if (kt + 1 < 8) { load_k(kt + 1); CP_COMMIT(); }   // hidden behind AV

        // ---- AV: ctx += P * V, M32 x N64 x K128 ----
        uint32_t vbase = sm + V_OFF + (uint32_t)((kt & 1) * 16384);
        #pragma unroll
        for (int ks = 0; ks < 8; ks++) {
            uint32_t kbyte = (uint32_t)(ks * 32) + a_kb;
            uint32_t af[4], bv[4];
            ldsm4(af, sm + pbase + (kbyte >> 7) * 4096u
                      + sw128(a_row * 128 + (kbyte & 127)));
            ldsm4t(bv, vbase + sw128((uint32_t)((ks * 16 + (lane & 15)) * 128)
                                     + (uint32_t)(warp_n * 32) + (uint32_t)((lane >> 4) * 16)));
            mma16816h(ctx[0], af, bv);
            mma16816h(ctx[1], af, bv + 2);
        }
        __syncthreads();   // V buf[kt&1] consumed
        if (kt + 2 < 8) { load_v(kt + 2, kt & 1); CP_COMMIT(); }
    }

    // ---- normalized context write: [B,S,D] ----
    int b = bh >> 4, h = bh & 15;
    #pragma unroll
    for (int half = 0; half < 2; half++) {
        int r = warp_m * 16 + (lane >> 2) + half * 8;
        float inv = 1.0f / rowsumS[r];
        size_t o = ((size_t)(b * NS + q0 + r)) * ND + h * NDH;
        #pragma unroll
        for (int nt = 0; nt < 2; nt++) {
            int d = warp_n * 16 + nt * 8 + (lane & 3) * 2;
            float c0 = ctx[nt][half * 2 + 0] * inv;
            float c1 = ctx[nt][half * 2 + 1] * inv;
            *(float2*)&out_ctx[o + d] = make_float2(c0, c1);
        }
    }

    // ---- deferred att write: read P tiles from smem, normalize, store ----
    {
        int r = t >> 3;               // 0..31
        int c8 = t & 7;               // 16 cols each
        float inv = 1.0f / rowsumS[r];
        int col0 = c8 * 16;
        uint32_t half = (uint32_t)((col0 >> 6) * 4096);
        uint32_t boff = (uint32_t)(r * 128 + (col0 & 63) * 2);
        float* orow = out_att + ((size_t)bh * NS + q0 + r) * NS + col0;
        #pragma unroll 1
        for (int kt = 0; kt < 8; kt++) {
            char* tb = smraw + P_OFF + kt * 8192;
            uint4 d0 = *(uint4*)(tb + half + sw128(boff));
            uint4 d1 = *(uint4*)(tb + half + sw128(boff + 16));
            float* op = orow + kt * 128;
            const uint32_t* w0 = (const uint32_t*)&d0;
            const uint32_t* w1 = (const uint32_t*)&d1;
            float4 f0, f1, f2, f3;
            {
                float2 a0 = __half22float2(*(__half2*)&w0[0]);
                float2 a1 = __half22float2(*(__half2*)&w0[1]);
                float2 a2 = __half22float2(*(__half2*)&w0[2]);
                float2 a3 = __half22float2(*(__half2*)&w0[3]);
                f0 = make_float4(a0.x * inv, a0.y * inv, a1.x * inv, a1.y * inv);
                f1 = make_float4(a2.x * inv, a2.y * inv, a3.x * inv, a3.y * inv);
            }
            {
                float2 a0 = __half22float2(*(__half2*)&w1[0]);
                float2 a1 = __half22float2(*(__half2*)&w1[1]);
                float2 a2 = __half22float2(*(__half2*)&w1[2]);
                float2 a3 = __half22float2(*(__half2*)&w1[3]);
                f2 = make_float4(a0.x * inv, a0.y * inv, a1.x * inv, a1.y * inv);
                f3 = make_float4(a2.x * inv, a2.y * inv, a3.x * inv, a3.y * inv);
            }
            *(float4*)&op[0]  = f0;
            *(float4*)&op[4]  = f1;
            *(float4*)&op[8]  = f2;
            *(float4*)&op[12] = f3;
        }
    }
}

extern "C" void kernel_launch(void* const* d_in, const int* in_sizes, int n_in,
                              void* d_out, int out_size) {
    const float* x  = (const float*)d_in[0];
    const float* Wq = (const float*)d_in[1];
    const float* bq = (const float*)d_in[2];
    const float* Wk = (const float*)d_in[3];
    const float* bk = (const float*)d_in[4];
    const float* Wv = (const float*)d_in[5];
    const float* bv = (const float*)d_in[6];
    // d_in[7] structure_bias: constant along the softmax axis -> cancels exactly.

    float* out_ctx = (float*)d_out;
    float* out_att = out_ctx + (size_t)NB * NS * ND;

    cudaFuncSetAttribute(qkv_mma_kernel, cudaFuncAttributeMaxDynamicSharedMemorySize, QKV_SMEM);
    cudaFuncSetAttribute(attn_mma_kernel, cudaFuncAttributeMaxDynamicSharedMemorySize, ATT_SMEM);

    prep_x_kernel<<<8192, 256>>>(x);
    prep_w_kernel<<<dim3(1024, 3), 256>>>(Wq, Wk, Wv);
    qkv_mma_kernel<<<dim3(24, 64), 256, QKV_SMEM>>>(bq, bk, bv);
    attn_mma_kernel<<<dim3(32, 128), 256, ATT_SMEM>>>(out_ctx, out_att);
}

// round 16
// speedup vs baseline: 2.2509x; 1.0150x over previous
#include <cuda_runtime.h>
#include <cuda_bf16.h>
#include <cuda_fp16.h>
#include <cstdint>

#define NB 8
#define NS 1024
#define ND 1024
#define NH 16
#define NDH 64

// ---------------- scratch (static device globals) ----------------
__device__ __align__(128) __half g_A[(size_t)NB * NS * 1024];          // xh
__device__ __align__(128) __half g_Bm[3 * (size_t)ND * 1024];          // wh
// attention operands, plain fp16: [bh][s][64]
__device__ __align__(128) __half g_Qs[(size_t)NB * NH * NS * NDH];     // qh*0.125*log2e
__device__ __align__(128) __half g_Ks[(size_t)NB * NH * NS * NDH];     // kh
__device__ __align__(128) __half g_Vs[(size_t)NB * NH * NS * NDH];     // vh

// ---------------- PTX helpers (compute_103-safe) ----------------
__device__ __forceinline__ uint32_t smem_u32(const void* p) {
    uint32_t a;
    asm("{ .reg .u64 t; cvta.to.shared.u64 t, %1; cvt.u32.u64 %0, t; }" : "=r"(a) : "l"(p));
    return a;
}
__device__ __forceinline__ void cp_async16(uint32_t dst, const void* src) {
    asm volatile("cp.async.cg.shared.global [%0], [%1], 16;" :: "r"(dst), "l"(src));
}
#define CP_COMMIT() asm volatile("cp.async.commit_group;" ::: "memory")
#define CP_WAIT(n)  asm volatile("cp.async.wait_group %0;" :: "n"(n) : "memory")

__device__ __forceinline__ void ldsm4(uint32_t* r, uint32_t addr) {
    asm volatile("ldmatrix.sync.aligned.m8n8.x4.shared.b16 {%0,%1,%2,%3}, [%4];"
                 : "=r"(r[0]), "=r"(r[1]), "=r"(r[2]), "=r"(r[3]) : "r"(addr));
}
__device__ __forceinline__ void ldsm4t(uint32_t* r, uint32_t addr) {
    asm volatile("ldmatrix.sync.aligned.m8n8.x4.trans.shared.b16 {%0,%1,%2,%3}, [%4];"
                 : "=r"(r[0]), "=r"(r[1]), "=r"(r[2]), "=r"(r[3]) : "r"(addr));
}
// fp16 mma
__device__ __forceinline__ void mma16816h(float* c, const uint32_t* a, const uint32_t* b) {
    asm volatile("mma.sync.aligned.m16n8k16.row.col.f32.f16.f16.f32 "
                 "{%0,%1,%2,%3}, {%4,%5,%6,%7}, {%8,%9}, {%0,%1,%2,%3};"
                 : "+f"(c[0]), "+f"(c[1]), "+f"(c[2]), "+f"(c[3])
                 : "r"(a[0]), "r"(a[1]), "r"(a[2]), "r"(a[3]), "r"(b[0]), "r"(b[1]));
}
__device__ __forceinline__ void mma16816hv(float* c, const uint32_t* a, uint32_t b0, uint32_t b1) {
    asm volatile("mma.sync.aligned.m16n8k16.row.col.f32.f16.f16.f32 "
                 "{%0,%1,%2,%3}, {%4,%5,%6,%7}, {%8,%9}, {%0,%1,%2,%3};"
                 : "+f"(c[0]), "+f"(c[1]), "+f"(c[2]), "+f"(c[3])
                 : "r"(a[0]), "r"(a[1]), "r"(a[2]), "r"(a[3]), "r"(b0), "r"(b1));
}
__device__ __forceinline__ float ex2f(float x) {
    float r;
    asm("ex2.approx.ftz.f32 %0, %1;" : "=f"(r) : "f"(x));
    return r;
}
__device__ __forceinline__ uint32_t sw128(uint32_t off) { return off ^ ((off >> 3) & 0x70); }

// ============================================================================
// Prep: plain fp16 operands for QKV.
// ============================================================================
__global__ __launch_bounds__(256) void prep_x_kernel(const float* __restrict__ x)
{
    size_t e = ((size_t)blockIdx.x * 256 + threadIdx.x) * 4;
    int m = (int)(e >> 10), k = (int)(e & 1023);
    float4 v = *(const float4*)&x[e];
    __half2 h01 = __floats2half2_rn(v.x, v.y);
    __half2 h23 = __floats2half2_rn(v.z, v.w);
    size_t ro = (size_t)m * 1024;
    *(__half2*)&g_A[ro + k]     = h01;
    *(__half2*)&g_A[ro + k + 2] = h23;
}

__global__ __launch_bounds__(256) void prep_w_kernel(
    const float* __restrict__ Wq, const float* __restrict__ Wk, const float* __restrict__ Wv)
{
    int z = blockIdx.y;
    const float* W = (z == 0) ? Wq : (z == 1) ? Wk : Wv;
    __half* gb = g_Bm + (size_t)z * ND * 1024;
    size_t e = ((size_t)blockIdx.x * 256 + threadIdx.x) * 4;
    int n = (int)(e >> 10), k = (int)(e & 1023);
    float4 v = *(const float4*)&W[e];
    __half2 h01 = __floats2half2_rn(v.x, v.y);
    __half2 h23 = __floats2half2_rn(v.z, v.w);
    size_t ro = (size_t)n * 1024;
    *(__half2*)&gb[ro + k]     = h01;
    *(__half2*)&gb[ro + k + 2] = h23;
}

// ============================================================================
// QKV GEMM via mma.sync fp16, K=1024 (16 k-tiles of 64). CTA 128x128,
// 3-stage cp.async pipeline, 2 CTAs/SM.
// Q scale folds 1/8 AND log2(e) so attention uses exp2 directly.
// ============================================================================
#define STAGE_BYTES 32768
#define QKV_SMEM (3 * STAGE_BYTES)

__global__ __launch_bounds__(256, 2)
void qkv_mma_kernel(const float* __restrict__ bq, const float* __restrict__ bk,
                    const float* __restrict__ bv)
{
    extern __shared__ char smraw[];
    __shared__ float biasS[128];
    uint32_t sm = smem_u32(smraw);

    int t = threadIdx.x;
    int wid = t >> 5, lane = t & 31;
    int warp_m = wid & 1, warp_n = wid >> 1;

    int bx = blockIdx.x;
    int z = bx >> 3;
    int n0 = (bx & 7) * 128;
    int m0 = blockIdx.y * 128;

    const float* bias = (z == 0) ? bq : (z == 1) ? bk : bv;
    const __half* Asrc = g_A + (size_t)m0 * 1024;
    const __half* Bsrc = g_Bm + (size_t)z * ND * 1024 + (size_t)n0 * 1024;

    if (t < 128) biasS[t] = bias[n0 + t];

    auto load_tile = [&](int kt, int s) {
        uint32_t base = sm + s * STAGE_BYTES;
        int k0 = kt * 64;
        #pragma unroll
        for (int i = 0; i < 8; i++) {
            int c = t + i * 256;
            int row = c >> 3, col = c & 7;
            uint32_t off = sw128((uint32_t)((row & 127) * 128 + col * 16));
            const __half* src = (row < 128)
                ? Asrc + (size_t)row * 1024 + k0 + col * 8
                : Bsrc + (size_t)(row - 128) * 1024 + k0 + col * 8;
            cp_async16(base + (row < 128 ? 0u : 16384u) + off, src);
        }
    };

    float acc[4][4][4];
    #pragma unroll
    for (int mt = 0; mt < 4; mt++)
        #pragma unroll
        for (int nt = 0; nt < 4; nt++)
            #pragma unroll
            for (int r = 0; r < 4; r++) acc[mt][nt][r] = 0.f;

    uint32_t a_row = (uint32_t)(warp_m * 64 + (lane & 15));
    uint32_t a_kb  = (uint32_t)((lane >> 4) << 4);
    uint32_t b_row = (uint32_t)(warp_n * 32 + (lane & 15));

    load_tile(0, 0); CP_COMMIT();
    load_tile(1, 1); CP_COMMIT();

    int cur = 0;
    for (int kt = 0; kt < 16; kt++) {
        if (kt + 1 < 16) CP_WAIT(1); else CP_WAIT(0);
        __syncthreads();
        if (kt + 2 < 16) {
            int nxt = cur + 2; if (nxt >= 3) nxt -= 3;
            load_tile(kt + 2, nxt); CP_COMMIT();
        }

        uint32_t abase = sm + cur * STAGE_BYTES;
        uint32_t bbase = abase + 16384u;
        #pragma unroll
        for (int ks = 0; ks < 4; ks++) {
            uint32_t kb = (uint32_t)(ks * 32);
            uint32_t af[4][4], bw[2][4];
            #pragma unroll
            for (int mt = 0; mt < 4; mt++)
                ldsm4(af[mt], abase + sw128((a_row + mt * 16) * 128 + kb + a_kb));
            #pragma unroll
            for (int p = 0; p < 2; p++)
                ldsm4(bw[p], bbase + sw128((b_row + p * 16) * 128 + kb + a_kb));
            #pragma unroll
            for (int mt = 0; mt < 4; mt++)
                #pragma unroll
                for (int p = 0; p < 2; p++) {
                    mma16816hv(acc[mt][2 * p],     af[mt], bw[p][0], bw[p][2]);
                    mma16816hv(acc[mt][2 * p + 1], af[mt], bw[p][1], bw[p][3]);
                }
        }
        __syncthreads();
        cur = cur + 1; if (cur >= 3) cur = 0;
    }

    // ---- epilogue: bias (+0.125*log2e for Q) -> plain fp16 attn operands ----
    int gq = lane >> 2;
    float scale = (z == 0) ? 0.125f * 1.44269504f : 1.0f;
    __half* dst = (z == 0) ? g_Qs : (z == 1) ? g_Ks : g_Vs;
    #pragma unroll
    for (int mt = 0; mt < 4; mt++) {
        int m_lo = m0 + warp_m * 64 + mt * 16 + gq;
        #pragma unroll
        for (int half = 0; half < 2; half++) {
            int m = m_lo + half * 8;
            int b = m >> 10, s = m & 1023;
            #pragma unroll
            for (int nt = 0; nt < 4; nt++) {
                int nc = warp_n * 32 + nt * 8 + (lane & 3) * 2;
                int n = n0 + nc;
                int h = n >> 6, dh = n & 63;
                int bh = b * NH + h;
                float c0 = (acc[mt][nt][half * 2 + 0] + biasS[nc]) * scale;
                float c1 = (acc[mt][nt][half * 2 + 1] + biasS[nc + 1]) * scale;
                __half2 hv = __floats2half2_rn(c0, c1);
                size_t o = ((size_t)bh * NS + s) * NDH + dh;
                *(__half2*)&dst[o] = hv;
            }
        }
    }
}

// ============================================================================
// Attention via mma.sync fp16, fused normalization. CTA: 32 q x one (b,h),
// 2 CTAs/SM (112KB smem). 8 k-tiles of 128. All 8 P tiles (fp16, 8KB each)
// stay in smem; att written once, normalized, in the tail.
// Q (4KB) aliased over P[7]. K single-buffered; V double-buffered.
// Scores are in log2 domain (log2e folded into Q) -> ex2.approx directly.
// ============================================================================
#define P_OFF  0u                       // 8 tiles x 8192 = 65536
#define QAL_OFF (P_OFF + 7u * 8192u)    // Q alias (4KB) over P[7]
#define K_OFF  65536u                   // 16384
#define V_OFF  81920u                   // 2 bufs x 16384 = 32768
#define RS_OFF 114688u                  // 32 floats
#define ATT_SMEM 114816u

__global__ __launch_bounds__(256, 2)
void attn_mma_kernel(float* __restrict__ out_ctx, float* __restrict__ out_att)
{
    extern __shared__ char smraw[];
    uint32_t sm = smem_u32(smraw);
    float* rowsumS = (float*)(smraw + RS_OFF);

    int t = threadIdx.x;
    int wid = t >> 5, lane = t & 31;
    int warp_m = wid & 1, warp_n = wid >> 1;
    int bh = blockIdx.y;
    int q0 = blockIdx.x * 32;

    const __half* Qg = g_Qs + ((size_t)bh * NS + q0) * NDH;
    const __half* Kg = g_Ks + (size_t)bh * NS * NDH;
    const __half* Vg = g_Vs + (size_t)bh * NS * NDH;

    auto load_k = [&](int kt) {
        #pragma unroll
        for (int i = 0; i < 4; i++) {
            int c = t + i * 256;
            int row = (c >> 3) & 127, col = c & 7;
            cp_async16(sm + K_OFF + sw128((uint32_t)(row * 128 + col * 16)),
                       Kg + ((size_t)(kt * 128 + row)) * NDH + col * 8);
        }
    };
    auto load_v = [&](int kt, int buf) {
        #pragma unroll
        for (int i = 0; i < 4; i++) {
            int c = t + i * 256;
            int row = (c >> 3) & 127, col = c & 7;
            cp_async16(sm + V_OFF + buf * 16384u
                          + sw128((uint32_t)(row * 128 + col * 16)),
                       Vg + ((size_t)(kt * 128 + row)) * NDH + col * 8);
        }
    };

    // prologue: Q (into alias region) + K(0) | V(0) | V(1)
    {
        int row = (t >> 3) & 31, col = t & 7;
        cp_async16(sm + QAL_OFF + sw128((uint32_t)(row * 128 + col * 16)),
                   Qg + (size_t)row * NDH + col * 8);
    }
    load_k(0); CP_COMMIT();
    load_v(0, 0); CP_COMMIT();
    load_v(1, 1); CP_COMMIT();
    if (t < 32) rowsumS[t] = 0.f;

    float ctx[2][4];
    #pragma unroll
    for (int nt = 0; nt < 2; nt++)
        #pragma unroll
        for (int r = 0; r < 4; r++) ctx[nt][r] = 0.f;

    uint32_t a_row = (uint32_t)(warp_m * 16 + (lane & 15));
    uint32_t a_kb  = (uint32_t)((lane >> 4) << 4);
    uint32_t b_row = (uint32_t)(warp_n * 32 + (lane & 15));

    uint32_t afq[4][4];    // Q fragments, resident in registers

    for (int kt = 0; kt < 8; kt++) {
        if (kt < 7) { CP_WAIT(1); } else { CP_WAIT(0); }
        __syncthreads();

        if (kt == 0) {
            #pragma unroll
            for (int ks = 0; ks < 4; ks++)
                ldsm4(afq[ks], sm + QAL_OFF
                      + sw128(a_row * 128 + (uint32_t)(ks * 32) + a_kb));
        }

        // ---- QK: M32 x N128 x K64 (warp tile M16 x N32, B via 2x ldsm4) ----
        float sacc[4][4];
        #pragma unroll
        for (int nt = 0; nt < 4; nt++)
            #pragma unroll
            for (int r = 0; r < 4; r++) sacc[nt][r] = 0.f;

        #pragma unroll
        for (int ks = 0; ks < 4; ks++) {
            uint32_t kb = (uint32_t)(ks * 32);
            uint32_t bw[2][4];
            #pragma unroll
            for (int p = 0; p < 2; p++)
                ldsm4(bw[p], sm + K_OFF
                             + sw128((b_row + p * 16) * 128 + kb + a_kb));
            #pragma unroll
            for (int p = 0; p < 2; p++) {
                mma16816hv(sacc[2 * p],     afq[ks], bw[p][0], bw[p][2]);
                mma16816hv(sacc[2 * p + 1], afq[ks], bw[p][1], bw[p][3]);
            }
        }

        // ---- exp2 -> P[kt] (fp16, smem only) + rowsum ----
        uint32_t pbase = (uint32_t)(P_OFF + kt * 8192);
        {
            float p0 = 0.f, p1 = 0.f;
            int r0 = warp_m * 16 + (lane >> 2);
            #pragma unroll
            for (int nt = 0; nt < 4; nt++) {
                int kc = warp_n * 32 + nt * 8 + (lane & 3) * 2;
                float e0 = ex2f(sacc[nt][0]);
                float e1 = ex2f(sacc[nt][1]);
                float e2 = ex2f(sacc[nt][2]);
                float e3 = ex2f(sacc[nt][3]);
                p0 += e0 + e1; p1 += e2 + e3;
                __half2 h0 = __floats2half2_rn(e0, e1);
                __half2 h1 = __floats2half2_rn(e2, e3);
                uint32_t po  = pbase + (uint32_t)((kc >> 6) * 4096)
                             + sw128((uint32_t)(r0 * 128 + (kc & 63) * 2));
                uint32_t po8 = pbase + (uint32_t)((kc >> 6) * 4096)
                             + sw128((uint32_t)((r0 + 8) * 128 + (kc & 63) * 2));
                *(__half2*)(smraw + po)  = h0;
                *(__half2*)(smraw + po8) = h1;
            }
            p0 += __shfl_xor_sync(0xffffffffu, p0, 1);
            p0 += __shfl_xor_sync(0xffffffffu, p0, 2);
            p1 += __shfl_xor_sync(0xffffffffu, p1, 1);
            p1 += __shfl_xor_sync(0xffffffffu, p1, 2);
            if ((lane & 3) == 0) {
                atomicAdd(&rowsumS[r0], p0);
                atomicAdd(&rowsumS[r0 + 8], p1);
            }
        }
        __syncthreads();   // P[kt] ready; all warps done with K(kt)
        if (kt + 1 < 8) { load_k(kt + 1); CP_COMMIT(); }   // hidden behind AV

        // ---- AV: ctx += P * V, M32 x N64 x K128 ----
        uint32_t vbase = sm + V_OFF + (uint32_t)((kt & 1) * 16384);
        #pragma unroll
        for (int ks = 0; ks < 8; ks++) {
            uint32_t kbyte = (uint32_t)(ks * 32) + a_kb;
            uint32_t af[4], bv[4];
            ldsm4(af, sm + pbase + (kbyte >> 7) * 4096u
                      + sw128(a_row * 128 + (kbyte & 127)));
            ldsm4t(bv, vbase + sw128((uint32_t)((ks * 16 + (lane & 15)) * 128)
                                     + (uint32_t)(warp_n * 32) + (uint32_t)((lane >> 4) * 16)));
            mma16816h(ctx[0], af, bv);
            mma16816h(ctx[1], af, bv + 2);
        }
        __syncthreads();   // V buf[kt&1] consumed
        if (kt + 2 < 8) { load_v(kt + 2, kt & 1); CP_COMMIT(); }
    }

    // ---- normalized context write: [B,S,D] ----
    int b = bh >> 4, h = bh & 15;
    #pragma unroll
    for (int half = 0; half < 2; half++) {
        int r = warp_m * 16 + (lane >> 2) + half * 8;
        float inv = 1.0f / rowsumS[r];
        size_t o = ((size_t)(b * NS + q0 + r)) * ND + h * NDH;
        #pragma unroll
        for (int nt = 0; nt < 2; nt++) {
            int d = warp_n * 16 + nt * 8 + (lane & 3) * 2;
            float c0 = ctx[nt][half * 2 + 0] * inv;
            float c1 = ctx[nt][half * 2 + 1] * inv;
            *(float2*)&out_ctx[o + d] = make_float2(c0, c1);
        }
    }

    // ---- deferred att write: read P tiles from smem, normalize, store ----
    {
        int r = t >> 3;               // 0..31
        int c8 = t & 7;               // 16 cols each
        float inv = 1.0f / rowsumS[r];
        int col0 = c8 * 16;
        uint32_t half = (uint32_t)((col0 >> 6) * 4096);
        uint32_t boff = (uint32_t)(r * 128 + (col0 & 63) * 2);
        float* orow = out_att + ((size_t)bh * NS + q0 + r) * NS + col0;
        #pragma unroll 1
        for (int kt = 0; kt < 8; kt++) {
            char* tb = smraw + P_OFF + kt * 8192;
            uint4 d0 = *(uint4*)(tb + half + sw128(boff));
            uint4 d1 = *(uint4*)(tb + half + sw128(boff + 16));
            float* op = orow + kt * 128;
            const uint32_t* w0 = (const uint32_t*)&d0;
            const uint32_t* w1 = (const uint32_t*)&d1;
            float4 f0, f1, f2, f3;
            {
                float2 a0 = __half22float2(*(__half2*)&w0[0]);
                float2 a1 = __half22float2(*(__half2*)&w0[1]);
                float2 a2 = __half22float2(*(__half2*)&w0[2]);
                float2 a3 = __half22float2(*(__half2*)&w0[3]);
                f0 = make_float4(a0.x * inv, a0.y * inv, a1.x * inv, a1.y * inv);
                f1 = make_float4(a2.x * inv, a2.y * inv, a3.x * inv, a3.y * inv);
            }
            {
                float2 a0 = __half22float2(*(__half2*)&w1[0]);
                float2 a1 = __half22float2(*(__half2*)&w1[1]);
                float2 a2 = __half22float2(*(__half2*)&w1[2]);
                float2 a3 = __half22float2(*(__half2*)&w1[3]);
                f2 = make_float4(a0.x * inv, a0.y * inv, a1.x * inv, a1.y * inv);
                f3 = make_float4(a2.x * inv, a2.y * inv, a3.x * inv, a3.y * inv);
            }
            *(float4*)&op[0]  = f0;
            *(float4*)&op[4]  = f1;
            *(float4*)&op[8]  = f2;
            *(float4*)&op[12] = f3;
        }
    }
}

extern "C" void kernel_launch(void* const* d_in, const int* in_sizes, int n_in,
                              void* d_out, int out_size) {
    const float* x  = (const float*)d_in[0];
    const float* Wq = (const float*)d_in[1];
    const float* bq = (const float*)d_in[2];
    const float* Wk = (const float*)d_in[3];
    const float* bk = (const float*)d_in[4];
    const float* Wv = (const float*)d_in[5];
    const float* bv = (const float*)d_in[6];
    // d_in[7] structure_bias: constant along the softmax axis -> cancels exactly.

    float* out_ctx = (float*)d_out;
    float* out_att = out_ctx + (size_t)NB * NS * ND;

    cudaFuncSetAttribute(qkv_mma_kernel, cudaFuncAttributeMaxDynamicSharedMemorySize, QKV_SMEM);
    cudaFuncSetAttribute(attn_mma_kernel, cudaFuncAttributeMaxDynamicSharedMemorySize, ATT_SMEM);

    prep_x_kernel<<<8192, 256>>>(x);
    prep_w_kernel<<<dim3(1024, 3), 256>>>(Wq, Wk, Wv);
    qkv_mma_kernel<<<dim3(24, 64), 256, QKV_SMEM>>>(bq, bk, bv);
    attn_mma_kernel<<<dim3(32, 128), 256, ATT_SMEM>>>(out_ctx, out_att);
}